// round 3
// baseline (speedup 1.0000x reference)
#include <cuda_runtime.h>
#include <cstdint>

// ---------------------------------------------------------------------------
// ProtoNet: out[q,c] = -(||z_q - proto_c||^2)
//   z_q   = xq @ W + b                       [Q, D]
//   proto = classmean(xs) @ W + b            [64, D]   (linearity of encoder)
//   out   = 2*z_q.proto^T - ||z_q||^2 - ||proto||^2
// Shapes: S=1024, Q=16384, F=2048, D=512, NWAY=64
// ---------------------------------------------------------------------------

#define NWAY 64

// Static scratch (no allocations allowed).
#define Q_MAX 16384
#define D_MAX 512
#define F_MAX 2048
#define S_SMEM 2048

__device__ float g_z[(size_t)Q_MAX * D_MAX];        // 32 MB
__device__ float g_cls_mean[NWAY * F_MAX];          // 512 KB
__device__ float g_proto[NWAY * D_MAX];             // 128 KB
__device__ float g_znorm[Q_MAX];                    // 64 KB
__device__ float g_pnorm[NWAY];
__device__ int   g_ys[4096];
__device__ float g_invcnt[NWAY];

// ---------------------------------------------------------------------------
// k_prep: detect int64-vs-int32 label layout, normalize labels, class counts.
// ---------------------------------------------------------------------------
__global__ void k_prep(const void* ys_raw, int S, int* ys_out, float* invcnt) {
    __shared__ int s_is32;
    __shared__ int s_cnt[NWAY];
    int tid = threadIdx.x;
    if (tid == 0) s_is32 = 0;
    if (tid < NWAY) s_cnt[tid] = 0;
    __syncthreads();

    // If int64 (values in [0,64)), every odd 32-bit word among the first S
    // words is a zero high-half. If int32, those words are random labels.
    const int* w32 = (const int*)ys_raw;
    for (int j = 1 + 2 * tid; j < S; j += 2 * blockDim.x) {
        if (w32[j] != 0) s_is32 = 1;   // benign race (all write 1)
    }
    __syncthreads();
    int is64 = !s_is32;

    const long long* w64 = (const long long*)ys_raw;
    for (int i = tid; i < S; i += blockDim.x) {
        int c = is64 ? (int)w64[i] : w32[i];
        ys_out[i] = c;
        atomicAdd(&s_cnt[c], 1);
    }
    __syncthreads();
    if (tid < NWAY) {
        int c = s_cnt[tid];
        invcnt[tid] = 1.0f / (float)(c > 0 ? c : 1);
    }
}

// ---------------------------------------------------------------------------
// k_cls_mean: per-class mean of xs in F-space.  grid = F/128, block = 128.
// Each thread owns one feature column; loops all S rows accumulating into a
// private-per-thread shared column slot -> no atomics in the hot loop.
// ---------------------------------------------------------------------------
__global__ void k_cls_mean(const float* __restrict__ xs, int S, int F,
                           const int* __restrict__ ys,
                           const float* __restrict__ invcnt,
                           float* __restrict__ cls_mean) {
    __shared__ float acc[NWAY][128];
    __shared__ int s_ys[S_SMEM];
    int tid = threadIdx.x;
    int f = blockIdx.x * 128 + tid;

    #pragma unroll
    for (int c = 0; c < NWAY; c++) acc[c][tid] = 0.0f;
    for (int i = tid; i < S && i < S_SMEM; i += blockDim.x) s_ys[i] = ys[i];
    __syncthreads();

    const int* ysp = (S <= S_SMEM) ? s_ys : ys;
    #pragma unroll 4
    for (int i = 0; i < S; i++) {
        acc[ysp[i]][tid] += xs[(size_t)i * F + f];
    }
    __syncthreads();

    #pragma unroll
    for (int c = 0; c < NWAY; c++) {
        cls_mean[(size_t)c * F + f] = acc[c][tid] * invcnt[c];
    }
}

// ---------------------------------------------------------------------------
// gemm_nn: C[M,N] = A[M,K] @ B[K,N] + bias[N]
// BM=128, BN=128, BK=8, 256 threads, 8x8 per thread, float4 everywhere.
// Handles M not a multiple of 128 (needed for M=64 proto GEMM).
// Requires: K % 8 == 0, N % 128 == 0.
// ---------------------------------------------------------------------------
#define BM 128
#define BN 128
#define BK 8
__global__ __launch_bounds__(256) void gemm_nn(
    const float* __restrict__ A, const float* __restrict__ B,
    const float* __restrict__ bias, float* __restrict__ C,
    int M, int N, int K)
{
    __shared__ float As[BK][BM];
    __shared__ float Bs[BK][BN];

    int tid = threadIdx.x;
    int rowBase = blockIdx.y * BM;
    int colBase = blockIdx.x * BN;

    // A: 128 rows x 8 cols = 256 float4
    int aRow = tid >> 1;
    int aCol = (tid & 1) * 4;
    // B: 8 rows x 128 cols = 256 float4
    int bRow = tid >> 5;
    int bCol = (tid & 31) * 4;

    int ty = tid >> 4;   // 0..15 -> row group (8 rows each)
    int tx = tid & 15;   // 0..15 -> col group (8 cols each)

    float acc[8][8];
    #pragma unroll
    for (int i = 0; i < 8; i++)
        #pragma unroll
        for (int j = 0; j < 8; j++) acc[i][j] = 0.0f;

    for (int k0 = 0; k0 < K; k0 += BK) {
        float4 a4 = make_float4(0.f, 0.f, 0.f, 0.f);
        int gRow = rowBase + aRow;
        if (gRow < M)
            a4 = *(const float4*)(A + (size_t)gRow * K + k0 + aCol);
        As[aCol + 0][aRow] = a4.x;
        As[aCol + 1][aRow] = a4.y;
        As[aCol + 2][aRow] = a4.z;
        As[aCol + 3][aRow] = a4.w;

        float4 b4 = *(const float4*)(B + (size_t)(k0 + bRow) * N + colBase + bCol);
        *(float4*)&Bs[bRow][bCol] = b4;
        __syncthreads();

        #pragma unroll
        for (int k = 0; k < BK; k++) {
            float a[8], b[8];
            *(float4*)&a[0] = *(const float4*)&As[k][ty * 8];
            *(float4*)&a[4] = *(const float4*)&As[k][ty * 8 + 4];
            *(float4*)&b[0] = *(const float4*)&Bs[k][tx * 8];
            *(float4*)&b[4] = *(const float4*)&Bs[k][tx * 8 + 4];
            #pragma unroll
            for (int i = 0; i < 8; i++)
                #pragma unroll
                for (int j = 0; j < 8; j++)
                    acc[i][j] = fmaf(a[i], b[j], acc[i][j]);
        }
        __syncthreads();
    }

    float bv[8];
    *(float4*)&bv[0] = *(const float4*)(bias + colBase + tx * 8);
    *(float4*)&bv[4] = *(const float4*)(bias + colBase + tx * 8 + 4);

    #pragma unroll
    for (int i = 0; i < 8; i++) {
        int r = rowBase + ty * 8 + i;
        if (r >= M) break;
        float4 o0 = make_float4(acc[i][0] + bv[0], acc[i][1] + bv[1],
                                acc[i][2] + bv[2], acc[i][3] + bv[3]);
        float4 o1 = make_float4(acc[i][4] + bv[4], acc[i][5] + bv[5],
                                acc[i][6] + bv[6], acc[i][7] + bv[7]);
        *(float4*)(C + (size_t)r * N + colBase + tx * 8)     = o0;
        *(float4*)(C + (size_t)r * N + colBase + tx * 8 + 4) = o1;
    }
}

// ---------------------------------------------------------------------------
// rownorm: out[m] = sum_k A[m,k]^2.  One warp per row. K % 4 == 0.
// ---------------------------------------------------------------------------
__global__ void rownorm(const float* __restrict__ A, float* __restrict__ out,
                        int M, int K) {
    int warp = (blockIdx.x * blockDim.x + threadIdx.x) >> 5;
    int lane = threadIdx.x & 31;
    if (warp >= M) return;
    const float* row = A + (size_t)warp * K;
    float s = 0.0f;
    for (int j = lane * 4; j < K; j += 32 * 4) {
        float4 v = *(const float4*)(row + j);
        s = fmaf(v.x, v.x, s);
        s = fmaf(v.y, v.y, s);
        s = fmaf(v.z, v.z, s);
        s = fmaf(v.w, v.w, s);
    }
    #pragma unroll
    for (int o = 16; o > 0; o >>= 1) s += __shfl_xor_sync(0xFFFFFFFFu, s, o);
    if (lane == 0) out[warp] = s;
}

// ---------------------------------------------------------------------------
// gemm_nt_epi: out[q,c] = 2 * dot(z[q,:], proto[c,:]) - znorm[q] - pnorm[c]
// A = z [M,K] row-major, B = proto [64,K] row-major.
// BM=128, BN=64, BK=32, 256 threads, 8x4 per thread. K % 32 == 0.
// ---------------------------------------------------------------------------
#define TBM 128
#define TBN 64
#define TBK 32
__global__ __launch_bounds__(256) void gemm_nt_epi(
    const float* __restrict__ A, const float* __restrict__ B,
    const float* __restrict__ znorm, const float* __restrict__ pnorm,
    float* __restrict__ out, int M, int K)
{
    __shared__ float As[TBK][TBM];
    __shared__ float Bs[TBK][TBN];

    int tid = threadIdx.x;
    int rowBase = blockIdx.y * TBM;

    int ty = tid >> 4;   // 0..15
    int tx = tid & 15;   // 0..15

    float acc[8][4];
    #pragma unroll
    for (int i = 0; i < 8; i++)
        #pragma unroll
        for (int j = 0; j < 4; j++) acc[i][j] = 0.0f;

    // loaders: colGroup = (tid%8)*4 covers 32 cols; rows stride 32
    int lCol = (tid & 7) * 4;
    int lRow = tid >> 3;   // 0..31

    for (int k0 = 0; k0 < K; k0 += TBK) {
        #pragma unroll
        for (int r = 0; r < 4; r++) {
            int gr = rowBase + lRow + r * 32;
            float4 a4 = *(const float4*)(A + (size_t)gr * K + k0 + lCol);
            As[lCol + 0][lRow + r * 32] = a4.x;
            As[lCol + 1][lRow + r * 32] = a4.y;
            As[lCol + 2][lRow + r * 32] = a4.z;
            As[lCol + 3][lRow + r * 32] = a4.w;
        }
        #pragma unroll
        for (int r = 0; r < 2; r++) {
            int gn = lRow + r * 32;   // 0..63
            float4 b4 = *(const float4*)(B + (size_t)gn * K + k0 + lCol);
            Bs[lCol + 0][gn] = b4.x;
            Bs[lCol + 1][gn] = b4.y;
            Bs[lCol + 2][gn] = b4.z;
            Bs[lCol + 3][gn] = b4.w;
        }
        __syncthreads();

        #pragma unroll
        for (int k = 0; k < TBK; k++) {
            float a[8], b[4];
            *(float4*)&a[0] = *(const float4*)&As[k][ty * 8];
            *(float4*)&a[4] = *(const float4*)&As[k][ty * 8 + 4];
            *(float4*)&b[0] = *(const float4*)&Bs[k][tx * 4];
            #pragma unroll
            for (int i = 0; i < 8; i++)
                #pragma unroll
                for (int j = 0; j < 4; j++)
                    acc[i][j] = fmaf(a[i], b[j], acc[i][j]);
        }
        __syncthreads();
    }

    float pn[4];
    *(float4*)&pn[0] = *(const float4*)(pnorm + tx * 4);

    #pragma unroll
    for (int i = 0; i < 8; i++) {
        int r = rowBase + ty * 8 + i;
        if (r >= M) break;
        float zn = znorm[r];
        float4 o;
        o.x = 2.0f * acc[i][0] - zn - pn[0];
        o.y = 2.0f * acc[i][1] - zn - pn[1];
        o.z = 2.0f * acc[i][2] - zn - pn[2];
        o.w = 2.0f * acc[i][3] - zn - pn[3];
        *(float4*)(out + (size_t)r * NWAY + tx * 4) = o;
    }
}

// ---------------------------------------------------------------------------
// Host launcher
// ---------------------------------------------------------------------------
extern "C" void kernel_launch(void* const* d_in, const int* in_sizes, int n_in,
                              void* d_out, int out_size) {
    const float* xs = (const float*)d_in[0];
    const void*  ys = d_in[1];
    const float* xq = (const float*)d_in[2];
    const float* W  = (const float*)d_in[3];
    const float* b  = (const float*)d_in[4];

    int S = in_sizes[1];
    int F = in_sizes[0] / S;
    int D = in_sizes[4];
    int Q = in_sizes[2] / F;

    float *p_z, *p_cls, *p_proto, *p_znorm, *p_pnorm, *p_invcnt;
    int *p_ys;
    cudaGetSymbolAddress((void**)&p_z, g_z);
    cudaGetSymbolAddress((void**)&p_cls, g_cls_mean);
    cudaGetSymbolAddress((void**)&p_proto, g_proto);
    cudaGetSymbolAddress((void**)&p_znorm, g_znorm);
    cudaGetSymbolAddress((void**)&p_pnorm, g_pnorm);
    cudaGetSymbolAddress((void**)&p_invcnt, g_invcnt);
    cudaGetSymbolAddress((void**)&p_ys, g_ys);

    // 1. labels + counts
    k_prep<<<1, 256>>>(ys, S, p_ys, p_invcnt);

    // 2. class means in F-space
    k_cls_mean<<<F / 128, 128>>>(xs, S, F, p_ys, p_invcnt, p_cls);

    // 3. prototypes in D-space: proto = cls_mean @ W + b   [64, D]
    {
        dim3 grid(D / BN, (NWAY + BM - 1) / BM);
        gemm_nn<<<grid, 256>>>(p_cls, W, b, p_proto, NWAY, D, F);
    }

    // 4. big GEMM: z = xq @ W + b   [Q, D]
    {
        dim3 grid(D / BN, (Q + BM - 1) / BM);
        gemm_nn<<<grid, 256>>>(xq, W, b, p_z, Q, D, F);
    }

    // 5. row norms
    rownorm<<<(Q + 7) / 8, 256>>>(p_z, p_znorm, Q, D);
    rownorm<<<(NWAY + 7) / 8, 256>>>(p_proto, p_pnorm, NWAY, D);

    // 6. fused cross-term + epilogue -> output
    {
        dim3 grid(1, (Q + TBM - 1) / TBM);
        gemm_nt_epi<<<grid, 256>>>(p_z, p_proto, p_znorm, p_pnorm,
                                   (float*)d_out, Q, D);
    }
}

// round 4
// speedup vs baseline: 3.3599x; 3.3599x over previous
#include <cuda_runtime.h>
#include <cstdint>

// ---------------------------------------------------------------------------
// ProtoNet: out[q,c] = -||z_q - proto_c||^2
//   z_q   = xq @ W + b                     [Q, D]   (tf32 tensor-core GEMM)
//   proto = (classsum(xs)/count) @ W + b   [64, D]  (linearity of encoder)
//   out   = 2*z_q.proto^T - ||z_q||^2 - ||proto||^2
// Shapes: S=1024, Q=16384, F=2048, D=512, NWAY=64
// ---------------------------------------------------------------------------

#define NWAY 64
#define Q_MAX 16384
#define D_MAX 512
#define F_MAX 2048

__device__ float g_z[(size_t)Q_MAX * D_MAX];        // 32 MB
__device__ float g_cls_sum[NWAY * F_MAX];           // 512 KB
__device__ float g_proto[NWAY * D_MAX];             // 128 KB
__device__ float g_znorm[Q_MAX];
__device__ float g_pnorm[NWAY];
__device__ int   g_ys[4096];
__device__ float g_invcnt[NWAY];
__device__ int   g_cnt[NWAY];

// ---------------------------------------------------------------------------
__global__ void k_zero(float* p, int n) {
    int i = blockIdx.x * blockDim.x + threadIdx.x;
    if (i < n) p[i] = 0.0f;
}

// ---------------------------------------------------------------------------
// k_prep: detect int64-vs-int32 label layout, normalize labels, class counts.
// ---------------------------------------------------------------------------
__global__ void k_prep(const void* ys_raw, int S, int* ys_out, float* invcnt,
                       int* cnt_out) {
    __shared__ int s_is32;
    __shared__ int s_cnt[NWAY];
    int tid = threadIdx.x;
    if (tid == 0) s_is32 = 0;
    if (tid < NWAY) s_cnt[tid] = 0;
    __syncthreads();

    const int* w32 = (const int*)ys_raw;
    for (int j = 1 + 2 * tid; j < S; j += 2 * blockDim.x) {
        if (w32[j] != 0) s_is32 = 1;   // benign race
    }
    __syncthreads();
    int is64 = !s_is32;

    const long long* w64 = (const long long*)ys_raw;
    for (int i = tid; i < S; i += blockDim.x) {
        int c = is64 ? (int)w64[i] : w32[i];
        ys_out[i] = c;
        atomicAdd(&s_cnt[c], 1);
    }
    __syncthreads();
    if (tid < NWAY) {
        int c = s_cnt[tid];
        cnt_out[tid] = c;
        invcnt[tid] = 1.0f / (float)(c > 0 ? c : 1);
    }
}

// ---------------------------------------------------------------------------
// k_cls_sum: per-class SUM of xs in F-space, S split 8 ways, atomic combine.
// grid (F/128, 8), block 128.
// ---------------------------------------------------------------------------
__global__ void k_cls_sum(const float* __restrict__ xs, int S, int F,
                          const int* __restrict__ ys,
                          float* __restrict__ cls_sum) {
    __shared__ float acc[NWAY][128];
    __shared__ int s_ys[256];
    int tid = threadIdx.x;
    int f = blockIdx.x * 128 + tid;
    int chunk = S / gridDim.y;
    int s0 = blockIdx.y * chunk;

    #pragma unroll
    for (int c = 0; c < NWAY; c++) acc[c][tid] = 0.0f;
    for (int i = tid; i < chunk; i += blockDim.x) s_ys[i] = ys[s0 + i];
    __syncthreads();

    #pragma unroll 4
    for (int i = 0; i < chunk; i++) {
        acc[s_ys[i]][tid] += xs[(size_t)(s0 + i) * F + f];
    }
    __syncthreads();

    #pragma unroll
    for (int c = 0; c < NWAY; c++) {
        atomicAdd(&cls_sum[(size_t)c * F + f], acc[c][tid]);
    }
}

// ---------------------------------------------------------------------------
// k_proto: proto[m][d] += invcnt[m] * sum_k cls_sum[m][k] * W[k][d]
// split-K (8) + 4-way m reuse. grid = D*16*8/256 blocks, block 256.
// proto pre-zeroed.
// ---------------------------------------------------------------------------
#define PROTO_KS 8
__global__ void k_proto(const float* __restrict__ cls_sum,
                        const float* __restrict__ W,
                        const float* __restrict__ invcnt,
                        float* __restrict__ proto, int F, int D) {
    int idx = blockIdx.x * blockDim.x + threadIdx.x;
    int d  = idx % D;
    int mg = (idx / D) % (NWAY / 4);
    int ks = idx / (D * (NWAY / 4));
    int kper = F / PROTO_KS;
    int k0 = ks * kper;

    const float* a = cls_sum + (size_t)(mg * 4) * F + k0;
    const float* w = W + (size_t)k0 * D + d;

    float s0 = 0.f, s1 = 0.f, s2 = 0.f, s3 = 0.f;
    #pragma unroll 4
    for (int k = 0; k < kper; k++) {
        float wv = w[(size_t)k * D];
        s0 = fmaf(a[k], wv, s0);
        s1 = fmaf(a[k + F], wv, s1);
        s2 = fmaf(a[k + 2 * F], wv, s2);
        s3 = fmaf(a[k + 3 * F], wv, s3);
    }
    int m = mg * 4;
    atomicAdd(&proto[(size_t)(m + 0) * D + d], s0 * invcnt[m + 0]);
    atomicAdd(&proto[(size_t)(m + 1) * D + d], s1 * invcnt[m + 1]);
    atomicAdd(&proto[(size_t)(m + 2) * D + d], s2 * invcnt[m + 2]);
    atomicAdd(&proto[(size_t)(m + 3) * D + d], s3 * invcnt[m + 3]);
}

// ---------------------------------------------------------------------------
// k_proto_fin: proto[c][d] += b[d] (only if class non-empty, matching
// reference clip semantics where empty class -> all zeros), pnorm[c]=||row||^2
// grid 64, block 128.
// ---------------------------------------------------------------------------
__global__ void k_proto_fin(float* __restrict__ proto,
                            const float* __restrict__ bias,
                            const int* __restrict__ cnt,
                            float* __restrict__ pnorm, int D) {
    __shared__ float red[128];
    int c = blockIdx.x;
    int tid = threadIdx.x;
    bool nonempty = cnt[c] > 0;
    float s = 0.f;
    for (int d = tid; d < D; d += blockDim.x) {
        float v = proto[(size_t)c * D + d] + (nonempty ? bias[d] : 0.0f);
        proto[(size_t)c * D + d] = v;
        s = fmaf(v, v, s);
    }
    red[tid] = s;
    __syncthreads();
    for (int o = 64; o > 0; o >>= 1) {
        if (tid < o) red[tid] += red[tid + o];
        __syncthreads();
    }
    if (tid == 0) pnorm[c] = red[0];
}

// ---------------------------------------------------------------------------
// gemm_tf32: Z[M,N] = A[M,K] @ W[K,N] + bias ; also znorm[m] += ||row tile||^2
// tf32 mma.sync m16n8k8, BM=128 BN=128 BK=16, 8 warps (2x4 of 64x32 tiles),
// double-buffered smem. Requires M%128==0, N%128==0, K%16==0.
// ---------------------------------------------------------------------------
#define GBM 128
#define GBN 128
#define GBK 16
#define AS_STRIDE 20    // 16 + 4 pad  -> conflict-free A-fragment LDS
#define BS_STRIDE 136   // 128 + 8 pad -> conflict-free B-fragment LDS

__device__ __forceinline__ float f2tf32(float x) {
    unsigned u;
    asm("cvt.rna.tf32.f32 %0, %1;" : "=r"(u) : "f"(x));
    return __uint_as_float(u);
}

__device__ __forceinline__ void mma8(float* d, const float* a, const float* b) {
    const unsigned* A = reinterpret_cast<const unsigned*>(a);
    const unsigned* B = reinterpret_cast<const unsigned*>(b);
    asm volatile(
        "mma.sync.aligned.m16n8k8.row.col.f32.tf32.tf32.f32 "
        "{%0,%1,%2,%3}, {%4,%5,%6,%7}, {%8,%9}, {%0,%1,%2,%3};\n"
        : "+f"(d[0]), "+f"(d[1]), "+f"(d[2]), "+f"(d[3])
        : "r"(A[0]), "r"(A[1]), "r"(A[2]), "r"(A[3]), "r"(B[0]), "r"(B[1]));
}

__global__ __launch_bounds__(256, 2) void gemm_tf32(
    const float* __restrict__ A, const float* __restrict__ W,
    const float* __restrict__ bias, float* __restrict__ Z,
    float* __restrict__ znorm, int M, int N, int K)
{
    __shared__ float As[2][GBM * AS_STRIDE];
    __shared__ float Bs[2][GBK * BS_STRIDE];

    int tid  = threadIdx.x;
    int warp = tid >> 5, lane = tid & 31;
    int wm = warp & 1;        // 0..1  (64-row half)
    int wn = warp >> 1;       // 0..3  (32-col strip)
    int rowBase = blockIdx.y * GBM;
    int colBase = blockIdx.x * GBN;

    // global loaders
    int arow = tid >> 1;                // 0..127
    int acol = (tid & 1) * 8;           // 0 / 8
    const float* aptr = A + (size_t)(rowBase + arow) * K + acol;
    int brow = tid >> 4;                // 0..15
    int bcol = (tid & 15) * 8;
    const float* bptr = W + (size_t)brow * N + colBase + bcol;

    float acc[4][4][4];
    #pragma unroll
    for (int i = 0; i < 4; i++)
        #pragma unroll
        for (int j = 0; j < 4; j++)
            #pragma unroll
            for (int r = 0; r < 4; r++) acc[i][j][r] = 0.0f;

    int lg = lane >> 2;      // 0..7
    int lq = lane & 3;       // 0..3

    // precomputed smem read offsets
    int aoff[4], boff[4];
    #pragma unroll
    for (int mt = 0; mt < 4; mt++)
        aoff[mt] = (wm * 64 + mt * 16 + lg) * AS_STRIDE + lq;
    #pragma unroll
    for (int nt = 0; nt < 4; nt++)
        boff[nt] = lq * BS_STRIDE + wn * 32 + nt * 8 + lg;

    // prologue: load chunk 0
    float4 pa0 = *(const float4*)(aptr);
    float4 pa1 = *(const float4*)(aptr + 4);
    float4 pb0 = *(const float4*)(bptr);
    float4 pb1 = *(const float4*)(bptr + 4);

    int asmoff = arow * AS_STRIDE + acol;
    int bsmoff = brow * BS_STRIDE + bcol;
    {
        float4 t;
        t.x=f2tf32(pa0.x); t.y=f2tf32(pa0.y); t.z=f2tf32(pa0.z); t.w=f2tf32(pa0.w);
        *(float4*)&As[0][asmoff] = t;
        t.x=f2tf32(pa1.x); t.y=f2tf32(pa1.y); t.z=f2tf32(pa1.z); t.w=f2tf32(pa1.w);
        *(float4*)&As[0][asmoff + 4] = t;
        t.x=f2tf32(pb0.x); t.y=f2tf32(pb0.y); t.z=f2tf32(pb0.z); t.w=f2tf32(pb0.w);
        *(float4*)&Bs[0][bsmoff] = t;
        t.x=f2tf32(pb1.x); t.y=f2tf32(pb1.y); t.z=f2tf32(pb1.z); t.w=f2tf32(pb1.w);
        *(float4*)&Bs[0][bsmoff + 4] = t;
    }
    __syncthreads();

    int nIt = K / GBK;
    int buf = 0;
    for (int it = 0; it < nIt; ++it) {
        bool has = (it + 1) < nIt;
        if (has) {
            const float* ap = aptr + (it + 1) * GBK;
            const float* bp = bptr + (size_t)(it + 1) * GBK * N;
            pa0 = *(const float4*)(ap);
            pa1 = *(const float4*)(ap + 4);
            pb0 = *(const float4*)(bp);
            pb1 = *(const float4*)(bp + 4);
        }

        #pragma unroll
        for (int kk = 0; kk < GBK; kk += 8) {
            float af[4][4], bf[4][2];
            #pragma unroll
            for (int mt = 0; mt < 4; mt++) {
                const float* base = &As[buf][aoff[mt] + kk];
                af[mt][0] = base[0];
                af[mt][1] = base[8 * AS_STRIDE];
                af[mt][2] = base[4];
                af[mt][3] = base[8 * AS_STRIDE + 4];
            }
            #pragma unroll
            for (int nt = 0; nt < 4; nt++) {
                const float* base = &Bs[buf][boff[nt] + kk * BS_STRIDE];
                bf[nt][0] = base[0];
                bf[nt][1] = base[4 * BS_STRIDE];
            }
            #pragma unroll
            for (int mt = 0; mt < 4; mt++)
                #pragma unroll
                for (int nt = 0; nt < 4; nt++)
                    mma8(acc[mt][nt], af[mt], bf[nt]);
        }

        if (has) {
            int nb = buf ^ 1;
            float4 t;
            t.x=f2tf32(pa0.x); t.y=f2tf32(pa0.y); t.z=f2tf32(pa0.z); t.w=f2tf32(pa0.w);
            *(float4*)&As[nb][asmoff] = t;
            t.x=f2tf32(pa1.x); t.y=f2tf32(pa1.y); t.z=f2tf32(pa1.z); t.w=f2tf32(pa1.w);
            *(float4*)&As[nb][asmoff + 4] = t;
            t.x=f2tf32(pb0.x); t.y=f2tf32(pb0.y); t.z=f2tf32(pb0.z); t.w=f2tf32(pb0.w);
            *(float4*)&Bs[nb][bsmoff] = t;
            t.x=f2tf32(pb1.x); t.y=f2tf32(pb1.y); t.z=f2tf32(pb1.z); t.w=f2tf32(pb1.w);
            *(float4*)&Bs[nb][bsmoff + 4] = t;
            __syncthreads();
            buf = nb;
        }
    }

    // epilogue: add bias, store Z, accumulate ||row||^2 into znorm
    #pragma unroll
    for (int mt = 0; mt < 4; mt++) {
        int r0 = rowBase + wm * 64 + mt * 16 + lg;
        float sum0 = 0.f, sum1 = 0.f;
        #pragma unroll
        for (int nt = 0; nt < 4; nt++) {
            int cb = colBase + wn * 32 + nt * 8 + lq * 2;
            float bv0 = bias[cb], bv1 = bias[cb + 1];
            float v0 = acc[mt][nt][0] + bv0;
            float v1 = acc[mt][nt][1] + bv1;
            float v2 = acc[mt][nt][2] + bv0;
            float v3 = acc[mt][nt][3] + bv1;
            *(float2*)(Z + (size_t)r0 * N + cb)       = make_float2(v0, v1);
            *(float2*)(Z + (size_t)(r0 + 8) * N + cb) = make_float2(v2, v3);
            sum0 = fmaf(v0, v0, fmaf(v1, v1, sum0));
            sum1 = fmaf(v2, v2, fmaf(v3, v3, sum1));
        }
        // reduce across the 4 lanes of the quad (same row)
        sum0 += __shfl_xor_sync(0xFFFFFFFFu, sum0, 1);
        sum0 += __shfl_xor_sync(0xFFFFFFFFu, sum0, 2);
        sum1 += __shfl_xor_sync(0xFFFFFFFFu, sum1, 1);
        sum1 += __shfl_xor_sync(0xFFFFFFFFu, sum1, 2);
        if (lq == 0) {
            atomicAdd(&znorm[r0], sum0);
            atomicAdd(&znorm[r0 + 8], sum1);
        }
    }
}

// ---------------------------------------------------------------------------
// gemm_nt_epi: out[q,c] = 2 * dot(z[q,:], proto[c,:]) - znorm[q] - pnorm[c]
// ---------------------------------------------------------------------------
#define TBM 128
#define TBK 32
__global__ __launch_bounds__(256) void gemm_nt_epi(
    const float* __restrict__ A, const float* __restrict__ B,
    const float* __restrict__ znorm, const float* __restrict__ pnorm,
    float* __restrict__ out, int M, int K)
{
    __shared__ float As[TBK][TBM];
    __shared__ float Bs[TBK][NWAY];

    int tid = threadIdx.x;
    int rowBase = blockIdx.y * TBM;
    int ty = tid >> 4;
    int tx = tid & 15;

    float acc[8][4];
    #pragma unroll
    for (int i = 0; i < 8; i++)
        #pragma unroll
        for (int j = 0; j < 4; j++) acc[i][j] = 0.0f;

    int lCol = (tid & 7) * 4;
    int lRow = tid >> 3;

    for (int k0 = 0; k0 < K; k0 += TBK) {
        #pragma unroll
        for (int r = 0; r < 4; r++) {
            int gr = rowBase + lRow + r * 32;
            float4 a4 = *(const float4*)(A + (size_t)gr * K + k0 + lCol);
            As[lCol + 0][lRow + r * 32] = a4.x;
            As[lCol + 1][lRow + r * 32] = a4.y;
            As[lCol + 2][lRow + r * 32] = a4.z;
            As[lCol + 3][lRow + r * 32] = a4.w;
        }
        #pragma unroll
        for (int r = 0; r < 2; r++) {
            int gn = lRow + r * 32;
            float4 b4 = *(const float4*)(B + (size_t)gn * K + k0 + lCol);
            Bs[lCol + 0][gn] = b4.x;
            Bs[lCol + 1][gn] = b4.y;
            Bs[lCol + 2][gn] = b4.z;
            Bs[lCol + 3][gn] = b4.w;
        }
        __syncthreads();

        #pragma unroll
        for (int k = 0; k < TBK; k++) {
            float a[8], b[4];
            *(float4*)&a[0] = *(const float4*)&As[k][ty * 8];
            *(float4*)&a[4] = *(const float4*)&As[k][ty * 8 + 4];
            *(float4*)&b[0] = *(const float4*)&Bs[k][tx * 4];
            #pragma unroll
            for (int i = 0; i < 8; i++)
                #pragma unroll
                for (int j = 0; j < 4; j++)
                    acc[i][j] = fmaf(a[i], b[j], acc[i][j]);
        }
        __syncthreads();
    }

    float pn[4];
    *(float4*)&pn[0] = *(const float4*)(pnorm + tx * 4);

    #pragma unroll
    for (int i = 0; i < 8; i++) {
        int r = rowBase + ty * 8 + i;
        float zn = znorm[r];
        float4 o;
        o.x = 2.0f * acc[i][0] - zn - pn[0];
        o.y = 2.0f * acc[i][1] - zn - pn[1];
        o.z = 2.0f * acc[i][2] - zn - pn[2];
        o.w = 2.0f * acc[i][3] - zn - pn[3];
        *(float4*)(out + (size_t)r * NWAY + tx * 4) = o;
    }
}

// ---------------------------------------------------------------------------
// Host launcher
// ---------------------------------------------------------------------------
extern "C" void kernel_launch(void* const* d_in, const int* in_sizes, int n_in,
                              void* d_out, int out_size) {
    const float* xs = (const float*)d_in[0];
    const void*  ys = d_in[1];
    const float* xq = (const float*)d_in[2];
    const float* W  = (const float*)d_in[3];
    const float* b  = (const float*)d_in[4];

    int S = in_sizes[1];
    int F = in_sizes[0] / S;
    int D = in_sizes[4];
    int Q = in_sizes[2] / F;

    float *p_z, *p_cls, *p_proto, *p_znorm, *p_pnorm, *p_invcnt;
    int *p_ys, *p_cnt;
    cudaGetSymbolAddress((void**)&p_z, g_z);
    cudaGetSymbolAddress((void**)&p_cls, g_cls_sum);
    cudaGetSymbolAddress((void**)&p_proto, g_proto);
    cudaGetSymbolAddress((void**)&p_znorm, g_znorm);
    cudaGetSymbolAddress((void**)&p_pnorm, g_pnorm);
    cudaGetSymbolAddress((void**)&p_invcnt, g_invcnt);
    cudaGetSymbolAddress((void**)&p_ys, g_ys);
    cudaGetSymbolAddress((void**)&p_cnt, g_cnt);

    // 0. zero accumulators
    k_zero<<<(NWAY * F + 255) / 256, 256>>>(p_cls, NWAY * F);
    k_zero<<<(NWAY * D + 255) / 256, 256>>>(p_proto, NWAY * D);
    k_zero<<<(Q + 255) / 256, 256>>>(p_znorm, Q);

    // 1. labels + counts
    k_prep<<<1, 256>>>(ys, S, p_ys, p_invcnt, p_cnt);

    // 2. class sums in F-space (S split 8 ways)
    {
        dim3 grid(F / 128, 8);
        k_cls_sum<<<grid, 128>>>(xs, S, F, p_ys, p_cls);
    }

    // 3. prototypes: proto = (cls_sum * invcnt) @ W  (split-K, atomics)
    {
        int threads = D * (NWAY / 4) * PROTO_KS;
        k_proto<<<threads / 256, 256>>>(p_cls, W, p_invcnt, p_proto, F, D);
    }

    // 4. proto finalize: += bias (non-empty only), pnorm
    k_proto_fin<<<NWAY, 128>>>(p_proto, b, p_cnt, p_pnorm, D);

    // 5. big GEMM on tensor cores: z = xq @ W + b, fused znorm
    {
        dim3 grid(D / GBN, Q / GBM);
        gemm_tf32<<<grid, 256>>>(xq, W, b, p_z, p_znorm, Q, D, F);
    }

    // 6. fused cross-term + epilogue -> output
    {
        dim3 grid(1, Q / TBM);
        gemm_nt_epi<<<grid, 256>>>(p_z, p_proto, p_znorm, p_pnorm,
                                   (float*)d_out, Q, D);
    }
}

// round 5
// speedup vs baseline: 3.4408x; 1.0241x over previous
#include <cuda_runtime.h>
#include <cstdint>

// ---------------------------------------------------------------------------
// ProtoNet: out[q,c] = -||z_q - proto_c||^2
//   z_q   = xq @ W + b                     [Q, D]   (tf32 tensor-core GEMM)
//   proto = (classsum(xs)/count) @ W + b   [64, D]  (linearity of encoder)
//   out   = 2*z_q.proto^T - ||z_q||^2 - ||proto||^2
// Shapes: S=1024, Q=16384, F=2048, D=512, NWAY=64
// ---------------------------------------------------------------------------

#define NWAY 64
#define Q_MAX 16384
#define D_MAX 512
#define F_MAX 2048

__device__ float g_z[(size_t)Q_MAX * D_MAX];        // 32 MB
__device__ float g_cls_sum[NWAY * F_MAX];           // 512 KB
__device__ float g_proto[NWAY * D_MAX];             // 128 KB
__device__ float g_znorm[Q_MAX];
__device__ float g_pnorm[NWAY];
__device__ int   g_ys[4096];
__device__ float g_invcnt[NWAY];
__device__ int   g_cnt[NWAY];

// ---------------------------------------------------------------------------
__global__ void k_zero(float* p, int n) {
    int i = blockIdx.x * blockDim.x + threadIdx.x;
    if (i < n) p[i] = 0.0f;
}

// ---------------------------------------------------------------------------
// k_prep: detect int64-vs-int32 label layout, normalize labels, class counts.
// ---------------------------------------------------------------------------
__global__ void k_prep(const void* ys_raw, int S, int* ys_out, float* invcnt,
                       int* cnt_out) {
    __shared__ int s_is32;
    __shared__ int s_cnt[NWAY];
    int tid = threadIdx.x;
    if (tid == 0) s_is32 = 0;
    if (tid < NWAY) s_cnt[tid] = 0;
    __syncthreads();

    const int* w32 = (const int*)ys_raw;
    for (int j = 1 + 2 * tid; j < S; j += 2 * blockDim.x) {
        if (w32[j] != 0) s_is32 = 1;   // benign race
    }
    __syncthreads();
    int is64 = !s_is32;

    const long long* w64 = (const long long*)ys_raw;
    for (int i = tid; i < S; i += blockDim.x) {
        int c = is64 ? (int)w64[i] : w32[i];
        ys_out[i] = c;
        atomicAdd(&s_cnt[c], 1);
    }
    __syncthreads();
    if (tid < NWAY) {
        int c = s_cnt[tid];
        cnt_out[tid] = c;
        invcnt[tid] = 1.0f / (float)(c > 0 ? c : 1);
    }
}

// ---------------------------------------------------------------------------
// k_cls_sum: per-class SUM of xs in F-space, S split 8 ways, atomic combine.
// grid (F/128, 8), block 128.
// ---------------------------------------------------------------------------
__global__ void k_cls_sum(const float* __restrict__ xs, int S, int F,
                          const int* __restrict__ ys,
                          float* __restrict__ cls_sum) {
    __shared__ float acc[NWAY][128];
    __shared__ int s_ys[256];
    int tid = threadIdx.x;
    int f = blockIdx.x * 128 + tid;
    int chunk = S / gridDim.y;
    int s0 = blockIdx.y * chunk;

    #pragma unroll
    for (int c = 0; c < NWAY; c++) acc[c][tid] = 0.0f;
    for (int i = tid; i < chunk; i += blockDim.x) s_ys[i] = ys[s0 + i];
    __syncthreads();

    #pragma unroll 4
    for (int i = 0; i < chunk; i++) {
        acc[s_ys[i]][tid] += xs[(size_t)(s0 + i) * F + f];
    }
    __syncthreads();

    #pragma unroll
    for (int c = 0; c < NWAY; c++) {
        atomicAdd(&cls_sum[(size_t)c * F + f], acc[c][tid]);
    }
}

// ---------------------------------------------------------------------------
// k_proto: proto[m][d] += invcnt[m] * sum_k cls_sum[m][k] * W[k][d]
// split-K (8) + 4-way m reuse. grid = D*16*8/256 blocks, block 256.
// proto pre-zeroed.
// ---------------------------------------------------------------------------
#define PROTO_KS 8
__global__ void k_proto(const float* __restrict__ cls_sum,
                        const float* __restrict__ W,
                        const float* __restrict__ invcnt,
                        float* __restrict__ proto, int F, int D) {
    int idx = blockIdx.x * blockDim.x + threadIdx.x;
    int d  = idx % D;
    int mg = (idx / D) % (NWAY / 4);
    int ks = idx / (D * (NWAY / 4));
    int kper = F / PROTO_KS;
    int k0 = ks * kper;

    const float* a = cls_sum + (size_t)(mg * 4) * F + k0;
    const float* w = W + (size_t)k0 * D + d;

    float s0 = 0.f, s1 = 0.f, s2 = 0.f, s3 = 0.f;
    #pragma unroll 4
    for (int k = 0; k < kper; k++) {
        float wv = w[(size_t)k * D];
        s0 = fmaf(a[k], wv, s0);
        s1 = fmaf(a[k + F], wv, s1);
        s2 = fmaf(a[k + 2 * F], wv, s2);
        s3 = fmaf(a[k + 3 * F], wv, s3);
    }
    int m = mg * 4;
    atomicAdd(&proto[(size_t)(m + 0) * D + d], s0 * invcnt[m + 0]);
    atomicAdd(&proto[(size_t)(m + 1) * D + d], s1 * invcnt[m + 1]);
    atomicAdd(&proto[(size_t)(m + 2) * D + d], s2 * invcnt[m + 2]);
    atomicAdd(&proto[(size_t)(m + 3) * D + d], s3 * invcnt[m + 3]);
}

// ---------------------------------------------------------------------------
// k_proto_fin: proto[c][d] += b[d] (only if class non-empty, matching
// reference clip semantics where empty class -> all zeros), pnorm[c]=||row||^2
// grid 64, block 128.
// ---------------------------------------------------------------------------
__global__ void k_proto_fin(float* __restrict__ proto,
                            const float* __restrict__ bias,
                            const int* __restrict__ cnt,
                            float* __restrict__ pnorm, int D) {
    __shared__ float red[128];
    int c = blockIdx.x;
    int tid = threadIdx.x;
    bool nonempty = cnt[c] > 0;
    float s = 0.f;
    for (int d = tid; d < D; d += blockDim.x) {
        float v = proto[(size_t)c * D + d] + (nonempty ? bias[d] : 0.0f);
        proto[(size_t)c * D + d] = v;
        s = fmaf(v, v, s);
    }
    red[tid] = s;
    __syncthreads();
    for (int o = 64; o > 0; o >>= 1) {
        if (tid < o) red[tid] += red[tid + o];
        __syncthreads();
    }
    if (tid == 0) pnorm[c] = red[0];
}

// ---------------------------------------------------------------------------
// gemm_tf32: Z[M,N] = A[M,K] @ W[K,N] + bias ; also znorm[m] += ||row tile||^2
// tf32 mma.sync m16n8k8, BM=128 BN=128 BK=16, 8 warps (2x4 of 64x32 tiles),
// double-buffered smem. Requires M%128==0, N%128==0, K%16==0.
// ---------------------------------------------------------------------------
#define GBM 128
#define GBN 128
#define GBK 16
#define AS_STRIDE 20    // 16 + 4 pad  -> conflict-free A-fragment LDS
#define BS_STRIDE 136   // 128 + 8 pad -> conflict-free B-fragment LDS

__device__ __forceinline__ float f2tf32(float x) {
    unsigned u;
    asm("cvt.rna.tf32.f32 %0, %1;" : "=r"(u) : "f"(x));
    return __uint_as_float(u);
}

__device__ __forceinline__ void mma8(float* d, const float* a, const float* b) {
    const unsigned* A = reinterpret_cast<const unsigned*>(a);
    const unsigned* B = reinterpret_cast<const unsigned*>(b);
    asm volatile(
        "mma.sync.aligned.m16n8k8.row.col.f32.tf32.tf32.f32 "
        "{%0,%1,%2,%3}, {%4,%5,%6,%7}, {%8,%9}, {%0,%1,%2,%3};\n"
        : "+f"(d[0]), "+f"(d[1]), "+f"(d[2]), "+f"(d[3])
        : "r"(A[0]), "r"(A[1]), "r"(A[2]), "r"(A[3]), "r"(B[0]), "r"(B[1]));
}

__global__ __launch_bounds__(256, 2) void gemm_tf32(
    const float* __restrict__ A, const float* __restrict__ W,
    const float* __restrict__ bias, float* __restrict__ Z,
    float* __restrict__ znorm, int M, int N, int K)
{
    __shared__ float As[2][GBM * AS_STRIDE];
    __shared__ float Bs[2][GBK * BS_STRIDE];

    int tid  = threadIdx.x;
    int warp = tid >> 5, lane = tid & 31;
    int wm = warp & 1;        // 0..1  (64-row half)
    int wn = warp >> 1;       // 0..3  (32-col strip)
    int rowBase = blockIdx.y * GBM;
    int colBase = blockIdx.x * GBN;

    // global loaders
    int arow = tid >> 1;                // 0..127
    int acol = (tid & 1) * 8;           // 0 / 8
    const float* aptr = A + (size_t)(rowBase + arow) * K + acol;
    int brow = tid >> 4;                // 0..15
    int bcol = (tid & 15) * 8;
    const float* bptr = W + (size_t)brow * N + colBase + bcol;

    float acc[4][4][4];
    #pragma unroll
    for (int i = 0; i < 4; i++)
        #pragma unroll
        for (int j = 0; j < 4; j++)
            #pragma unroll
            for (int r = 0; r < 4; r++) acc[i][j][r] = 0.0f;

    int lg = lane >> 2;      // 0..7
    int lq = lane & 3;       // 0..3

    // precomputed smem read offsets
    int aoff[4], boff[4];
    #pragma unroll
    for (int mt = 0; mt < 4; mt++)
        aoff[mt] = (wm * 64 + mt * 16 + lg) * AS_STRIDE + lq;
    #pragma unroll
    for (int nt = 0; nt < 4; nt++)
        boff[nt] = lq * BS_STRIDE + wn * 32 + nt * 8 + lg;

    // prologue: load chunk 0
    float4 pa0 = *(const float4*)(aptr);
    float4 pa1 = *(const float4*)(aptr + 4);
    float4 pb0 = *(const float4*)(bptr);
    float4 pb1 = *(const float4*)(bptr + 4);

    int asmoff = arow * AS_STRIDE + acol;
    int bsmoff = brow * BS_STRIDE + bcol;
    {
        float4 t;
        t.x=f2tf32(pa0.x); t.y=f2tf32(pa0.y); t.z=f2tf32(pa0.z); t.w=f2tf32(pa0.w);
        *(float4*)&As[0][asmoff] = t;
        t.x=f2tf32(pa1.x); t.y=f2tf32(pa1.y); t.z=f2tf32(pa1.z); t.w=f2tf32(pa1.w);
        *(float4*)&As[0][asmoff + 4] = t;
        t.x=f2tf32(pb0.x); t.y=f2tf32(pb0.y); t.z=f2tf32(pb0.z); t.w=f2tf32(pb0.w);
        *(float4*)&Bs[0][bsmoff] = t;
        t.x=f2tf32(pb1.x); t.y=f2tf32(pb1.y); t.z=f2tf32(pb1.z); t.w=f2tf32(pb1.w);
        *(float4*)&Bs[0][bsmoff + 4] = t;
    }
    __syncthreads();

    int nIt = K / GBK;
    int buf = 0;
    for (int it = 0; it < nIt; ++it) {
        bool has = (it + 1) < nIt;
        if (has) {
            const float* ap = aptr + (it + 1) * GBK;
            const float* bp = bptr + (size_t)(it + 1) * GBK * N;
            pa0 = *(const float4*)(ap);
            pa1 = *(const float4*)(ap + 4);
            pb0 = *(const float4*)(bp);
            pb1 = *(const float4*)(bp + 4);
        }

        #pragma unroll
        for (int kk = 0; kk < GBK; kk += 8) {
            float af[4][4], bf[4][2];
            #pragma unroll
            for (int mt = 0; mt < 4; mt++) {
                const float* base = &As[buf][aoff[mt] + kk];
                af[mt][0] = base[0];
                af[mt][1] = base[8 * AS_STRIDE];
                af[mt][2] = base[4];
                af[mt][3] = base[8 * AS_STRIDE + 4];
            }
            #pragma unroll
            for (int nt = 0; nt < 4; nt++) {
                const float* base = &Bs[buf][boff[nt] + kk * BS_STRIDE];
                bf[nt][0] = base[0];
                bf[nt][1] = base[4 * BS_STRIDE];
            }
            #pragma unroll
            for (int mt = 0; mt < 4; mt++)
                #pragma unroll
                for (int nt = 0; nt < 4; nt++)
                    mma8(acc[mt][nt], af[mt], bf[nt]);
        }

        if (has) {
            int nb = buf ^ 1;
            float4 t;
            t.x=f2tf32(pa0.x); t.y=f2tf32(pa0.y); t.z=f2tf32(pa0.z); t.w=f2tf32(pa0.w);
            *(float4*)&As[nb][asmoff] = t;
            t.x=f2tf32(pa1.x); t.y=f2tf32(pa1.y); t.z=f2tf32(pa1.z); t.w=f2tf32(pa1.w);
            *(float4*)&As[nb][asmoff + 4] = t;
            t.x=f2tf32(pb0.x); t.y=f2tf32(pb0.y); t.z=f2tf32(pb0.z); t.w=f2tf32(pb0.w);
            *(float4*)&Bs[nb][bsmoff] = t;
            t.x=f2tf32(pb1.x); t.y=f2tf32(pb1.y); t.z=f2tf32(pb1.z); t.w=f2tf32(pb1.w);
            *(float4*)&Bs[nb][bsmoff + 4] = t;
            __syncthreads();
            buf = nb;
        }
    }

    // epilogue: add bias, store Z, accumulate ||row||^2 into znorm
    #pragma unroll
    for (int mt = 0; mt < 4; mt++) {
        int r0 = rowBase + wm * 64 + mt * 16 + lg;
        float sum0 = 0.f, sum1 = 0.f;
        #pragma unroll
        for (int nt = 0; nt < 4; nt++) {
            int cb = colBase + wn * 32 + nt * 8 + lq * 2;
            float bv0 = bias[cb], bv1 = bias[cb + 1];
            float v0 = acc[mt][nt][0] + bv0;
            float v1 = acc[mt][nt][1] + bv1;
            float v2 = acc[mt][nt][2] + bv0;
            float v3 = acc[mt][nt][3] + bv1;
            *(float2*)(Z + (size_t)r0 * N + cb)       = make_float2(v0, v1);
            *(float2*)(Z + (size_t)(r0 + 8) * N + cb) = make_float2(v2, v3);
            sum0 = fmaf(v0, v0, fmaf(v1, v1, sum0));
            sum1 = fmaf(v2, v2, fmaf(v3, v3, sum1));
        }
        // reduce across the 4 lanes of the quad (same row)
        sum0 += __shfl_xor_sync(0xFFFFFFFFu, sum0, 1);
        sum0 += __shfl_xor_sync(0xFFFFFFFFu, sum0, 2);
        sum1 += __shfl_xor_sync(0xFFFFFFFFu, sum1, 1);
        sum1 += __shfl_xor_sync(0xFFFFFFFFu, sum1, 2);
        if (lq == 0) {
            atomicAdd(&znorm[r0], sum0);
            atomicAdd(&znorm[r0 + 8], sum1);
        }
    }
}

// ---------------------------------------------------------------------------
// gemm_nt_epi: out[q,c] = 2 * dot(z[q,:], proto[c,:]) - znorm[q] - pnorm[c]
// ---------------------------------------------------------------------------
#define TBM 128
#define TBK 32
__global__ __launch_bounds__(256) void gemm_nt_epi(
    const float* __restrict__ A, const float* __restrict__ B,
    const float* __restrict__ znorm, const float* __restrict__ pnorm,
    float* __restrict__ out, int M, int K)
{
    __shared__ float As[TBK][TBM];
    __shared__ float Bs[TBK][NWAY];

    int tid = threadIdx.x;
    int rowBase = blockIdx.y * TBM;
    int ty = tid >> 4;
    int tx = tid & 15;

    float acc[8][4];
    #pragma unroll
    for (int i = 0; i < 8; i++)
        #pragma unroll
        for (int j = 0; j < 4; j++) acc[i][j] = 0.0f;

    int lCol = (tid & 7) * 4;
    int lRow = tid >> 3;

    for (int k0 = 0; k0 < K; k0 += TBK) {
        #pragma unroll
        for (int r = 0; r < 4; r++) {
            int gr = rowBase + lRow + r * 32;
            float4 a4 = *(const float4*)(A + (size_t)gr * K + k0 + lCol);
            As[lCol + 0][lRow + r * 32] = a4.x;
            As[lCol + 1][lRow + r * 32] = a4.y;
            As[lCol + 2][lRow + r * 32] = a4.z;
            As[lCol + 3][lRow + r * 32] = a4.w;
        }
        #pragma unroll
        for (int r = 0; r < 2; r++) {
            int gn = lRow + r * 32;
            float4 b4 = *(const float4*)(B + (size_t)gn * K + k0 + lCol);
            Bs[lCol + 0][gn] = b4.x;
            Bs[lCol + 1][gn] = b4.y;
            Bs[lCol + 2][gn] = b4.z;
            Bs[lCol + 3][gn] = b4.w;
        }
        __syncthreads();

        #pragma unroll
        for (int k = 0; k < TBK; k++) {
            float a[8], b[4];
            *(float4*)&a[0] = *(const float4*)&As[k][ty * 8];
            *(float4*)&a[4] = *(const float4*)&As[k][ty * 8 + 4];
            *(float4*)&b[0] = *(const float4*)&Bs[k][tx * 4];
            #pragma unroll
            for (int i = 0; i < 8; i++)
                #pragma unroll
                for (int j = 0; j < 4; j++)
                    acc[i][j] = fmaf(a[i], b[j], acc[i][j]);
        }
        __syncthreads();
    }

    float pn[4];
    *(float4*)&pn[0] = *(const float4*)(pnorm + tx * 4);

    #pragma unroll
    for (int i = 0; i < 8; i++) {
        int r = rowBase + ty * 8 + i;
        float zn = znorm[r];
        float4 o;
        o.x = 2.0f * acc[i][0] - zn - pn[0];
        o.y = 2.0f * acc[i][1] - zn - pn[1];
        o.z = 2.0f * acc[i][2] - zn - pn[2];
        o.w = 2.0f * acc[i][3] - zn - pn[3];
        *(float4*)(out + (size_t)r * NWAY + tx * 4) = o;
    }
}

// ---------------------------------------------------------------------------
// Host launcher
// ---------------------------------------------------------------------------
extern "C" void kernel_launch(void* const* d_in, const int* in_sizes, int n_in,
                              void* d_out, int out_size) {
    const float* xs = (const float*)d_in[0];
    const void*  ys = d_in[1];
    const float* xq = (const float*)d_in[2];
    const float* W  = (const float*)d_in[3];
    const float* b  = (const float*)d_in[4];

    int S = in_sizes[1];
    int F = in_sizes[0] / S;
    int D = in_sizes[4];
    int Q = in_sizes[2] / F;

    float *p_z, *p_cls, *p_proto, *p_znorm, *p_pnorm, *p_invcnt;
    int *p_ys, *p_cnt;
    cudaGetSymbolAddress((void**)&p_z, g_z);
    cudaGetSymbolAddress((void**)&p_cls, g_cls_sum);
    cudaGetSymbolAddress((void**)&p_proto, g_proto);
    cudaGetSymbolAddress((void**)&p_znorm, g_znorm);
    cudaGetSymbolAddress((void**)&p_pnorm, g_pnorm);
    cudaGetSymbolAddress((void**)&p_invcnt, g_invcnt);
    cudaGetSymbolAddress((void**)&p_ys, g_ys);
    cudaGetSymbolAddress((void**)&p_cnt, g_cnt);

    // 0. zero accumulators
    k_zero<<<(NWAY * F + 255) / 256, 256>>>(p_cls, NWAY * F);
    k_zero<<<(NWAY * D + 255) / 256, 256>>>(p_proto, NWAY * D);
    k_zero<<<(Q + 255) / 256, 256>>>(p_znorm, Q);

    // 1. labels + counts
    k_prep<<<1, 256>>>(ys, S, p_ys, p_invcnt, p_cnt);

    // 2. class sums in F-space (S split 8 ways)
    {
        dim3 grid(F / 128, 8);
        k_cls_sum<<<grid, 128>>>(xs, S, F, p_ys, p_cls);
    }

    // 3. prototypes: proto = (cls_sum * invcnt) @ W  (split-K, atomics)
    {
        int threads = D * (NWAY / 4) * PROTO_KS;
        k_proto<<<threads / 256, 256>>>(p_cls, W, p_invcnt, p_proto, F, D);
    }

    // 4. proto finalize: += bias (non-empty only), pnorm
    k_proto_fin<<<NWAY, 128>>>(p_proto, b, p_cnt, p_pnorm, D);

    // 5. big GEMM on tensor cores: z = xq @ W + b, fused znorm
    {
        dim3 grid(D / GBN, Q / GBM);
        gemm_tf32<<<grid, 256>>>(xq, W, b, p_z, p_znorm, Q, D, F);
    }

    // 6. fused cross-term + epilogue -> output
    {
        dim3 grid(1, Q / TBM);
        gemm_nt_epi<<<grid, 256>>>(p_z, p_proto, p_znorm, p_pnorm,
                                   (float*)d_out, Q, D);
    }
}

// round 6
// speedup vs baseline: 3.4410x; 1.0001x over previous
#include <cuda_runtime.h>
#include <cstdint>

// ---------------------------------------------------------------------------
// ProtoNet: out[q,c] = -||z_q - proto_c||^2
//   z_q   = xq @ W + b                     [Q, D]   (tf32 tensor-core GEMM)
//   proto = (classsum(xs)/count) @ W + b   [64, D]  (linearity of encoder)
//   out   = 2*z_q.proto^T - ||z_q||^2 - ||proto||^2
// Shapes: S=1024, Q=16384, F=2048, D=512, NWAY=64
// ---------------------------------------------------------------------------

#define NWAY 64
#define Q_MAX 16384
#define D_MAX 512
#define F_MAX 2048

__device__ float g_z[(size_t)Q_MAX * D_MAX];        // 32 MB
__device__ float g_cls_sum[NWAY * F_MAX];           // 512 KB
__device__ float g_proto[NWAY * D_MAX];             // 128 KB
__device__ float g_znorm[Q_MAX];
__device__ float g_pnorm[NWAY];
__device__ int   g_ys[4096];
__device__ float g_invcnt[NWAY];
__device__ int   g_cnt[NWAY];

// ---------------------------------------------------------------------------
__global__ void k_zero(float* p, int n) {
    int i = blockIdx.x * blockDim.x + threadIdx.x;
    if (i < n) p[i] = 0.0f;
}

// ---------------------------------------------------------------------------
// k_prep: detect int64-vs-int32 label layout, normalize labels, class counts.
// ---------------------------------------------------------------------------
__global__ void k_prep(const void* ys_raw, int S, int* ys_out, float* invcnt,
                       int* cnt_out) {
    __shared__ int s_is32;
    __shared__ int s_cnt[NWAY];
    int tid = threadIdx.x;
    if (tid == 0) s_is32 = 0;
    if (tid < NWAY) s_cnt[tid] = 0;
    __syncthreads();

    const int* w32 = (const int*)ys_raw;
    for (int j = 1 + 2 * tid; j < S; j += 2 * blockDim.x) {
        if (w32[j] != 0) s_is32 = 1;   // benign race
    }
    __syncthreads();
    int is64 = !s_is32;

    const long long* w64 = (const long long*)ys_raw;
    for (int i = tid; i < S; i += blockDim.x) {
        int c = is64 ? (int)w64[i] : w32[i];
        ys_out[i] = c;
        atomicAdd(&s_cnt[c], 1);
    }
    __syncthreads();
    if (tid < NWAY) {
        int c = s_cnt[tid];
        cnt_out[tid] = c;
        invcnt[tid] = 1.0f / (float)(c > 0 ? c : 1);
    }
}

// ---------------------------------------------------------------------------
// k_cls_sum: per-class SUM of xs in F-space, S split 8 ways, atomic combine.
// grid (F/128, 8), block 128.
// ---------------------------------------------------------------------------
__global__ void k_cls_sum(const float* __restrict__ xs, int S, int F,
                          const int* __restrict__ ys,
                          float* __restrict__ cls_sum) {
    __shared__ float acc[NWAY][128];
    __shared__ int s_ys[256];
    int tid = threadIdx.x;
    int f = blockIdx.x * 128 + tid;
    int chunk = S / gridDim.y;
    int s0 = blockIdx.y * chunk;

    #pragma unroll
    for (int c = 0; c < NWAY; c++) acc[c][tid] = 0.0f;
    for (int i = tid; i < chunk; i += blockDim.x) s_ys[i] = ys[s0 + i];
    __syncthreads();

    #pragma unroll 4
    for (int i = 0; i < chunk; i++) {
        acc[s_ys[i]][tid] += xs[(size_t)(s0 + i) * F + f];
    }
    __syncthreads();

    #pragma unroll
    for (int c = 0; c < NWAY; c++) {
        atomicAdd(&cls_sum[(size_t)c * F + f], acc[c][tid]);
    }
}

// ---------------------------------------------------------------------------
// k_proto: proto[m][d] += invcnt[m] * sum_k cls_sum[m][k] * W[k][d]
// split-K (8) + 4-way m reuse. grid = D*16*8/256 blocks, block 256.
// proto pre-zeroed.
// ---------------------------------------------------------------------------
#define PROTO_KS 8
__global__ void k_proto(const float* __restrict__ cls_sum,
                        const float* __restrict__ W,
                        const float* __restrict__ invcnt,
                        float* __restrict__ proto, int F, int D) {
    int idx = blockIdx.x * blockDim.x + threadIdx.x;
    int d  = idx % D;
    int mg = (idx / D) % (NWAY / 4);
    int ks = idx / (D * (NWAY / 4));
    int kper = F / PROTO_KS;
    int k0 = ks * kper;

    const float* a = cls_sum + (size_t)(mg * 4) * F + k0;
    const float* w = W + (size_t)k0 * D + d;

    float s0 = 0.f, s1 = 0.f, s2 = 0.f, s3 = 0.f;
    #pragma unroll 4
    for (int k = 0; k < kper; k++) {
        float wv = w[(size_t)k * D];
        s0 = fmaf(a[k], wv, s0);
        s1 = fmaf(a[k + F], wv, s1);
        s2 = fmaf(a[k + 2 * F], wv, s2);
        s3 = fmaf(a[k + 3 * F], wv, s3);
    }
    int m = mg * 4;
    atomicAdd(&proto[(size_t)(m + 0) * D + d], s0 * invcnt[m + 0]);
    atomicAdd(&proto[(size_t)(m + 1) * D + d], s1 * invcnt[m + 1]);
    atomicAdd(&proto[(size_t)(m + 2) * D + d], s2 * invcnt[m + 2]);
    atomicAdd(&proto[(size_t)(m + 3) * D + d], s3 * invcnt[m + 3]);
}

// ---------------------------------------------------------------------------
// k_proto_fin: proto[c][d] += b[d] (only if class non-empty, matching
// reference clip semantics where empty class -> all zeros), pnorm[c]=||row||^2
// grid 64, block 128.
// ---------------------------------------------------------------------------
__global__ void k_proto_fin(float* __restrict__ proto,
                            const float* __restrict__ bias,
                            const int* __restrict__ cnt,
                            float* __restrict__ pnorm, int D) {
    __shared__ float red[128];
    int c = blockIdx.x;
    int tid = threadIdx.x;
    bool nonempty = cnt[c] > 0;
    float s = 0.f;
    for (int d = tid; d < D; d += blockDim.x) {
        float v = proto[(size_t)c * D + d] + (nonempty ? bias[d] : 0.0f);
        proto[(size_t)c * D + d] = v;
        s = fmaf(v, v, s);
    }
    red[tid] = s;
    __syncthreads();
    for (int o = 64; o > 0; o >>= 1) {
        if (tid < o) red[tid] += red[tid + o];
        __syncthreads();
    }
    if (tid == 0) pnorm[c] = red[0];
}

// ---------------------------------------------------------------------------
// gemm_tf32: Z[M,N] = A[M,K] @ W[K,N] + bias ; also znorm[m] += ||row tile||^2
// tf32 mma.sync m16n8k8, BM=128 BN=128 BK=16, 8 warps (2x4 of 64x32 tiles),
// double-buffered smem. Requires M%128==0, N%128==0, K%16==0.
// ---------------------------------------------------------------------------
#define GBM 128
#define GBN 128
#define GBK 16
#define AS_STRIDE 20    // 16 + 4 pad  -> conflict-free A-fragment LDS
#define BS_STRIDE 136   // 128 + 8 pad -> conflict-free B-fragment LDS

__device__ __forceinline__ float f2tf32(float x) {
    unsigned u;
    asm("cvt.rna.tf32.f32 %0, %1;" : "=r"(u) : "f"(x));
    return __uint_as_float(u);
}

__device__ __forceinline__ void mma8(float* d, const float* a, const float* b) {
    const unsigned* A = reinterpret_cast<const unsigned*>(a);
    const unsigned* B = reinterpret_cast<const unsigned*>(b);
    asm volatile(
        "mma.sync.aligned.m16n8k8.row.col.f32.tf32.tf32.f32 "
        "{%0,%1,%2,%3}, {%4,%5,%6,%7}, {%8,%9}, {%0,%1,%2,%3};\n"
        : "+f"(d[0]), "+f"(d[1]), "+f"(d[2]), "+f"(d[3])
        : "r"(A[0]), "r"(A[1]), "r"(A[2]), "r"(A[3]), "r"(B[0]), "r"(B[1]));
}

__global__ __launch_bounds__(256, 2) void gemm_tf32(
    const float* __restrict__ A, const float* __restrict__ W,
    const float* __restrict__ bias, float* __restrict__ Z,
    float* __restrict__ znorm, int M, int N, int K)
{
    __shared__ float As[2][GBM * AS_STRIDE];
    __shared__ float Bs[2][GBK * BS_STRIDE];

    int tid  = threadIdx.x;
    int warp = tid >> 5, lane = tid & 31;
    int wm = warp & 1;        // 0..1  (64-row half)
    int wn = warp >> 1;       // 0..3  (32-col strip)
    int rowBase = blockIdx.y * GBM;
    int colBase = blockIdx.x * GBN;

    // global loaders
    int arow = tid >> 1;                // 0..127
    int acol = (tid & 1) * 8;           // 0 / 8
    const float* aptr = A + (size_t)(rowBase + arow) * K + acol;
    int brow = tid >> 4;                // 0..15
    int bcol = (tid & 15) * 8;
    const float* bptr = W + (size_t)brow * N + colBase + bcol;

    float acc[4][4][4];
    #pragma unroll
    for (int i = 0; i < 4; i++)
        #pragma unroll
        for (int j = 0; j < 4; j++)
            #pragma unroll
            for (int r = 0; r < 4; r++) acc[i][j][r] = 0.0f;

    int lg = lane >> 2;      // 0..7
    int lq = lane & 3;       // 0..3

    // precomputed smem read offsets
    int aoff[4], boff[4];
    #pragma unroll
    for (int mt = 0; mt < 4; mt++)
        aoff[mt] = (wm * 64 + mt * 16 + lg) * AS_STRIDE + lq;
    #pragma unroll
    for (int nt = 0; nt < 4; nt++)
        boff[nt] = lq * BS_STRIDE + wn * 32 + nt * 8 + lg;

    // prologue: load chunk 0
    float4 pa0 = *(const float4*)(aptr);
    float4 pa1 = *(const float4*)(aptr + 4);
    float4 pb0 = *(const float4*)(bptr);
    float4 pb1 = *(const float4*)(bptr + 4);

    int asmoff = arow * AS_STRIDE + acol;
    int bsmoff = brow * BS_STRIDE + bcol;
    {
        float4 t;
        t.x=f2tf32(pa0.x); t.y=f2tf32(pa0.y); t.z=f2tf32(pa0.z); t.w=f2tf32(pa0.w);
        *(float4*)&As[0][asmoff] = t;
        t.x=f2tf32(pa1.x); t.y=f2tf32(pa1.y); t.z=f2tf32(pa1.z); t.w=f2tf32(pa1.w);
        *(float4*)&As[0][asmoff + 4] = t;
        t.x=f2tf32(pb0.x); t.y=f2tf32(pb0.y); t.z=f2tf32(pb0.z); t.w=f2tf32(pb0.w);
        *(float4*)&Bs[0][bsmoff] = t;
        t.x=f2tf32(pb1.x); t.y=f2tf32(pb1.y); t.z=f2tf32(pb1.z); t.w=f2tf32(pb1.w);
        *(float4*)&Bs[0][bsmoff + 4] = t;
    }
    __syncthreads();

    int nIt = K / GBK;
    int buf = 0;
    for (int it = 0; it < nIt; ++it) {
        bool has = (it + 1) < nIt;
        if (has) {
            const float* ap = aptr + (it + 1) * GBK;
            const float* bp = bptr + (size_t)(it + 1) * GBK * N;
            pa0 = *(const float4*)(ap);
            pa1 = *(const float4*)(ap + 4);
            pb0 = *(const float4*)(bp);
            pb1 = *(const float4*)(bp + 4);
        }

        #pragma unroll
        for (int kk = 0; kk < GBK; kk += 8) {
            float af[4][4], bf[4][2];
            #pragma unroll
            for (int mt = 0; mt < 4; mt++) {
                const float* base = &As[buf][aoff[mt] + kk];
                af[mt][0] = base[0];
                af[mt][1] = base[8 * AS_STRIDE];
                af[mt][2] = base[4];
                af[mt][3] = base[8 * AS_STRIDE + 4];
            }
            #pragma unroll
            for (int nt = 0; nt < 4; nt++) {
                const float* base = &Bs[buf][boff[nt] + kk * BS_STRIDE];
                bf[nt][0] = base[0];
                bf[nt][1] = base[4 * BS_STRIDE];
            }
            #pragma unroll
            for (int mt = 0; mt < 4; mt++)
                #pragma unroll
                for (int nt = 0; nt < 4; nt++)
                    mma8(acc[mt][nt], af[mt], bf[nt]);
        }

        if (has) {
            int nb = buf ^ 1;
            float4 t;
            t.x=f2tf32(pa0.x); t.y=f2tf32(pa0.y); t.z=f2tf32(pa0.z); t.w=f2tf32(pa0.w);
            *(float4*)&As[nb][asmoff] = t;
            t.x=f2tf32(pa1.x); t.y=f2tf32(pa1.y); t.z=f2tf32(pa1.z); t.w=f2tf32(pa1.w);
            *(float4*)&As[nb][asmoff + 4] = t;
            t.x=f2tf32(pb0.x); t.y=f2tf32(pb0.y); t.z=f2tf32(pb0.z); t.w=f2tf32(pb0.w);
            *(float4*)&Bs[nb][bsmoff] = t;
            t.x=f2tf32(pb1.x); t.y=f2tf32(pb1.y); t.z=f2tf32(pb1.z); t.w=f2tf32(pb1.w);
            *(float4*)&Bs[nb][bsmoff + 4] = t;
            __syncthreads();
            buf = nb;
        }
    }

    // epilogue: add bias, store Z, accumulate ||row||^2 into znorm
    #pragma unroll
    for (int mt = 0; mt < 4; mt++) {
        int r0 = rowBase + wm * 64 + mt * 16 + lg;
        float sum0 = 0.f, sum1 = 0.f;
        #pragma unroll
        for (int nt = 0; nt < 4; nt++) {
            int cb = colBase + wn * 32 + nt * 8 + lq * 2;
            float bv0 = bias[cb], bv1 = bias[cb + 1];
            float v0 = acc[mt][nt][0] + bv0;
            float v1 = acc[mt][nt][1] + bv1;
            float v2 = acc[mt][nt][2] + bv0;
            float v3 = acc[mt][nt][3] + bv1;
            *(float2*)(Z + (size_t)r0 * N + cb)       = make_float2(v0, v1);
            *(float2*)(Z + (size_t)(r0 + 8) * N + cb) = make_float2(v2, v3);
            sum0 = fmaf(v0, v0, fmaf(v1, v1, sum0));
            sum1 = fmaf(v2, v2, fmaf(v3, v3, sum1));
        }
        // reduce across the 4 lanes of the quad (same row)
        sum0 += __shfl_xor_sync(0xFFFFFFFFu, sum0, 1);
        sum0 += __shfl_xor_sync(0xFFFFFFFFu, sum0, 2);
        sum1 += __shfl_xor_sync(0xFFFFFFFFu, sum1, 1);
        sum1 += __shfl_xor_sync(0xFFFFFFFFu, sum1, 2);
        if (lq == 0) {
            atomicAdd(&znorm[r0], sum0);
            atomicAdd(&znorm[r0 + 8], sum1);
        }
    }
}

// ---------------------------------------------------------------------------
// gemm_nt_epi: out[q,c] = 2 * dot(z[q,:], proto[c,:]) - znorm[q] - pnorm[c]
// ---------------------------------------------------------------------------
#define TBM 128
#define TBK 32
__global__ __launch_bounds__(256) void gemm_nt_epi(
    const float* __restrict__ A, const float* __restrict__ B,
    const float* __restrict__ znorm, const float* __restrict__ pnorm,
    float* __restrict__ out, int M, int K)
{
    __shared__ float As[TBK][TBM];
    __shared__ float Bs[TBK][NWAY];

    int tid = threadIdx.x;
    int rowBase = blockIdx.y * TBM;
    int ty = tid >> 4;
    int tx = tid & 15;

    float acc[8][4];
    #pragma unroll
    for (int i = 0; i < 8; i++)
        #pragma unroll
        for (int j = 0; j < 4; j++) acc[i][j] = 0.0f;

    int lCol = (tid & 7) * 4;
    int lRow = tid >> 3;

    for (int k0 = 0; k0 < K; k0 += TBK) {
        #pragma unroll
        for (int r = 0; r < 4; r++) {
            int gr = rowBase + lRow + r * 32;
            float4 a4 = *(const float4*)(A + (size_t)gr * K + k0 + lCol);
            As[lCol + 0][lRow + r * 32] = a4.x;
            As[lCol + 1][lRow + r * 32] = a4.y;
            As[lCol + 2][lRow + r * 32] = a4.z;
            As[lCol + 3][lRow + r * 32] = a4.w;
        }
        #pragma unroll
        for (int r = 0; r < 2; r++) {
            int gn = lRow + r * 32;
            float4 b4 = *(const float4*)(B + (size_t)gn * K + k0 + lCol);
            Bs[lCol + 0][gn] = b4.x;
            Bs[lCol + 1][gn] = b4.y;
            Bs[lCol + 2][gn] = b4.z;
            Bs[lCol + 3][gn] = b4.w;
        }
        __syncthreads();

        #pragma unroll
        for (int k = 0; k < TBK; k++) {
            float a[8], b[4];
            *(float4*)&a[0] = *(const float4*)&As[k][ty * 8];
            *(float4*)&a[4] = *(const float4*)&As[k][ty * 8 + 4];
            *(float4*)&b[0] = *(const float4*)&Bs[k][tx * 4];
            #pragma unroll
            for (int i = 0; i < 8; i++)
                #pragma unroll
                for (int j = 0; j < 4; j++)
                    acc[i][j] = fmaf(a[i], b[j], acc[i][j]);
        }
        __syncthreads();
    }

    float pn[4];
    *(float4*)&pn[0] = *(const float4*)(pnorm + tx * 4);

    #pragma unroll
    for (int i = 0; i < 8; i++) {
        int r = rowBase + ty * 8 + i;
        float zn = znorm[r];
        float4 o;
        o.x = 2.0f * acc[i][0] - zn - pn[0];
        o.y = 2.0f * acc[i][1] - zn - pn[1];
        o.z = 2.0f * acc[i][2] - zn - pn[2];
        o.w = 2.0f * acc[i][3] - zn - pn[3];
        *(float4*)(out + (size_t)r * NWAY + tx * 4) = o;
    }
}

// ---------------------------------------------------------------------------
// Host launcher
// ---------------------------------------------------------------------------
extern "C" void kernel_launch(void* const* d_in, const int* in_sizes, int n_in,
                              void* d_out, int out_size) {
    const float* xs = (const float*)d_in[0];
    const void*  ys = d_in[1];
    const float* xq = (const float*)d_in[2];
    const float* W  = (const float*)d_in[3];
    const float* b  = (const float*)d_in[4];

    int S = in_sizes[1];
    int F = in_sizes[0] / S;
    int D = in_sizes[4];
    int Q = in_sizes[2] / F;

    float *p_z, *p_cls, *p_proto, *p_znorm, *p_pnorm, *p_invcnt;
    int *p_ys, *p_cnt;
    cudaGetSymbolAddress((void**)&p_z, g_z);
    cudaGetSymbolAddress((void**)&p_cls, g_cls_sum);
    cudaGetSymbolAddress((void**)&p_proto, g_proto);
    cudaGetSymbolAddress((void**)&p_znorm, g_znorm);
    cudaGetSymbolAddress((void**)&p_pnorm, g_pnorm);
    cudaGetSymbolAddress((void**)&p_invcnt, g_invcnt);
    cudaGetSymbolAddress((void**)&p_ys, g_ys);
    cudaGetSymbolAddress((void**)&p_cnt, g_cnt);

    // 0. zero accumulators
    k_zero<<<(NWAY * F + 255) / 256, 256>>>(p_cls, NWAY * F);
    k_zero<<<(NWAY * D + 255) / 256, 256>>>(p_proto, NWAY * D);
    k_zero<<<(Q + 255) / 256, 256>>>(p_znorm, Q);

    // 1. labels + counts
    k_prep<<<1, 256>>>(ys, S, p_ys, p_invcnt, p_cnt);

    // 2. class sums in F-space (S split 8 ways)
    {
        dim3 grid(F / 128, 8);
        k_cls_sum<<<grid, 128>>>(xs, S, F, p_ys, p_cls);
    }

    // 3. prototypes: proto = (cls_sum * invcnt) @ W  (split-K, atomics)
    {
        int threads = D * (NWAY / 4) * PROTO_KS;
        k_proto<<<threads / 256, 256>>>(p_cls, W, p_invcnt, p_proto, F, D);
    }

    // 4. proto finalize: += bias (non-empty only), pnorm
    k_proto_fin<<<NWAY, 128>>>(p_proto, b, p_cnt, p_pnorm, D);

    // 5. big GEMM on tensor cores: z = xq @ W + b, fused znorm
    {
        dim3 grid(D / GBN, Q / GBM);
        gemm_tf32<<<grid, 256>>>(xq, W, b, p_z, p_znorm, Q, D, F);
    }

    // 6. fused cross-term + epilogue -> output
    {
        dim3 grid(1, Q / TBM);
        gemm_nt_epi<<<grid, 256>>>(p_z, p_proto, p_znorm, p_pnorm,
                                   (float*)d_out, Q, D);
    }
}

// round 7
// speedup vs baseline: 3.9351x; 1.1436x over previous
#include <cuda_runtime.h>
#include <cstdint>

// ---------------------------------------------------------------------------
// ProtoNet: out[q,c] = -||z_q - proto_c||^2
//   z_q   = xq @ W + b          (tf32 tensor cores, never materialized)
//   proto = (classsum(xs)/cnt) @ W + b
//   out   = 2*z.proto^T - ||z||^2 - ||proto||^2
// Fully fused: the big GEMM computes z tiles in registers, stages them to
// smem as tf32, and runs the z@proto^T cross-term on tensor cores in-kernel.
// Shapes: S=1024, Q=16384, F=2048, D=512, NWAY=64
// ---------------------------------------------------------------------------

#define NWAY 64
#define Q_MAX 16384
#define F_MAX 2048
#define NC 4              // D / 128 column chunks

__device__ float g_cls_sum[NWAY * F_MAX];                 // 512 KB
__device__ float g_proto[NWAY * 512];                     // 128 KB
__device__ float g_pnorm[NWAY];
__device__ int   g_ys[4096];
__device__ float g_invcnt[NWAY];
__device__ int   g_cnt[NWAY];
__device__ float g_crossp[(size_t)NC * Q_MAX * NWAY];     // 16 MB partial cross
__device__ float g_znp[NC * 4 * Q_MAX];                   // 1 MB partial norms

// ---------------------------------------------------------------------------
__global__ void k_zero2(float* a, int na, float* b, int nb) {
    int i = blockIdx.x * blockDim.x + threadIdx.x;
    if (i < na) a[i] = 0.0f;
    else { int j = i - na; if (j < nb) b[j] = 0.0f; }
}

// ---------------------------------------------------------------------------
// k_prep: detect int64-vs-int32 label layout, normalize labels, class counts.
// ---------------------------------------------------------------------------
__global__ void k_prep(const void* ys_raw, int S, int* ys_out, float* invcnt,
                       int* cnt_out) {
    __shared__ int s_is32;
    __shared__ int s_cnt[NWAY];
    int tid = threadIdx.x;
    if (tid == 0) s_is32 = 0;
    if (tid < NWAY) s_cnt[tid] = 0;
    __syncthreads();

    const int* w32 = (const int*)ys_raw;
    for (int j = 1 + 2 * tid; j < S; j += 2 * blockDim.x) {
        if (w32[j] != 0) s_is32 = 1;   // benign race
    }
    __syncthreads();
    int is64 = !s_is32;

    const long long* w64 = (const long long*)ys_raw;
    for (int i = tid; i < S; i += blockDim.x) {
        int c = is64 ? (int)w64[i] : w32[i];
        ys_out[i] = c;
        atomicAdd(&s_cnt[c], 1);
    }
    __syncthreads();
    if (tid < NWAY) {
        int c = s_cnt[tid];
        cnt_out[tid] = c;
        invcnt[tid] = 1.0f / (float)(c > 0 ? c : 1);
    }
}

// ---------------------------------------------------------------------------
// k_cls_sum: per-class SUM of xs in F-space, S split 8 ways, atomic combine.
// ---------------------------------------------------------------------------
__global__ void k_cls_sum(const float* __restrict__ xs, int S, int F,
                          const int* __restrict__ ys,
                          float* __restrict__ cls_sum) {
    __shared__ float acc[NWAY][128];
    __shared__ int s_ys[256];
    int tid = threadIdx.x;
    int f = blockIdx.x * 128 + tid;
    int chunk = S / gridDim.y;
    int s0 = blockIdx.y * chunk;

    #pragma unroll
    for (int c = 0; c < NWAY; c++) acc[c][tid] = 0.0f;
    for (int i = tid; i < chunk; i += blockDim.x) s_ys[i] = ys[s0 + i];
    __syncthreads();

    #pragma unroll 4
    for (int i = 0; i < chunk; i++) {
        acc[s_ys[i]][tid] += xs[(size_t)(s0 + i) * F + f];
    }
    __syncthreads();

    #pragma unroll
    for (int c = 0; c < NWAY; c++) {
        atomicAdd(&cls_sum[(size_t)c * F + f], acc[c][tid]);
    }
}

// ---------------------------------------------------------------------------
// k_proto: proto[m][d] += invcnt[m] * sum_k cls_sum[m][k] * W[k][d]
// split-K (8) + 4-way m reuse. proto pre-zeroed.
// ---------------------------------------------------------------------------
#define PROTO_KS 8
__global__ void k_proto(const float* __restrict__ cls_sum,
                        const float* __restrict__ W,
                        const float* __restrict__ invcnt,
                        float* __restrict__ proto, int F, int D) {
    int idx = blockIdx.x * blockDim.x + threadIdx.x;
    int d  = idx % D;
    int mg = (idx / D) % (NWAY / 4);
    int ks = idx / (D * (NWAY / 4));
    int kper = F / PROTO_KS;
    int k0 = ks * kper;

    const float* a = cls_sum + (size_t)(mg * 4) * F + k0;
    const float* w = W + (size_t)k0 * D + d;

    float s0 = 0.f, s1 = 0.f, s2 = 0.f, s3 = 0.f;
    #pragma unroll 4
    for (int k = 0; k < kper; k++) {
        float wv = w[(size_t)k * D];
        s0 = fmaf(a[k], wv, s0);
        s1 = fmaf(a[k + F], wv, s1);
        s2 = fmaf(a[k + 2 * F], wv, s2);
        s3 = fmaf(a[k + 3 * F], wv, s3);
    }
    int m = mg * 4;
    atomicAdd(&proto[(size_t)(m + 0) * D + d], s0 * invcnt[m + 0]);
    atomicAdd(&proto[(size_t)(m + 1) * D + d], s1 * invcnt[m + 1]);
    atomicAdd(&proto[(size_t)(m + 2) * D + d], s2 * invcnt[m + 2]);
    atomicAdd(&proto[(size_t)(m + 3) * D + d], s3 * invcnt[m + 3]);
}

// ---------------------------------------------------------------------------
// k_proto_fin: proto[c][d] += b[d] (non-empty classes only), pnorm[c]
// ---------------------------------------------------------------------------
__global__ void k_proto_fin(float* __restrict__ proto,
                            const float* __restrict__ bias,
                            const int* __restrict__ cnt,
                            float* __restrict__ pnorm, int D) {
    __shared__ float red[128];
    int c = blockIdx.x;
    int tid = threadIdx.x;
    bool nonempty = cnt[c] > 0;
    float s = 0.f;
    for (int d = tid; d < D; d += blockDim.x) {
        float v = proto[(size_t)c * D + d] + (nonempty ? bias[d] : 0.0f);
        proto[(size_t)c * D + d] = v;
        s = fmaf(v, v, s);
    }
    red[tid] = s;
    __syncthreads();
    for (int o = 64; o > 0; o >>= 1) {
        if (tid < o) red[tid] += red[tid + o];
        __syncthreads();
    }
    if (tid == 0) pnorm[c] = red[0];
}

// ---------------------------------------------------------------------------
// gemm_fused: for chunk cx (128 cols of D) and a 128-row tile of xq:
//   z = xq @ W[:,chunk] + b[chunk]      (tf32 mma, double-buffered)
//   znp[cx*4+wn][row]   = partial ||z||^2 over this warp's 32 cols
//   crossp[cx][row][c]  = z_chunk @ proto[:,chunk]^T   (tensor cores, smem z)
// grid (NC, Q/128), 256 threads. M%128==0, K%16==0, N=NC*128.
// ---------------------------------------------------------------------------
#define GBM 128
#define GBK 16
#define AS_STRIDE 20    // 16 + 4 pad
#define BS_STRIDE 136   // 128 + 8 pad
#define ZS_STRIDE 132   // 128 + 4 pad  (A-frag conflict-free)
#define PS_STRIDE 72    // 64 + 8 pad   (B-frag conflict-free)
// dynamic smem layout (floats):
//   As: [0, 5120)           2*128*20        (main loop only)
//   Bs: [5120, 9472)        2*16*136        (main loop only)
//   Zs: [0, 16896)          128*132         (epilogue only, overlaps As/Bs)
//   Ps: [16896, 26112)      128*72          (disjoint)
#define SMEM_FLOATS 26112

__device__ __forceinline__ float f2tf32(float x) {
    unsigned u;
    asm("cvt.rna.tf32.f32 %0, %1;" : "=r"(u) : "f"(x));
    return __uint_as_float(u);
}

__device__ __forceinline__ void mma8(float* d, const float* a, const float* b) {
    const unsigned* A = reinterpret_cast<const unsigned*>(a);
    const unsigned* B = reinterpret_cast<const unsigned*>(b);
    asm volatile(
        "mma.sync.aligned.m16n8k8.row.col.f32.tf32.tf32.f32 "
        "{%0,%1,%2,%3}, {%4,%5,%6,%7}, {%8,%9}, {%0,%1,%2,%3};\n"
        : "+f"(d[0]), "+f"(d[1]), "+f"(d[2]), "+f"(d[3])
        : "r"(A[0]), "r"(A[1]), "r"(A[2]), "r"(A[3]), "r"(B[0]), "r"(B[1]));
}

__global__ __launch_bounds__(256, 2) void gemm_fused(
    const float* __restrict__ A, const float* __restrict__ W,
    const float* __restrict__ bias, const float* __restrict__ proto,
    float* __restrict__ crossp, float* __restrict__ znp,
    int M, int N, int K)
{
    extern __shared__ float sm[];
    float* As = sm;            // double buffer
    float* Bs = sm + 5120;
    float* Zs = sm;            // reused after main loop
    float* Ps = sm + 16896;

    int tid  = threadIdx.x;
    int warp = tid >> 5, lane = tid & 31;
    int wm = warp & 1;        // 0..1  (64-row half)
    int wn = warp >> 1;       // 0..3  (32-col strip)
    int cx = blockIdx.x;      // column chunk
    int rowBase = blockIdx.y * GBM;
    int colBase = cx * 128;

    // global loaders
    int arow = tid >> 1;
    int acol = (tid & 1) * 8;
    const float* aptr = A + (size_t)(rowBase + arow) * K + acol;
    int brow = tid >> 4;
    int bcol = (tid & 15) * 8;
    const float* bptr = W + (size_t)brow * N + colBase + bcol;

    float acc[4][4][4];
    #pragma unroll
    for (int i = 0; i < 4; i++)
        #pragma unroll
        for (int j = 0; j < 4; j++)
            #pragma unroll
            for (int r = 0; r < 4; r++) acc[i][j][r] = 0.0f;

    int lg = lane >> 2;      // 0..7
    int lq = lane & 3;       // 0..3

    int aoff[4], boff[4];
    #pragma unroll
    for (int mt = 0; mt < 4; mt++)
        aoff[mt] = (wm * 64 + mt * 16 + lg) * AS_STRIDE + lq;
    #pragma unroll
    for (int nt = 0; nt < 4; nt++)
        boff[nt] = lq * BS_STRIDE + wn * 32 + nt * 8 + lg;

    // prologue chunk-0 loads
    float4 pa0 = *(const float4*)(aptr);
    float4 pa1 = *(const float4*)(aptr + 4);
    float4 pb0 = *(const float4*)(bptr);
    float4 pb1 = *(const float4*)(bptr + 4);

    // Load proto chunk into Ps (k-major, tf32) — disjoint smem, no sync needed
    {
        int c = tid >> 2;              // 0..63
        int part = (tid & 3) * 32;     // 0,32,64,96
        const float* pr = proto + (size_t)c * N + colBase + part;
        #pragma unroll
        for (int j = 0; j < 8; j++) {
            float4 v = *(const float4*)(pr + j * 4);
            int d = part + j * 4;
            Ps[(d + 0) * PS_STRIDE + c] = f2tf32(v.x);
            Ps[(d + 1) * PS_STRIDE + c] = f2tf32(v.y);
            Ps[(d + 2) * PS_STRIDE + c] = f2tf32(v.z);
            Ps[(d + 3) * PS_STRIDE + c] = f2tf32(v.w);
        }
    }

    int asmoff = arow * AS_STRIDE + acol;
    int bsmoff = brow * BS_STRIDE + bcol;
    {
        float4 t;
        t.x=f2tf32(pa0.x); t.y=f2tf32(pa0.y); t.z=f2tf32(pa0.z); t.w=f2tf32(pa0.w);
        *(float4*)&As[asmoff] = t;
        t.x=f2tf32(pa1.x); t.y=f2tf32(pa1.y); t.z=f2tf32(pa1.z); t.w=f2tf32(pa1.w);
        *(float4*)&As[asmoff + 4] = t;
        t.x=f2tf32(pb0.x); t.y=f2tf32(pb0.y); t.z=f2tf32(pb0.z); t.w=f2tf32(pb0.w);
        *(float4*)&Bs[bsmoff] = t;
        t.x=f2tf32(pb1.x); t.y=f2tf32(pb1.y); t.z=f2tf32(pb1.z); t.w=f2tf32(pb1.w);
        *(float4*)&Bs[bsmoff + 4] = t;
    }
    __syncthreads();

    int nIt = K / GBK;
    int buf = 0;
    const int ABUF = GBM * AS_STRIDE;   // 2560
    const int BBUF = GBK * BS_STRIDE;   // 2176
    for (int it = 0; it < nIt; ++it) {
        bool has = (it + 1) < nIt;
        if (has) {
            const float* ap = aptr + (it + 1) * GBK;
            const float* bp = bptr + (size_t)(it + 1) * GBK * N;
            pa0 = *(const float4*)(ap);
            pa1 = *(const float4*)(ap + 4);
            pb0 = *(const float4*)(bp);
            pb1 = *(const float4*)(bp + 4);
        }

        #pragma unroll
        for (int kk = 0; kk < GBK; kk += 8) {
            float af[4][4], bf[4][2];
            #pragma unroll
            for (int mt = 0; mt < 4; mt++) {
                const float* base = &As[buf * ABUF + aoff[mt] + kk];
                af[mt][0] = base[0];
                af[mt][1] = base[8 * AS_STRIDE];
                af[mt][2] = base[4];
                af[mt][3] = base[8 * AS_STRIDE + 4];
            }
            #pragma unroll
            for (int nt = 0; nt < 4; nt++) {
                const float* base = &Bs[buf * BBUF + boff[nt] + kk * BS_STRIDE];
                bf[nt][0] = base[0];
                bf[nt][1] = base[4 * BS_STRIDE];
            }
            #pragma unroll
            for (int mt = 0; mt < 4; mt++)
                #pragma unroll
                for (int nt = 0; nt < 4; nt++)
                    mma8(acc[mt][nt], af[mt], bf[nt]);
        }

        if (has) {
            int nb = buf ^ 1;
            float4 t;
            t.x=f2tf32(pa0.x); t.y=f2tf32(pa0.y); t.z=f2tf32(pa0.z); t.w=f2tf32(pa0.w);
            *(float4*)&As[nb * ABUF + asmoff] = t;
            t.x=f2tf32(pa1.x); t.y=f2tf32(pa1.y); t.z=f2tf32(pa1.z); t.w=f2tf32(pa1.w);
            *(float4*)&As[nb * ABUF + asmoff + 4] = t;
            t.x=f2tf32(pb0.x); t.y=f2tf32(pb0.y); t.z=f2tf32(pb0.z); t.w=f2tf32(pb0.w);
            *(float4*)&Bs[nb * BBUF + bsmoff] = t;
            t.x=f2tf32(pb1.x); t.y=f2tf32(pb1.y); t.z=f2tf32(pb1.z); t.w=f2tf32(pb1.w);
            *(float4*)&Bs[nb * BBUF + bsmoff + 4] = t;
            __syncthreads();
            buf = nb;
        }
    }

    // all As/Bs reads done before Zs overwrites them
    __syncthreads();

    // epilogue 1: bias add, znorm partials, stage z (tf32) into Zs
    #pragma unroll
    for (int mt = 0; mt < 4; mt++) {
        int rl = wm * 64 + mt * 16 + lg;           // local row
        float sum0 = 0.f, sum1 = 0.f;
        #pragma unroll
        for (int nt = 0; nt < 4; nt++) {
            int cl = wn * 32 + nt * 8 + lq * 2;    // local col in chunk
            float bv0 = bias[colBase + cl], bv1 = bias[colBase + cl + 1];
            float v0 = acc[mt][nt][0] + bv0;
            float v1 = acc[mt][nt][1] + bv1;
            float v2 = acc[mt][nt][2] + bv0;
            float v3 = acc[mt][nt][3] + bv1;
            *(float2*)&Zs[rl * ZS_STRIDE + cl] =
                make_float2(f2tf32(v0), f2tf32(v1));
            *(float2*)&Zs[(rl + 8) * ZS_STRIDE + cl] =
                make_float2(f2tf32(v2), f2tf32(v3));
            sum0 = fmaf(v0, v0, fmaf(v1, v1, sum0));
            sum1 = fmaf(v2, v2, fmaf(v3, v3, sum1));
        }
        sum0 += __shfl_xor_sync(0xFFFFFFFFu, sum0, 1);
        sum0 += __shfl_xor_sync(0xFFFFFFFFu, sum0, 2);
        sum1 += __shfl_xor_sync(0xFFFFFFFFu, sum1, 1);
        sum1 += __shfl_xor_sync(0xFFFFFFFFu, sum1, 2);
        if (lq == 0) {
            int slab = (cx * 4 + wn) * M;
            znp[slab + rowBase + rl]     = sum0;
            znp[slab + rowBase + rl + 8] = sum1;
        }
    }
    __syncthreads();

    // epilogue 2: cross partial = Zs[128x128] @ Ps^T -> [128 x 64]
    // warp w owns rows 16w..16w+15
    {
        float cacc[8][4];
        #pragma unroll
        for (int ct = 0; ct < 8; ct++)
            #pragma unroll
            for (int r = 0; r < 4; r++) cacc[ct][r] = 0.0f;

        int arow0 = (warp * 16 + lg) * ZS_STRIDE + lq;
        #pragma unroll 4
        for (int kk = 0; kk < 128; kk += 8) {
            float a[4];
            const float* ab = &Zs[arow0 + kk];
            a[0] = ab[0];
            a[1] = ab[8 * ZS_STRIDE];
            a[2] = ab[4];
            a[3] = ab[8 * ZS_STRIDE + 4];
            #pragma unroll
            for (int ct = 0; ct < 8; ct++) {
                float b[2];
                const float* bb = &Ps[(kk + lq) * PS_STRIDE + ct * 8 + lg];
                b[0] = bb[0];
                b[1] = bb[4 * PS_STRIDE];
                mma8(cacc[ct], a, b);
            }
        }

        size_t slab = (size_t)cx * M;
        int r0 = rowBase + warp * 16 + lg;
        #pragma unroll
        for (int ct = 0; ct < 8; ct++) {
            int col = ct * 8 + lq * 2;
            *(float2*)&crossp[(slab + r0) * NWAY + col] =
                make_float2(cacc[ct][0], cacc[ct][1]);
            *(float2*)&crossp[(slab + r0 + 8) * NWAY + col] =
                make_float2(cacc[ct][2], cacc[ct][3]);
        }
    }
}

// ---------------------------------------------------------------------------
// k_fin: out[q,c] = 2 * sum_cx crossp[cx][q][c] - sum znp[*][q] - pnorm[c]
// one thread per 4 outputs. grid = Q*16/256.
// ---------------------------------------------------------------------------
__global__ void k_fin(const float* __restrict__ crossp,
                      const float* __restrict__ znp,
                      const float* __restrict__ pnorm,
                      float* __restrict__ out, int Q) {
    int idx = blockIdx.x * blockDim.x + threadIdx.x;
    int q = idx >> 4;
    int c4 = (idx & 15) * 4;
    size_t base = (size_t)q * NWAY + c4;
    size_t slab = (size_t)Q * NWAY;

    float4 s0 = *(const float4*)&crossp[base];
    float4 s1 = *(const float4*)&crossp[base + slab];
    float4 s2 = *(const float4*)&crossp[base + 2 * slab];
    float4 s3 = *(const float4*)&crossp[base + 3 * slab];

    float zn = 0.f;
    #pragma unroll
    for (int j = 0; j < NC * 4; j++) zn += znp[j * Q + q];

    float4 pn = *(const float4*)&pnorm[c4];

    float4 o;
    o.x = 2.0f * (s0.x + s1.x + s2.x + s3.x) - zn - pn.x;
    o.y = 2.0f * (s0.y + s1.y + s2.y + s3.y) - zn - pn.y;
    o.z = 2.0f * (s0.z + s1.z + s2.z + s3.z) - zn - pn.z;
    o.w = 2.0f * (s0.w + s1.w + s2.w + s3.w) - zn - pn.w;
    *(float4*)&out[base] = o;
}

// ---------------------------------------------------------------------------
// Host launcher
// ---------------------------------------------------------------------------
extern "C" void kernel_launch(void* const* d_in, const int* in_sizes, int n_in,
                              void* d_out, int out_size) {
    const float* xs = (const float*)d_in[0];
    const void*  ys = d_in[1];
    const float* xq = (const float*)d_in[2];
    const float* W  = (const float*)d_in[3];
    const float* b  = (const float*)d_in[4];

    int S = in_sizes[1];
    int F = in_sizes[0] / S;
    int D = in_sizes[4];
    int Q = in_sizes[2] / F;

    float *p_cls, *p_proto, *p_pnorm, *p_invcnt, *p_crossp, *p_znp;
    int *p_ys, *p_cnt;
    cudaGetSymbolAddress((void**)&p_cls, g_cls_sum);
    cudaGetSymbolAddress((void**)&p_proto, g_proto);
    cudaGetSymbolAddress((void**)&p_pnorm, g_pnorm);
    cudaGetSymbolAddress((void**)&p_invcnt, g_invcnt);
    cudaGetSymbolAddress((void**)&p_ys, g_ys);
    cudaGetSymbolAddress((void**)&p_cnt, g_cnt);
    cudaGetSymbolAddress((void**)&p_crossp, g_crossp);
    cudaGetSymbolAddress((void**)&p_znp, g_znp);

    // 0. zero the two atomic accumulators (one launch)
    {
        int n = NWAY * F + NWAY * D;
        k_zero2<<<(n + 255) / 256, 256>>>(p_cls, NWAY * F, p_proto, NWAY * D);
    }

    // 1. labels + counts
    k_prep<<<1, 256>>>(ys, S, p_ys, p_invcnt, p_cnt);

    // 2. class sums in F-space (S split 8 ways)
    {
        dim3 grid(F / 128, 8);
        k_cls_sum<<<grid, 128>>>(xs, S, F, p_ys, p_cls);
    }

    // 3. prototypes: proto = (cls_sum * invcnt) @ W  (split-K, atomics)
    {
        int threads = D * (NWAY / 4) * PROTO_KS;
        k_proto<<<threads / 256, 256>>>(p_cls, W, p_invcnt, p_proto, F, D);
    }

    // 4. proto finalize: += bias (non-empty only), pnorm
    k_proto_fin<<<NWAY, 128>>>(p_proto, b, p_cnt, p_pnorm, D);

    // 5. fused GEMM: z-tiles + znorm partials + cross partials (launch idx 5)
    {
        cudaFuncSetAttribute(gemm_fused,
                             cudaFuncAttributeMaxDynamicSharedMemorySize,
                             SMEM_FLOATS * 4);
        dim3 grid(NC, Q / GBM);
        gemm_fused<<<grid, 256, SMEM_FLOATS * 4>>>(
            xq, W, b, p_proto, p_crossp, p_znp, Q, D, F);
    }

    // 6. combine partials -> output
    k_fin<<<Q * 16 / 256, 256>>>(p_crossp, p_znp, p_pnorm, (float*)d_out, Q);
}

// round 8
// speedup vs baseline: 4.4333x; 1.1266x over previous
#include <cuda_runtime.h>
#include <cstdint>

// ---------------------------------------------------------------------------
// ProtoNet: out[q,c] = -||z_q - proto_c||^2
//   z_q   = xq @ W + b          (tf32 tensor cores, never materialized)
//   proto = (classsum(xs)/cnt) @ W + b   (tf32 tensor cores, split-K)
//   out   = 2*z.proto^T - ||z||^2 - ||proto||^2
// Shapes: S=1024, Q=16384, F=2048, D=512, NWAY=64
// ---------------------------------------------------------------------------

#define NWAY 64
#define Q_MAX 16384
#define F_MAX 2048
#define NC 4              // D / 128 column chunks

__device__ float g_cls_sum[NWAY * F_MAX];                 // 512 KB
__device__ float g_proto[NWAY * 512];                     // 128 KB
__device__ float g_pnorm[NWAY];
__device__ int   g_ys[4096];
__device__ float g_invcnt[NWAY];
__device__ int   g_cnt[NWAY];
__device__ float g_crossp[(size_t)NC * Q_MAX * NWAY];     // 16 MB partial cross
__device__ float g_znp[NC * 4 * Q_MAX];                   // 1 MB partial norms

// ---------------------------------------------------------------------------
__global__ void k_zero2(float* a, int na, float* b, int nb) {
    int i = blockIdx.x * blockDim.x + threadIdx.x;
    if (i < na) a[i] = 0.0f;
    else { int j = i - na; if (j < nb) b[j] = 0.0f; }
}

// ---------------------------------------------------------------------------
// k_prep: detect int64-vs-int32 label layout, normalize labels, class counts.
// ---------------------------------------------------------------------------
__global__ void k_prep(const void* ys_raw, int S, int* ys_out, float* invcnt,
                       int* cnt_out) {
    __shared__ int s_is32;
    __shared__ int s_cnt[NWAY];
    int tid = threadIdx.x;
    if (tid == 0) s_is32 = 0;
    if (tid < NWAY) s_cnt[tid] = 0;
    __syncthreads();

    const int* w32 = (const int*)ys_raw;
    for (int j = 1 + 2 * tid; j < S; j += 2 * blockDim.x) {
        if (w32[j] != 0) s_is32 = 1;   // benign race
    }
    __syncthreads();
    int is64 = !s_is32;

    const long long* w64 = (const long long*)ys_raw;
    for (int i = tid; i < S; i += blockDim.x) {
        int c = is64 ? (int)w64[i] : w32[i];
        ys_out[i] = c;
        atomicAdd(&s_cnt[c], 1);
    }
    __syncthreads();
    if (tid < NWAY) {
        int c = s_cnt[tid];
        cnt_out[tid] = c;
        invcnt[tid] = 1.0f / (float)(c > 0 ? c : 1);
    }
}

// ---------------------------------------------------------------------------
// k_cls_sum: per-class SUM of xs in F-space, S split 8 ways, atomic combine.
// ---------------------------------------------------------------------------
__global__ void k_cls_sum(const float* __restrict__ xs, int S, int F,
                          const int* __restrict__ ys,
                          float* __restrict__ cls_sum) {
    __shared__ float acc[NWAY][128];
    __shared__ int s_ys[256];
    int tid = threadIdx.x;
    int f = blockIdx.x * 128 + tid;
    int chunk = S / gridDim.y;
    int s0 = blockIdx.y * chunk;

    #pragma unroll
    for (int c = 0; c < NWAY; c++) acc[c][tid] = 0.0f;
    for (int i = tid; i < chunk; i += blockDim.x) s_ys[i] = ys[s0 + i];
    __syncthreads();

    #pragma unroll 4
    for (int i = 0; i < chunk; i++) {
        acc[s_ys[i]][tid] += xs[(size_t)(s0 + i) * F + f];
    }
    __syncthreads();

    #pragma unroll
    for (int c = 0; c < NWAY; c++) {
        atomicAdd(&cls_sum[(size_t)c * F + f], acc[c][tid]);
    }
}

// ---------------------------------------------------------------------------
// tf32 helpers
// ---------------------------------------------------------------------------
__device__ __forceinline__ float f2tf32(float x) {
    unsigned u;
    asm("cvt.rna.tf32.f32 %0, %1;" : "=r"(u) : "f"(x));
    return __uint_as_float(u);
}

__device__ __forceinline__ void mma8(float* d, const float* a, const float* b) {
    const unsigned* A = reinterpret_cast<const unsigned*>(a);
    const unsigned* B = reinterpret_cast<const unsigned*>(b);
    asm volatile(
        "mma.sync.aligned.m16n8k8.row.col.f32.tf32.tf32.f32 "
        "{%0,%1,%2,%3}, {%4,%5,%6,%7}, {%8,%9}, {%0,%1,%2,%3};\n"
        : "+f"(d[0]), "+f"(d[1]), "+f"(d[2]), "+f"(d[3])
        : "r"(A[0]), "r"(A[1]), "r"(A[2]), "r"(A[3]), "r"(B[0]), "r"(B[1]));
}

// ---------------------------------------------------------------------------
// k_proto_tc: proto += ((invcnt*cls_sum) @ W) tile, tf32 tensor cores.
// grid (D/128, 16 split-K slices of 128 k each), 256 threads (8 warps:
// 2 row-halves x 4 col-strips). Whole A slice (64x128) and W slice (128x128)
// staged in dynamic smem. W is read exactly ONCE across the grid.
// proto pre-zeroed; atomicAdd combine across split-K.
// ---------------------------------------------------------------------------
#define PAS 132   // A smem stride (128 + 4)
#define PWS 136   // W smem stride (128 + 8)
#define PROTO_SMEM_FLOATS (64 * PAS + 128 * PWS)   // 8448 + 17408 = 25856

__global__ __launch_bounds__(256) void k_proto_tc(
    const float* __restrict__ cls_sum, const float* __restrict__ W,
    const float* __restrict__ invcnt, float* __restrict__ proto,
    int F, int D)
{
    extern __shared__ float sm[];
    float* As = sm;             // 64 x PAS
    float* Ws = sm + 64 * PAS;  // 128 x PWS

    int tid  = threadIdx.x;
    int warp = tid >> 5, lane = tid & 31;
    int wm = warp & 1;         // 0..1 (32-row half)
    int wn = warp >> 1;        // 0..3 (32-col strip)
    int colBase = blockIdx.x * 128;
    int k0 = blockIdx.y * 128;

    // load A slice: 64 rows x 128 k, scaled by invcnt[row], tf32
    {
        int row = tid >> 2;
        int kp  = (tid & 3) * 32;
        float ic = invcnt[row];
        const float* ap = cls_sum + (size_t)row * F + k0 + kp;
        #pragma unroll
        for (int j = 0; j < 8; j++) {
            float4 v = *(const float4*)(ap + j * 4);
            float4 t;
            t.x = f2tf32(v.x * ic); t.y = f2tf32(v.y * ic);
            t.z = f2tf32(v.z * ic); t.w = f2tf32(v.w * ic);
            *(float4*)&As[row * PAS + kp + j * 4] = t;
        }
    }
    // load W slice: 128 k x 128 cols, tf32
    {
        int kr = tid >> 1;
        int cp = (tid & 1) * 64;
        const float* wp = W + (size_t)(k0 + kr) * D + colBase + cp;
        #pragma unroll
        for (int j = 0; j < 16; j++) {
            float4 v = *(const float4*)(wp + j * 4);
            float4 t;
            t.x = f2tf32(v.x); t.y = f2tf32(v.y);
            t.z = f2tf32(v.z); t.w = f2tf32(v.w);
            *(float4*)&Ws[kr * PWS + cp + j * 4] = t;
        }
    }
    __syncthreads();

    int lg = lane >> 2;
    int lq = lane & 3;

    float acc[2][4][4];
    #pragma unroll
    for (int i = 0; i < 2; i++)
        #pragma unroll
        for (int j = 0; j < 4; j++)
            #pragma unroll
            for (int r = 0; r < 4; r++) acc[i][j][r] = 0.0f;

    int aoff[2], boff[4];
    #pragma unroll
    for (int mt = 0; mt < 2; mt++)
        aoff[mt] = (wm * 32 + mt * 16 + lg) * PAS + lq;
    #pragma unroll
    for (int nt = 0; nt < 4; nt++)
        boff[nt] = lq * PWS + wn * 32 + nt * 8 + lg;

    #pragma unroll 4
    for (int kk = 0; kk < 128; kk += 8) {
        float af[2][4], bf[4][2];
        #pragma unroll
        for (int mt = 0; mt < 2; mt++) {
            const float* base = &As[aoff[mt] + kk];
            af[mt][0] = base[0];
            af[mt][1] = base[8 * PAS];
            af[mt][2] = base[4];
            af[mt][3] = base[8 * PAS + 4];
        }
        #pragma unroll
        for (int nt = 0; nt < 4; nt++) {
            const float* base = &Ws[boff[nt] + kk * PWS];
            bf[nt][0] = base[0];
            bf[nt][1] = base[4 * PWS];
        }
        #pragma unroll
        for (int mt = 0; mt < 2; mt++)
            #pragma unroll
            for (int nt = 0; nt < 4; nt++)
                mma8(acc[mt][nt], af[mt], bf[nt]);
    }

    // atomic combine into proto
    #pragma unroll
    for (int mt = 0; mt < 2; mt++) {
        int r = wm * 32 + mt * 16 + lg;
        #pragma unroll
        for (int nt = 0; nt < 4; nt++) {
            int d = colBase + wn * 32 + nt * 8 + lq * 2;
            atomicAdd(&proto[(size_t)r * D + d],       acc[mt][nt][0]);
            atomicAdd(&proto[(size_t)r * D + d + 1],   acc[mt][nt][1]);
            atomicAdd(&proto[(size_t)(r + 8) * D + d],     acc[mt][nt][2]);
            atomicAdd(&proto[(size_t)(r + 8) * D + d + 1], acc[mt][nt][3]);
        }
    }
}

// ---------------------------------------------------------------------------
// k_proto_fin: proto[c][d] += b[d] (non-empty classes only), pnorm[c]
// ---------------------------------------------------------------------------
__global__ void k_proto_fin(float* __restrict__ proto,
                            const float* __restrict__ bias,
                            const int* __restrict__ cnt,
                            float* __restrict__ pnorm, int D) {
    __shared__ float red[128];
    int c = blockIdx.x;
    int tid = threadIdx.x;
    bool nonempty = cnt[c] > 0;
    float s = 0.f;
    for (int d = tid; d < D; d += blockDim.x) {
        float v = proto[(size_t)c * D + d] + (nonempty ? bias[d] : 0.0f);
        proto[(size_t)c * D + d] = v;
        s = fmaf(v, v, s);
    }
    red[tid] = s;
    __syncthreads();
    for (int o = 64; o > 0; o >>= 1) {
        if (tid < o) red[tid] += red[tid + o];
        __syncthreads();
    }
    if (tid == 0) pnorm[c] = red[0];
}

// ---------------------------------------------------------------------------
// gemm_fused: for chunk cx (128 cols of D) and a 128-row tile of xq:
//   z = xq @ W[:,chunk] + b[chunk]      (tf32 mma, double-buffered)
//   znp[cx*4+wn][row]   = partial ||z||^2 over this warp's 32 cols
//   crossp[cx][row][c]  = z_chunk @ proto[:,chunk]^T   (tensor cores, smem z)
// ---------------------------------------------------------------------------
#define GBM 128
#define GBK 16
#define AS_STRIDE 20    // 16 + 4 pad
#define BS_STRIDE 136   // 128 + 8 pad
#define ZS_STRIDE 132   // 128 + 4 pad
#define PS_STRIDE 72    // 64 + 8 pad
#define SMEM_FLOATS 26112

__global__ __launch_bounds__(256, 2) void gemm_fused(
    const float* __restrict__ A, const float* __restrict__ W,
    const float* __restrict__ bias, const float* __restrict__ proto,
    float* __restrict__ crossp, float* __restrict__ znp,
    int M, int N, int K)
{
    extern __shared__ float sm[];
    float* As = sm;            // double buffer
    float* Bs = sm + 5120;
    float* Zs = sm;            // reused after main loop
    float* Ps = sm + 16896;

    int tid  = threadIdx.x;
    int warp = tid >> 5, lane = tid & 31;
    int wm = warp & 1;
    int wn = warp >> 1;
    int cx = blockIdx.x;
    int rowBase = blockIdx.y * GBM;
    int colBase = cx * 128;

    int arow = tid >> 1;
    int acol = (tid & 1) * 8;
    const float* aptr = A + (size_t)(rowBase + arow) * K + acol;
    int brow = tid >> 4;
    int bcol = (tid & 15) * 8;
    const float* bptr = W + (size_t)brow * N + colBase + bcol;

    float acc[4][4][4];
    #pragma unroll
    for (int i = 0; i < 4; i++)
        #pragma unroll
        for (int j = 0; j < 4; j++)
            #pragma unroll
            for (int r = 0; r < 4; r++) acc[i][j][r] = 0.0f;

    int lg = lane >> 2;
    int lq = lane & 3;

    int aoff[4], boff[4];
    #pragma unroll
    for (int mt = 0; mt < 4; mt++)
        aoff[mt] = (wm * 64 + mt * 16 + lg) * AS_STRIDE + lq;
    #pragma unroll
    for (int nt = 0; nt < 4; nt++)
        boff[nt] = lq * BS_STRIDE + wn * 32 + nt * 8 + lg;

    float4 pa0 = *(const float4*)(aptr);
    float4 pa1 = *(const float4*)(aptr + 4);
    float4 pb0 = *(const float4*)(bptr);
    float4 pb1 = *(const float4*)(bptr + 4);

    // Load proto chunk into Ps (k-major, tf32) — disjoint smem
    {
        int c = tid >> 2;
        int part = (tid & 3) * 32;
        const float* pr = proto + (size_t)c * N + colBase + part;
        #pragma unroll
        for (int j = 0; j < 8; j++) {
            float4 v = *(const float4*)(pr + j * 4);
            int d = part + j * 4;
            Ps[(d + 0) * PS_STRIDE + c] = f2tf32(v.x);
            Ps[(d + 1) * PS_STRIDE + c] = f2tf32(v.y);
            Ps[(d + 2) * PS_STRIDE + c] = f2tf32(v.z);
            Ps[(d + 3) * PS_STRIDE + c] = f2tf32(v.w);
        }
    }

    int asmoff = arow * AS_STRIDE + acol;
    int bsmoff = brow * BS_STRIDE + bcol;
    {
        float4 t;
        t.x=f2tf32(pa0.x); t.y=f2tf32(pa0.y); t.z=f2tf32(pa0.z); t.w=f2tf32(pa0.w);
        *(float4*)&As[asmoff] = t;
        t.x=f2tf32(pa1.x); t.y=f2tf32(pa1.y); t.z=f2tf32(pa1.z); t.w=f2tf32(pa1.w);
        *(float4*)&As[asmoff + 4] = t;
        t.x=f2tf32(pb0.x); t.y=f2tf32(pb0.y); t.z=f2tf32(pb0.z); t.w=f2tf32(pb0.w);
        *(float4*)&Bs[bsmoff] = t;
        t.x=f2tf32(pb1.x); t.y=f2tf32(pb1.y); t.z=f2tf32(pb1.z); t.w=f2tf32(pb1.w);
        *(float4*)&Bs[bsmoff + 4] = t;
    }
    __syncthreads();

    int nIt = K / GBK;
    int buf = 0;
    const int ABUF = GBM * AS_STRIDE;
    const int BBUF = GBK * BS_STRIDE;
    for (int it = 0; it < nIt; ++it) {
        bool has = (it + 1) < nIt;
        if (has) {
            const float* ap = aptr + (it + 1) * GBK;
            const float* bp = bptr + (size_t)(it + 1) * GBK * N;
            pa0 = *(const float4*)(ap);
            pa1 = *(const float4*)(ap + 4);
            pb0 = *(const float4*)(bp);
            pb1 = *(const float4*)(bp + 4);
        }

        #pragma unroll
        for (int kk = 0; kk < GBK; kk += 8) {
            float af[4][4], bf[4][2];
            #pragma unroll
            for (int mt = 0; mt < 4; mt++) {
                const float* base = &As[buf * ABUF + aoff[mt] + kk];
                af[mt][0] = base[0];
                af[mt][1] = base[8 * AS_STRIDE];
                af[mt][2] = base[4];
                af[mt][3] = base[8 * AS_STRIDE + 4];
            }
            #pragma unroll
            for (int nt = 0; nt < 4; nt++) {
                const float* base = &Bs[buf * BBUF + boff[nt] + kk * BS_STRIDE];
                bf[nt][0] = base[0];
                bf[nt][1] = base[4 * BS_STRIDE];
            }
            #pragma unroll
            for (int mt = 0; mt < 4; mt++)
                #pragma unroll
                for (int nt = 0; nt < 4; nt++)
                    mma8(acc[mt][nt], af[mt], bf[nt]);
        }

        if (has) {
            int nb = buf ^ 1;
            float4 t;
            t.x=f2tf32(pa0.x); t.y=f2tf32(pa0.y); t.z=f2tf32(pa0.z); t.w=f2tf32(pa0.w);
            *(float4*)&As[nb * ABUF + asmoff] = t;
            t.x=f2tf32(pa1.x); t.y=f2tf32(pa1.y); t.z=f2tf32(pa1.z); t.w=f2tf32(pa1.w);
            *(float4*)&As[nb * ABUF + asmoff + 4] = t;
            t.x=f2tf32(pb0.x); t.y=f2tf32(pb0.y); t.z=f2tf32(pb0.z); t.w=f2tf32(pb0.w);
            *(float4*)&Bs[nb * BBUF + bsmoff] = t;
            t.x=f2tf32(pb1.x); t.y=f2tf32(pb1.y); t.z=f2tf32(pb1.z); t.w=f2tf32(pb1.w);
            *(float4*)&Bs[nb * BBUF + bsmoff + 4] = t;
            __syncthreads();
            buf = nb;
        }
    }

    __syncthreads();

    // epilogue 1: bias add, znorm partials, stage z (tf32) into Zs
    #pragma unroll
    for (int mt = 0; mt < 4; mt++) {
        int rl = wm * 64 + mt * 16 + lg;
        float sum0 = 0.f, sum1 = 0.f;
        #pragma unroll
        for (int nt = 0; nt < 4; nt++) {
            int cl = wn * 32 + nt * 8 + lq * 2;
            float bv0 = bias[colBase + cl], bv1 = bias[colBase + cl + 1];
            float v0 = acc[mt][nt][0] + bv0;
            float v1 = acc[mt][nt][1] + bv1;
            float v2 = acc[mt][nt][2] + bv0;
            float v3 = acc[mt][nt][3] + bv1;
            *(float2*)&Zs[rl * ZS_STRIDE + cl] =
                make_float2(f2tf32(v0), f2tf32(v1));
            *(float2*)&Zs[(rl + 8) * ZS_STRIDE + cl] =
                make_float2(f2tf32(v2), f2tf32(v3));
            sum0 = fmaf(v0, v0, fmaf(v1, v1, sum0));
            sum1 = fmaf(v2, v2, fmaf(v3, v3, sum1));
        }
        sum0 += __shfl_xor_sync(0xFFFFFFFFu, sum0, 1);
        sum0 += __shfl_xor_sync(0xFFFFFFFFu, sum0, 2);
        sum1 += __shfl_xor_sync(0xFFFFFFFFu, sum1, 1);
        sum1 += __shfl_xor_sync(0xFFFFFFFFu, sum1, 2);
        if (lq == 0) {
            int slab = (cx * 4 + wn) * M;
            znp[slab + rowBase + rl]     = sum0;
            znp[slab + rowBase + rl + 8] = sum1;
        }
    }
    __syncthreads();

    // epilogue 2: cross partial = Zs[128x128] @ Ps^T -> [128 x 64]
    {
        float cacc[8][4];
        #pragma unroll
        for (int ct = 0; ct < 8; ct++)
            #pragma unroll
            for (int r = 0; r < 4; r++) cacc[ct][r] = 0.0f;

        int arow0 = (warp * 16 + lg) * ZS_STRIDE + lq;
        #pragma unroll 4
        for (int kk = 0; kk < 128; kk += 8) {
            float a[4];
            const float* ab = &Zs[arow0 + kk];
            a[0] = ab[0];
            a[1] = ab[8 * ZS_STRIDE];
            a[2] = ab[4];
            a[3] = ab[8 * ZS_STRIDE + 4];
            #pragma unroll
            for (int ct = 0; ct < 8; ct++) {
                float b[2];
                const float* bb = &Ps[(kk + lq) * PS_STRIDE + ct * 8 + lg];
                b[0] = bb[0];
                b[1] = bb[4 * PS_STRIDE];
                mma8(cacc[ct], a, b);
            }
        }

        size_t slab = (size_t)cx * M;
        int r0 = rowBase + warp * 16 + lg;
        #pragma unroll
        for (int ct = 0; ct < 8; ct++) {
            int col = ct * 8 + lq * 2;
            *(float2*)&crossp[(slab + r0) * NWAY + col] =
                make_float2(cacc[ct][0], cacc[ct][1]);
            *(float2*)&crossp[(slab + r0 + 8) * NWAY + col] =
                make_float2(cacc[ct][2], cacc[ct][3]);
        }
    }
}

// ---------------------------------------------------------------------------
// k_fin: out[q,c] = 2 * sum_cx crossp[cx][q][c] - sum znp[*][q] - pnorm[c]
// ---------------------------------------------------------------------------
__global__ void k_fin(const float* __restrict__ crossp,
                      const float* __restrict__ znp,
                      const float* __restrict__ pnorm,
                      float* __restrict__ out, int Q) {
    int idx = blockIdx.x * blockDim.x + threadIdx.x;
    int q = idx >> 4;
    int c4 = (idx & 15) * 4;
    size_t base = (size_t)q * NWAY + c4;
    size_t slab = (size_t)Q * NWAY;

    float4 s0 = *(const float4*)&crossp[base];
    float4 s1 = *(const float4*)&crossp[base + slab];
    float4 s2 = *(const float4*)&crossp[base + 2 * slab];
    float4 s3 = *(const float4*)&crossp[base + 3 * slab];

    float zn = 0.f;
    #pragma unroll
    for (int j = 0; j < NC * 4; j++) zn += znp[j * Q + q];

    float4 pn = *(const float4*)&pnorm[c4];

    float4 o;
    o.x = 2.0f * (s0.x + s1.x + s2.x + s3.x) - zn - pn.x;
    o.y = 2.0f * (s0.y + s1.y + s2.y + s3.y) - zn - pn.y;
    o.z = 2.0f * (s0.z + s1.z + s2.z + s3.z) - zn - pn.z;
    o.w = 2.0f * (s0.w + s1.w + s2.w + s3.w) - zn - pn.w;
    *(float4*)&out[base] = o;
}

// ---------------------------------------------------------------------------
// Host launcher
// ---------------------------------------------------------------------------
extern "C" void kernel_launch(void* const* d_in, const int* in_sizes, int n_in,
                              void* d_out, int out_size) {
    const float* xs = (const float*)d_in[0];
    const void*  ys = d_in[1];
    const float* xq = (const float*)d_in[2];
    const float* W  = (const float*)d_in[3];
    const float* b  = (const float*)d_in[4];

    int S = in_sizes[1];
    int F = in_sizes[0] / S;
    int D = in_sizes[4];
    int Q = in_sizes[2] / F;

    float *p_cls, *p_proto, *p_pnorm, *p_invcnt, *p_crossp, *p_znp;
    int *p_ys, *p_cnt;
    cudaGetSymbolAddress((void**)&p_cls, g_cls_sum);
    cudaGetSymbolAddress((void**)&p_proto, g_proto);
    cudaGetSymbolAddress((void**)&p_pnorm, g_pnorm);
    cudaGetSymbolAddress((void**)&p_invcnt, g_invcnt);
    cudaGetSymbolAddress((void**)&p_ys, g_ys);
    cudaGetSymbolAddress((void**)&p_cnt, g_cnt);
    cudaGetSymbolAddress((void**)&p_crossp, g_crossp);
    cudaGetSymbolAddress((void**)&p_znp, g_znp);

    // 0. zero the two atomic accumulators (one launch)
    {
        int n = NWAY * F + NWAY * D;
        k_zero2<<<(n + 255) / 256, 256>>>(p_cls, NWAY * F, p_proto, NWAY * D);
    }

    // 1. labels + counts
    k_prep<<<1, 256>>>(ys, S, p_ys, p_invcnt, p_cnt);

    // 2. class sums in F-space (S split 8 ways)
    {
        dim3 grid(F / 128, 8);
        k_cls_sum<<<grid, 128>>>(xs, S, F, p_ys, p_cls);
    }

    // 3. prototypes on tensor cores: proto = (invcnt*cls_sum) @ W
    {
        cudaFuncSetAttribute(k_proto_tc,
                             cudaFuncAttributeMaxDynamicSharedMemorySize,
                             PROTO_SMEM_FLOATS * 4);
        dim3 grid(D / 128, F / 128);   // 4 x 16
        k_proto_tc<<<grid, 256, PROTO_SMEM_FLOATS * 4>>>(
            p_cls, W, p_invcnt, p_proto, F, D);
    }

    // 4. proto finalize: += bias (non-empty only), pnorm
    k_proto_fin<<<NWAY, 128>>>(p_proto, b, p_cnt, p_pnorm, D);

    // 5. fused GEMM: z-tiles + znorm partials + cross partials
    {
        cudaFuncSetAttribute(gemm_fused,
                             cudaFuncAttributeMaxDynamicSharedMemorySize,
                             SMEM_FLOATS * 4);
        dim3 grid(NC, Q / GBM);
        gemm_fused<<<grid, 256, SMEM_FLOATS * 4>>>(
            xq, W, b, p_proto, p_crossp, p_znp, Q, D, F);
    }

    // 6. combine partials -> output
    k_fin<<<Q * 16 / 256, 256>>>(p_crossp, p_znp, p_pnorm, (float*)d_out, Q);
}

// round 10
// speedup vs baseline: 6.2396x; 1.4075x over previous
#include <cuda_runtime.h>
#include <cuda_fp16.h>
#include <cstdint>

// ---------------------------------------------------------------------------
// ProtoNet: out[q,c] = -||z_q - proto_c||^2
//   z_q   = xq @ W + b          (fp16 mma.sync m16n8k16, fp32 accum,
//                                never materialized to gmem)
//   proto = (classsum(xs)/cnt) @ W + b   (tf32 mma.sync, split-K)
//   out   = 2*z.proto^T - ||z||^2 - ||proto||^2
// Shapes: S=1024, Q=16384, F=2048, D=512, NWAY=64
// ---------------------------------------------------------------------------

#define NWAY 64
#define Q_MAX 16384
#define F_MAX 2048
#define NC 4              // D / 128 column chunks

__device__ float g_cls_sum[NWAY * F_MAX];                 // 512 KB
__device__ float g_proto[NWAY * 512];                     // 128 KB
__device__ float g_pnorm[NWAY];
__device__ int   g_ys[4096];
__device__ float g_invcnt[NWAY];
__device__ int   g_cnt[NWAY];
__device__ float g_crossp[(size_t)NC * Q_MAX * NWAY];     // 16 MB partial cross
__device__ float g_znp[NC * 4 * Q_MAX];                   // 1 MB partial norms

// ---------------------------------------------------------------------------
// helpers
// ---------------------------------------------------------------------------
__device__ __forceinline__ float f2tf32(float x) {
    unsigned u;
    asm("cvt.rna.tf32.f32 %0, %1;" : "=r"(u) : "f"(x));
    return __uint_as_float(u);
}

// tf32 m16n8k8 (proto kernel)
__device__ __forceinline__ void mma8(float* d, const float* a, const float* b) {
    const unsigned* A = reinterpret_cast<const unsigned*>(a);
    const unsigned* B = reinterpret_cast<const unsigned*>(b);
    asm volatile(
        "mma.sync.aligned.m16n8k8.row.col.f32.tf32.tf32.f32 "
        "{%0,%1,%2,%3}, {%4,%5,%6,%7}, {%8,%9}, {%0,%1,%2,%3};\n"
        : "+f"(d[0]), "+f"(d[1]), "+f"(d[2]), "+f"(d[3])
        : "r"(A[0]), "r"(A[1]), "r"(A[2]), "r"(A[3]), "r"(B[0]), "r"(B[1]));
}

// fp16 m16n8k16, fp32 accum (main kernel)
__device__ __forceinline__ void mma16(float* d, const uint32_t* a,
                                      const uint32_t* b) {
    asm volatile(
        "mma.sync.aligned.m16n8k16.row.col.f32.f16.f16.f32 "
        "{%0,%1,%2,%3}, {%4,%5,%6,%7}, {%8,%9}, {%0,%1,%2,%3};\n"
        : "+f"(d[0]), "+f"(d[1]), "+f"(d[2]), "+f"(d[3])
        : "r"(a[0]), "r"(a[1]), "r"(a[2]), "r"(a[3]), "r"(b[0]), "r"(b[1]));
}

#define LDSM_X4(r, addr)                                                      \
    asm volatile("ldmatrix.sync.aligned.m8n8.x4.shared.b16 {%0,%1,%2,%3}, [%4];" \
                 : "=r"((r)[0]), "=r"((r)[1]), "=r"((r)[2]), "=r"((r)[3])     \
                 : "r"(addr))

#define LDSM_X2T(r, addr)                                                     \
    asm volatile("ldmatrix.sync.aligned.m8n8.x2.trans.shared.b16 {%0,%1}, [%2];" \
                 : "=r"((r)[0]), "=r"((r)[1]) : "r"(addr))

__device__ __forceinline__ uint32_t smem_u32(const void* p) {
    uint32_t a;
    asm("{ .reg .u64 t; cvta.to.shared.u64 t, %1; cvt.u32.u64 %0, t; }"
        : "=r"(a) : "l"(p));
    return a;
}

// 8 floats -> 4 half2
__device__ __forceinline__ void cvt8(const float* g, __half2* h) {
    float4 v0 = *(const float4*)g;
    float4 v1 = *(const float4*)(g + 4);
    h[0] = __floats2half2_rn(v0.x, v0.y);
    h[1] = __floats2half2_rn(v0.z, v0.w);
    h[2] = __floats2half2_rn(v1.x, v1.y);
    h[3] = __floats2half2_rn(v1.z, v1.w);
}

// ---------------------------------------------------------------------------
__global__ void k_zero2(float* a, int na, float* b, int nb) {
    int i = blockIdx.x * blockDim.x + threadIdx.x;
    if (i < na) a[i] = 0.0f;
    else { int j = i - na; if (j < nb) b[j] = 0.0f; }
}

// ---------------------------------------------------------------------------
// k_prep: detect int64-vs-int32 label layout, normalize labels, class counts.
// ---------------------------------------------------------------------------
__global__ void k_prep(const void* ys_raw, int S, int* ys_out, float* invcnt,
                       int* cnt_out) {
    __shared__ int s_is32;
    __shared__ int s_cnt[NWAY];
    int tid = threadIdx.x;
    if (tid == 0) s_is32 = 0;
    if (tid < NWAY) s_cnt[tid] = 0;
    __syncthreads();

    const int* w32 = (const int*)ys_raw;
    for (int j = 1 + 2 * tid; j < S; j += 2 * blockDim.x) {
        if (w32[j] != 0) s_is32 = 1;   // benign race
    }
    __syncthreads();
    int is64 = !s_is32;

    const long long* w64 = (const long long*)ys_raw;
    for (int i = tid; i < S; i += blockDim.x) {
        int c = is64 ? (int)w64[i] : w32[i];
        ys_out[i] = c;
        atomicAdd(&s_cnt[c], 1);
    }
    __syncthreads();
    if (tid < NWAY) {
        int c = s_cnt[tid];
        cnt_out[tid] = c;
        invcnt[tid] = 1.0f / (float)(c > 0 ? c : 1);
    }
}

// ---------------------------------------------------------------------------
// k_cls_sum: per-class SUM of xs in F-space, S split 8 ways, atomic combine.
// ---------------------------------------------------------------------------
__global__ void k_cls_sum(const float* __restrict__ xs, int S, int F,
                          const int* __restrict__ ys,
                          float* __restrict__ cls_sum) {
    __shared__ float acc[NWAY][128];
    __shared__ int s_ys[256];
    int tid = threadIdx.x;
    int f = blockIdx.x * 128 + tid;
    int chunk = S / gridDim.y;
    int s0 = blockIdx.y * chunk;

    #pragma unroll
    for (int c = 0; c < NWAY; c++) acc[c][tid] = 0.0f;
    for (int i = tid; i < chunk; i += blockDim.x) s_ys[i] = ys[s0 + i];
    __syncthreads();

    #pragma unroll 4
    for (int i = 0; i < chunk; i++) {
        acc[s_ys[i]][tid] += xs[(size_t)(s0 + i) * F + f];
    }
    __syncthreads();

    #pragma unroll
    for (int c = 0; c < NWAY; c++) {
        atomicAdd(&cls_sum[(size_t)c * F + f], acc[c][tid]);
    }
}

// ---------------------------------------------------------------------------
// k_proto_tc: proto += ((invcnt*cls_sum) @ W) tile, tf32 mma.sync, split-K.
// ---------------------------------------------------------------------------
#define PAS 132
#define PWS 136
#define PROTO_SMEM_FLOATS (64 * PAS + 128 * PWS)

__global__ __launch_bounds__(256) void k_proto_tc(
    const float* __restrict__ cls_sum, const float* __restrict__ W,
    const float* __restrict__ invcnt, float* __restrict__ proto,
    int F, int D)
{
    extern __shared__ float sm[];
    float* As = sm;
    float* Ws = sm + 64 * PAS;

    int tid  = threadIdx.x;
    int warp = tid >> 5, lane = tid & 31;
    int wm = warp & 1;
    int wn = warp >> 1;
    int colBase = blockIdx.x * 128;
    int k0 = blockIdx.y * 128;

    {
        int row = tid >> 2;
        int kp  = (tid & 3) * 32;
        float ic = invcnt[row];
        const float* ap = cls_sum + (size_t)row * F + k0 + kp;
        #pragma unroll
        for (int j = 0; j < 8; j++) {
            float4 v = *(const float4*)(ap + j * 4);
            float4 t;
            t.x = f2tf32(v.x * ic); t.y = f2tf32(v.y * ic);
            t.z = f2tf32(v.z * ic); t.w = f2tf32(v.w * ic);
            *(float4*)&As[row * PAS + kp + j * 4] = t;
        }
    }
    {
        int kr = tid >> 1;
        int cp = (tid & 1) * 64;
        const float* wp = W + (size_t)(k0 + kr) * D + colBase + cp;
        #pragma unroll
        for (int j = 0; j < 16; j++) {
            float4 v = *(const float4*)(wp + j * 4);
            float4 t;
            t.x = f2tf32(v.x); t.y = f2tf32(v.y);
            t.z = f2tf32(v.z); t.w = f2tf32(v.w);
            *(float4*)&Ws[kr * PWS + cp + j * 4] = t;
        }
    }
    __syncthreads();

    int lg = lane >> 2;
    int lq = lane & 3;

    float acc[2][4][4];
    #pragma unroll
    for (int i = 0; i < 2; i++)
        #pragma unroll
        for (int j = 0; j < 4; j++)
            #pragma unroll
            for (int r = 0; r < 4; r++) acc[i][j][r] = 0.0f;

    int aoff[2], boff[4];
    #pragma unroll
    for (int mt = 0; mt < 2; mt++)
        aoff[mt] = (wm * 32 + mt * 16 + lg) * PAS + lq;
    #pragma unroll
    for (int nt = 0; nt < 4; nt++)
        boff[nt] = lq * PWS + wn * 32 + nt * 8 + lg;

    #pragma unroll 4
    for (int kk = 0; kk < 128; kk += 8) {
        float af[2][4], bf[4][2];
        #pragma unroll
        for (int mt = 0; mt < 2; mt++) {
            const float* base = &As[aoff[mt] + kk];
            af[mt][0] = base[0];
            af[mt][1] = base[8 * PAS];
            af[mt][2] = base[4];
            af[mt][3] = base[8 * PAS + 4];
        }
        #pragma unroll
        for (int nt = 0; nt < 4; nt++) {
            const float* base = &Ws[boff[nt] + kk * PWS];
            bf[nt][0] = base[0];
            bf[nt][1] = base[4 * PWS];
        }
        #pragma unroll
        for (int mt = 0; mt < 2; mt++)
            #pragma unroll
            for (int nt = 0; nt < 4; nt++)
                mma8(acc[mt][nt], af[mt], bf[nt]);
    }

    #pragma unroll
    for (int mt = 0; mt < 2; mt++) {
        int r = wm * 32 + mt * 16 + lg;
        #pragma unroll
        for (int nt = 0; nt < 4; nt++) {
            int d = colBase + wn * 32 + nt * 8 + lq * 2;
            atomicAdd(&proto[(size_t)r * D + d],       acc[mt][nt][0]);
            atomicAdd(&proto[(size_t)r * D + d + 1],   acc[mt][nt][1]);
            atomicAdd(&proto[(size_t)(r + 8) * D + d],     acc[mt][nt][2]);
            atomicAdd(&proto[(size_t)(r + 8) * D + d + 1], acc[mt][nt][3]);
        }
    }
}

// ---------------------------------------------------------------------------
// k_proto_fin: proto[c][d] += b[d] (non-empty classes only), pnorm[c]
// ---------------------------------------------------------------------------
__global__ void k_proto_fin(float* __restrict__ proto,
                            const float* __restrict__ bias,
                            const int* __restrict__ cnt,
                            float* __restrict__ pnorm, int D) {
    __shared__ float red[128];
    int c = blockIdx.x;
    int tid = threadIdx.x;
    bool nonempty = cnt[c] > 0;
    float s = 0.f;
    for (int d = tid; d < D; d += blockDim.x) {
        float v = proto[(size_t)c * D + d] + (nonempty ? bias[d] : 0.0f);
        proto[(size_t)c * D + d] = v;
        s = fmaf(v, v, s);
    }
    red[tid] = s;
    __syncthreads();
    for (int o = 64; o > 0; o >>= 1) {
        if (tid < o) red[tid] += red[tid + o];
        __syncthreads();
    }
    if (tid == 0) pnorm[c] = red[0];
}

// ---------------------------------------------------------------------------
// gemm_fused (fp16): for chunk cx (128 cols of D) and a 128-row tile of xq:
//   z = xq @ W[:,chunk] + b[chunk]   (fp16 m16n8k16, fp32 accum, dbl-buffered)
//   znp[cx*4+wn][row]   = partial ||z||^2 over this warp's 32 cols
//   crossp[cx][row][c]  = z_chunk @ proto[:,chunk]^T  (fp16 mma, smem z)
// SMEM (bytes): As[2] 2x6144, Bs[2] at 12288 2x4352  (main loop, 20992 total)
//               Zs [0,34816) 128x136 half  (epilogue, overlaps As/Bs)
//               Ps [34816,53248) 128x72 half
// ---------------------------------------------------------------------------
#define AS2 24      // halfs per A smem row (16 + 8 pad)
#define BS2 136     // halfs per B smem k-row (128 + 8 pad)
#define ZS2 136
#define PS2 72
#define AS_BYTES (128 * AS2 * 2)    // 6144
#define BS_BYTES (16 * BS2 * 2)     // 4352
#define OFF_BS   (2 * AS_BYTES)     // 12288
#define OFF_PS   34816
#define GEMM_SMEM (OFF_PS + 128 * PS2 * 2)   // 53248

__global__ __launch_bounds__(256, 2) void gemm_fused(
    const float* __restrict__ A, const float* __restrict__ W,
    const float* __restrict__ bias, const float* __restrict__ proto,
    float* __restrict__ crossp, float* __restrict__ znp,
    int M, int N, int K)
{
    extern __shared__ __align__(16) char smraw[];
    const uint32_t sbase = smem_u32(smraw);

    int tid  = threadIdx.x;
    int warp = tid >> 5, lane = tid & 31;
    int wm = warp & 1;        // 0..1  (64-row half)
    int wn = warp >> 1;       // 0..3  (32-col strip)
    int cx = blockIdx.x;
    int rowBase = blockIdx.y * 128;
    int colBase = cx * 128;

    // global loaders: A 128x16 fp32 -> fp16, B (W) 16x128 fp32 -> fp16
    int arow = tid >> 1, akoff = (tid & 1) * 8;
    const float* aptr = A + (size_t)(rowBase + arow) * K + akoff;
    int bkrow = tid >> 4, bnoff = (tid & 15) * 8;
    const float* bptr = W + (size_t)bkrow * N + colBase + bnoff;

    uint32_t aStoreOff = (uint32_t)(arow * AS2 + akoff) * 2;   // bytes
    uint32_t bStoreOff = (uint32_t)(bkrow * BS2 + bnoff) * 2;

    float acc[4][4][4];
    #pragma unroll
    for (int i = 0; i < 4; i++)
        #pragma unroll
        for (int j = 0; j < 4; j++)
            #pragma unroll
            for (int r = 0; r < 4; r++) acc[i][j][r] = 0.0f;

    // ldmatrix per-lane byte offsets
    int r16 = lane & 15, khalf = (lane >> 4) * 8;
    uint32_t aFragOff[4], bFragOff[4];
    #pragma unroll
    for (int mt = 0; mt < 4; mt++)
        aFragOff[mt] = (uint32_t)((wm * 64 + mt * 16 + r16) * AS2 + khalf) * 2;
    #pragma unroll
    for (int nt = 0; nt < 4; nt++)
        bFragOff[nt] = (uint32_t)(r16 * BS2 + wn * 32 + nt * 8) * 2;

    // prologue: chunk 0
    __half2 pa[4], pb[4];
    cvt8(aptr, pa);
    cvt8(bptr, pb);
    *(uint4*)(smraw + aStoreOff) = *(uint4*)pa;
    *(uint4*)(smraw + OFF_BS + bStoreOff) = *(uint4*)pb;
    __syncthreads();

    const int nIt = K / 16;   // 128
    int buf = 0;
    for (int it = 0; it < nIt; ++it) {
        bool has = (it + 1) < nIt;
        if (has) {
            cvt8(aptr + (it + 1) * 16, pa);
            cvt8(bptr + (size_t)(it + 1) * 16 * N, pb);
        }

        uint32_t aB = sbase + buf * AS_BYTES;
        uint32_t bB = sbase + OFF_BS + buf * BS_BYTES;
        uint32_t af[4][4], bf[4][2];
        #pragma unroll
        for (int mt = 0; mt < 4; mt++) LDSM_X4(af[mt], aB + aFragOff[mt]);
        #pragma unroll
        for (int nt = 0; nt < 4; nt++) LDSM_X2T(bf[nt], bB + bFragOff[nt]);
        #pragma unroll
        for (int mt = 0; mt < 4; mt++)
            #pragma unroll
            for (int nt = 0; nt < 4; nt++)
                mma16(acc[mt][nt], af[mt], bf[nt]);

        if (has) {
            int nb = buf ^ 1;
            *(uint4*)(smraw + nb * AS_BYTES + aStoreOff) = *(uint4*)pa;
            *(uint4*)(smraw + OFF_BS + nb * BS_BYTES + bStoreOff) = *(uint4*)pb;
            __syncthreads();
            buf = nb;
        }
    }
    __syncthreads();   // all mma smem reads done before Zs overwrites

    __half* Zs = (__half*)smraw;
    __half* Ps = (__half*)(smraw + OFF_PS);

    // fill Ps: proto[c][colBase..+128] -> Ps[d][c] fp16 (disjoint region)
    {
        int cc = tid >> 2;
        int dpart = (tid & 3) * 32;
        const float* pr = proto + (size_t)cc * N + colBase + dpart;
        #pragma unroll
        for (int j = 0; j < 8; j++) {
            float4 v = *(const float4*)(pr + j * 4);
            int d = dpart + j * 4;
            Ps[(d + 0) * PS2 + cc] = __float2half_rn(v.x);
            Ps[(d + 1) * PS2 + cc] = __float2half_rn(v.y);
            Ps[(d + 2) * PS2 + cc] = __float2half_rn(v.z);
            Ps[(d + 3) * PS2 + cc] = __float2half_rn(v.w);
        }
    }

    int lg = lane >> 2, lq = lane & 3;

    // epilogue 1: bias add, znorm partials, stage z (fp16) into Zs
    #pragma unroll
    for (int mt = 0; mt < 4; mt++) {
        int rl = wm * 64 + mt * 16 + lg;
        float sum0 = 0.f, sum1 = 0.f;
        #pragma unroll
        for (int nt = 0; nt < 4; nt++) {
            int cl = wn * 32 + nt * 8 + lq * 2;
            float bv0 = bias[colBase + cl], bv1 = bias[colBase + cl + 1];
            float v0 = acc[mt][nt][0] + bv0;
            float v1 = acc[mt][nt][1] + bv1;
            float v2 = acc[mt][nt][2] + bv0;
            float v3 = acc[mt][nt][3] + bv1;
            *(__half2*)&Zs[rl * ZS2 + cl]       = __floats2half2_rn(v0, v1);
            *(__half2*)&Zs[(rl + 8) * ZS2 + cl] = __floats2half2_rn(v2, v3);
            sum0 = fmaf(v0, v0, fmaf(v1, v1, sum0));
            sum1 = fmaf(v2, v2, fmaf(v3, v3, sum1));
        }
        sum0 += __shfl_xor_sync(0xFFFFFFFFu, sum0, 1);
        sum0 += __shfl_xor_sync(0xFFFFFFFFu, sum0, 2);
        sum1 += __shfl_xor_sync(0xFFFFFFFFu, sum1, 1);
        sum1 += __shfl_xor_sync(0xFFFFFFFFu, sum1, 2);
        if (lq == 0) {
            int slab = (cx * 4 + wn) * M;
            znp[slab + rowBase + rl]     = sum0;
            znp[slab + rowBase + rl + 8] = sum1;
        }
    }
    __syncthreads();

    // epilogue 2: cross partial = Zs[128x128] @ Ps^T -> [128 x 64] (fp16 mma)
    {
        float cacc[8][4];
        #pragma unroll
        for (int ct = 0; ct < 8; ct++)
            #pragma unroll
            for (int r = 0; r < 4; r++) cacc[ct][r] = 0.0f;

        uint32_t zlm = sbase +
            (uint32_t)((warp * 16 + r16) * ZS2 + khalf) * 2;
        uint32_t psBase = sbase + OFF_PS;

        #pragma unroll
        for (int kk = 0; kk < 8; kk++) {        // 8 k16-steps over 128
            uint32_t afx[4];
            LDSM_X4(afx, zlm + kk * 32);        // 16 halfs = 32 bytes per step
            #pragma unroll
            for (int ct = 0; ct < 8; ct++) {
                uint32_t bfx[2];
                LDSM_X2T(bfx, psBase +
                    (uint32_t)((kk * 16 + r16) * PS2 + ct * 8) * 2);
                mma16(cacc[ct], afx, bfx);
            }
        }

        size_t slab = (size_t)cx * M;
        int r0 = rowBase + warp * 16 + lg;
        #pragma unroll
        for (int ct = 0; ct < 8; ct++) {
            int col = ct * 8 + lq * 2;
            *(float2*)&crossp[(slab + r0) * NWAY + col] =
                make_float2(cacc[ct][0], cacc[ct][1]);
            *(float2*)&crossp[(slab + r0 + 8) * NWAY + col] =
                make_float2(cacc[ct][2], cacc[ct][3]);
        }
    }
}

// ---------------------------------------------------------------------------
// k_fin: out[q,c] = 2 * sum_cx crossp[cx][q][c] - sum_j znp[j][q] - pnorm[c]
// ---------------------------------------------------------------------------
__global__ void k_fin(const float* __restrict__ crossp,
                      const float* __restrict__ znp,
                      const float* __restrict__ pnorm,
                      float* __restrict__ out, int Q) {
    int idx = blockIdx.x * blockDim.x + threadIdx.x;
    int q = idx >> 4;
    int c4 = (idx & 15) * 4;
    size_t base = (size_t)q * NWAY + c4;
    size_t slab = (size_t)Q * NWAY;

    float4 s0 = *(const float4*)&crossp[base];
    float4 s1 = *(const float4*)&crossp[base + slab];
    float4 s2 = *(const float4*)&crossp[base + 2 * slab];
    float4 s3 = *(const float4*)&crossp[base + 3 * slab];

    float zn = 0.f;
    #pragma unroll
    for (int j = 0; j < NC * 4; j++) zn += znp[(size_t)j * Q + q];

    float4 pn = *(const float4*)&pnorm[c4];

    float4 o;
    o.x = 2.0f * (s0.x + s1.x + s2.x + s3.x) - zn - pn.x;
    o.y = 2.0f * (s0.y + s1.y + s2.y + s3.y) - zn - pn.y;
    o.z = 2.0f * (s0.z + s1.z + s2.z + s3.z) - zn - pn.z;
    o.w = 2.0f * (s0.w + s1.w + s2.w + s3.w) - zn - pn.w;
    *(float4*)&out[base] = o;
}

// ---------------------------------------------------------------------------
// Host launcher
// ---------------------------------------------------------------------------
extern "C" void kernel_launch(void* const* d_in, const int* in_sizes, int n_in,
                              void* d_out, int out_size) {
    const float* xs = (const float*)d_in[0];
    const void*  ys = d_in[1];
    const float* xq = (const float*)d_in[2];
    const float* W  = (const float*)d_in[3];
    const float* b  = (const float*)d_in[4];

    int S = in_sizes[1];
    int F = in_sizes[0] / S;
    int D = in_sizes[4];
    int Q = in_sizes[2] / F;

    float *p_cls, *p_proto, *p_pnorm, *p_invcnt, *p_crossp, *p_znp;
    int *p_ys, *p_cnt;
    cudaGetSymbolAddress((void**)&p_cls, g_cls_sum);
    cudaGetSymbolAddress((void**)&p_proto, g_proto);
    cudaGetSymbolAddress((void**)&p_pnorm, g_pnorm);
    cudaGetSymbolAddress((void**)&p_invcnt, g_invcnt);
    cudaGetSymbolAddress((void**)&p_ys, g_ys);
    cudaGetSymbolAddress((void**)&p_cnt, g_cnt);
    cudaGetSymbolAddress((void**)&p_crossp, g_crossp);
    cudaGetSymbolAddress((void**)&p_znp, g_znp);

    // 0. zero atomic accumulators
    {
        int n = NWAY * F + NWAY * D;
        k_zero2<<<(n + 255) / 256, 256>>>(p_cls, NWAY * F, p_proto, NWAY * D);
    }

    // 1. labels + counts
    k_prep<<<1, 256>>>(ys, S, p_ys, p_invcnt, p_cnt);

    // 2. class sums in F-space
    {
        dim3 grid(F / 128, 8);
        k_cls_sum<<<grid, 128>>>(xs, S, F, p_ys, p_cls);
    }

    // 3. prototypes: proto = (invcnt*cls_sum) @ W  (tf32 tensor cores)
    {
        cudaFuncSetAttribute(k_proto_tc,
                             cudaFuncAttributeMaxDynamicSharedMemorySize,
                             PROTO_SMEM_FLOATS * 4);
        dim3 grid(D / 128, F / 128);
        k_proto_tc<<<grid, 256, PROTO_SMEM_FLOATS * 4>>>(
            p_cls, W, p_invcnt, p_proto, F, D);
    }

    // 4. proto finalize
    k_proto_fin<<<NWAY, 128>>>(p_proto, b, p_cnt, p_pnorm, D);

    // 5. fused fp16 GEMM: z-tiles + znorm partials + cross partials
    {
        cudaFuncSetAttribute(gemm_fused,
                             cudaFuncAttributeMaxDynamicSharedMemorySize,
                             GEMM_SMEM);
        dim3 grid(NC, Q / 128);
        gemm_fused<<<grid, 256, GEMM_SMEM>>>(
            xq, W, b, p_proto, p_crossp, p_znp, Q, D, F);
    }

    // 6. combine partials -> output
    k_fin<<<Q * 16 / 256, 256>>>(p_crossp, p_znp, p_pnorm, (float*)d_out, Q);
}

// round 11
// speedup vs baseline: 8.1719x; 1.3097x over previous
#include <cuda_runtime.h>
#include <cuda_fp16.h>
#include <cstdint>

// ---------------------------------------------------------------------------
// ProtoNet: out[q,c] = -||z_q - proto_c||^2
//   z_q   = xq @ W + b   (fp16 m16n8k16 mma, fp32 accum, cp.async pipeline,
//                         never materialized to gmem)
//   proto = (classsum(xs)/cnt) @ W + b   (tf32 mma.sync, split-K)
//   out   = 2*z.proto^T - ||z||^2 - ||proto||^2
// Shapes: S=1024, Q=16384, F=2048, D=512, NWAY=64
// ---------------------------------------------------------------------------

#define NWAY 64
#define Q_MAX 16384
#define F_MAX 2048
#define NC 4              // D / 128 column chunks

__device__ __half g_xq16[(size_t)Q_MAX * F_MAX];          // 64 MB
__device__ __half g_w16[F_MAX * 512];                     // 2 MB
__device__ float g_cls_sum[NWAY * F_MAX];                 // 512 KB
__device__ float g_proto[NWAY * 512];                     // 128 KB
__device__ float g_pnorm[NWAY];
__device__ int   g_ys[4096];
__device__ float g_invcnt[NWAY];
__device__ int   g_cnt[NWAY];
__device__ float g_crossp[(size_t)NC * Q_MAX * NWAY];     // 16 MB partial cross
__device__ float g_znp[NC * 4 * Q_MAX];                   // 1 MB partial norms

// ---------------------------------------------------------------------------
// helpers
// ---------------------------------------------------------------------------
__device__ __forceinline__ float f2tf32(float x) {
    unsigned u;
    asm("cvt.rna.tf32.f32 %0, %1;" : "=r"(u) : "f"(x));
    return __uint_as_float(u);
}

__device__ __forceinline__ void mma8(float* d, const float* a, const float* b) {
    const unsigned* A = reinterpret_cast<const unsigned*>(a);
    const unsigned* B = reinterpret_cast<const unsigned*>(b);
    asm volatile(
        "mma.sync.aligned.m16n8k8.row.col.f32.tf32.tf32.f32 "
        "{%0,%1,%2,%3}, {%4,%5,%6,%7}, {%8,%9}, {%0,%1,%2,%3};\n"
        : "+f"(d[0]), "+f"(d[1]), "+f"(d[2]), "+f"(d[3])
        : "r"(A[0]), "r"(A[1]), "r"(A[2]), "r"(A[3]), "r"(B[0]), "r"(B[1]));
}

__device__ __forceinline__ void mma16(float* d, const uint32_t* a,
                                      const uint32_t* b) {
    asm volatile(
        "mma.sync.aligned.m16n8k16.row.col.f32.f16.f16.f32 "
        "{%0,%1,%2,%3}, {%4,%5,%6,%7}, {%8,%9}, {%0,%1,%2,%3};\n"
        : "+f"(d[0]), "+f"(d[1]), "+f"(d[2]), "+f"(d[3])
        : "r"(a[0]), "r"(a[1]), "r"(a[2]), "r"(a[3]), "r"(b[0]), "r"(b[1]));
}

#define LDSM_X4(r, addr)                                                      \
    asm volatile("ldmatrix.sync.aligned.m8n8.x4.shared.b16 {%0,%1,%2,%3}, [%4];" \
                 : "=r"((r)[0]), "=r"((r)[1]), "=r"((r)[2]), "=r"((r)[3])     \
                 : "r"(addr))

#define LDSM_X2T(r, addr)                                                     \
    asm volatile("ldmatrix.sync.aligned.m8n8.x2.trans.shared.b16 {%0,%1}, [%2];" \
                 : "=r"((r)[0]), "=r"((r)[1]) : "r"(addr))

#define CP_ASYNC16(dst, src)                                                  \
    asm volatile("cp.async.cg.shared.global [%0], [%1], 16;"                  \
                 :: "r"(dst), "l"(src) : "memory")
#define CP_COMMIT() asm volatile("cp.async.commit_group;" ::: "memory")
#define CP_WAIT3()  asm volatile("cp.async.wait_group 3;" ::: "memory")

__device__ __forceinline__ uint32_t smem_u32(const void* p) {
    uint32_t a;
    asm("{ .reg .u64 t; cvta.to.shared.u64 t, %1; cvt.u32.u64 %0, t; }"
        : "=r"(a) : "l"(p));
    return a;
}

// ---------------------------------------------------------------------------
__global__ void k_zero2(float* a, int na, float* b, int nb) {
    int i = blockIdx.x * blockDim.x + threadIdx.x;
    if (i < na) a[i] = 0.0f;
    else { int j = i - na; if (j < nb) b[j] = 0.0f; }
}

// k_cvt: fp32 -> fp16, 8 elems/thread
__global__ void k_cvt(const float* __restrict__ x, __half* __restrict__ y,
                      int n8) {
    int i = blockIdx.x * blockDim.x + threadIdx.x;
    if (i >= n8) return;
    const float4* p = (const float4*)x + (size_t)i * 2;
    float4 a = p[0], b = p[1];
    __half2 h[4];
    h[0] = __floats2half2_rn(a.x, a.y);
    h[1] = __floats2half2_rn(a.z, a.w);
    h[2] = __floats2half2_rn(b.x, b.y);
    h[3] = __floats2half2_rn(b.z, b.w);
    *(uint4*)(y + (size_t)i * 8) = *(uint4*)h;
}

// ---------------------------------------------------------------------------
// k_prep: detect int64-vs-int32 label layout, normalize labels, class counts.
// ---------------------------------------------------------------------------
__global__ void k_prep(const void* ys_raw, int S, int* ys_out, float* invcnt,
                       int* cnt_out) {
    __shared__ int s_is32;
    __shared__ int s_cnt[NWAY];
    int tid = threadIdx.x;
    if (tid == 0) s_is32 = 0;
    if (tid < NWAY) s_cnt[tid] = 0;
    __syncthreads();

    const int* w32 = (const int*)ys_raw;
    for (int j = 1 + 2 * tid; j < S; j += 2 * blockDim.x) {
        if (w32[j] != 0) s_is32 = 1;   // benign race
    }
    __syncthreads();
    int is64 = !s_is32;

    const long long* w64 = (const long long*)ys_raw;
    for (int i = tid; i < S; i += blockDim.x) {
        int c = is64 ? (int)w64[i] : w32[i];
        ys_out[i] = c;
        atomicAdd(&s_cnt[c], 1);
    }
    __syncthreads();
    if (tid < NWAY) {
        int c = s_cnt[tid];
        cnt_out[tid] = c;
        invcnt[tid] = 1.0f / (float)(c > 0 ? c : 1);
    }
}

// ---------------------------------------------------------------------------
// k_cls_sum: per-class SUM of xs in F-space, S split 8 ways, atomic combine.
// ---------------------------------------------------------------------------
__global__ void k_cls_sum(const float* __restrict__ xs, int S, int F,
                          const int* __restrict__ ys,
                          float* __restrict__ cls_sum) {
    __shared__ float acc[NWAY][128];
    __shared__ int s_ys[256];
    int tid = threadIdx.x;
    int f = blockIdx.x * 128 + tid;
    int chunk = S / gridDim.y;
    int s0 = blockIdx.y * chunk;

    #pragma unroll
    for (int c = 0; c < NWAY; c++) acc[c][tid] = 0.0f;
    for (int i = tid; i < chunk; i += blockDim.x) s_ys[i] = ys[s0 + i];
    __syncthreads();

    #pragma unroll 4
    for (int i = 0; i < chunk; i++) {
        acc[s_ys[i]][tid] += xs[(size_t)(s0 + i) * F + f];
    }
    __syncthreads();

    #pragma unroll
    for (int c = 0; c < NWAY; c++) {
        atomicAdd(&cls_sum[(size_t)c * F + f], acc[c][tid]);
    }
}

// ---------------------------------------------------------------------------
// k_proto_tc: proto += ((invcnt*cls_sum) @ W) tile, tf32 mma.sync, split-K.
// ---------------------------------------------------------------------------
#define PAS 132
#define PWS 136
#define PROTO_SMEM_FLOATS (64 * PAS + 128 * PWS)

__global__ __launch_bounds__(256) void k_proto_tc(
    const float* __restrict__ cls_sum, const float* __restrict__ W,
    const float* __restrict__ invcnt, float* __restrict__ proto,
    int F, int D)
{
    extern __shared__ float sm[];
    float* As = sm;
    float* Ws = sm + 64 * PAS;

    int tid  = threadIdx.x;
    int warp = tid >> 5, lane = tid & 31;
    int wm = warp & 1;
    int wn = warp >> 1;
    int colBase = blockIdx.x * 128;
    int k0 = blockIdx.y * 128;

    {
        int row = tid >> 2;
        int kp  = (tid & 3) * 32;
        float ic = invcnt[row];
        const float* ap = cls_sum + (size_t)row * F + k0 + kp;
        #pragma unroll
        for (int j = 0; j < 8; j++) {
            float4 v = *(const float4*)(ap + j * 4);
            float4 t;
            t.x = f2tf32(v.x * ic); t.y = f2tf32(v.y * ic);
            t.z = f2tf32(v.z * ic); t.w = f2tf32(v.w * ic);
            *(float4*)&As[row * PAS + kp + j * 4] = t;
        }
    }
    {
        int kr = tid >> 1;
        int cp = (tid & 1) * 64;
        const float* wp = W + (size_t)(k0 + kr) * D + colBase + cp;
        #pragma unroll
        for (int j = 0; j < 16; j++) {
            float4 v = *(const float4*)(wp + j * 4);
            float4 t;
            t.x = f2tf32(v.x); t.y = f2tf32(v.y);
            t.z = f2tf32(v.z); t.w = f2tf32(v.w);
            *(float4*)&Ws[kr * PWS + cp + j * 4] = t;
        }
    }
    __syncthreads();

    int lg = lane >> 2;
    int lq = lane & 3;

    float acc[2][4][4];
    #pragma unroll
    for (int i = 0; i < 2; i++)
        #pragma unroll
        for (int j = 0; j < 4; j++)
            #pragma unroll
            for (int r = 0; r < 4; r++) acc[i][j][r] = 0.0f;

    int aoff[2], boff[4];
    #pragma unroll
    for (int mt = 0; mt < 2; mt++)
        aoff[mt] = (wm * 32 + mt * 16 + lg) * PAS + lq;
    #pragma unroll
    for (int nt = 0; nt < 4; nt++)
        boff[nt] = lq * PWS + wn * 32 + nt * 8 + lg;

    #pragma unroll 4
    for (int kk = 0; kk < 128; kk += 8) {
        float af[2][4], bf[4][2];
        #pragma unroll
        for (int mt = 0; mt < 2; mt++) {
            const float* base = &As[aoff[mt] + kk];
            af[mt][0] = base[0];
            af[mt][1] = base[8 * PAS];
            af[mt][2] = base[4];
            af[mt][3] = base[8 * PAS + 4];
        }
        #pragma unroll
        for (int nt = 0; nt < 4; nt++) {
            const float* base = &Ws[boff[nt] + kk * PWS];
            bf[nt][0] = base[0];
            bf[nt][1] = base[4 * PWS];
        }
        #pragma unroll
        for (int mt = 0; mt < 2; mt++)
            #pragma unroll
            for (int nt = 0; nt < 4; nt++)
                mma8(acc[mt][nt], af[mt], bf[nt]);
    }

    #pragma unroll
    for (int mt = 0; mt < 2; mt++) {
        int r = wm * 32 + mt * 16 + lg;
        #pragma unroll
        for (int nt = 0; nt < 4; nt++) {
            int d = colBase + wn * 32 + nt * 8 + lq * 2;
            atomicAdd(&proto[(size_t)r * D + d],       acc[mt][nt][0]);
            atomicAdd(&proto[(size_t)r * D + d + 1],   acc[mt][nt][1]);
            atomicAdd(&proto[(size_t)(r + 8) * D + d],     acc[mt][nt][2]);
            atomicAdd(&proto[(size_t)(r + 8) * D + d + 1], acc[mt][nt][3]);
        }
    }
}

// ---------------------------------------------------------------------------
// k_proto_fin: proto[c][d] += b[d] (non-empty classes only), pnorm[c]
// ---------------------------------------------------------------------------
__global__ void k_proto_fin(float* __restrict__ proto,
                            const float* __restrict__ bias,
                            const int* __restrict__ cnt,
                            float* __restrict__ pnorm, int D) {
    __shared__ float red[128];
    int c = blockIdx.x;
    int tid = threadIdx.x;
    bool nonempty = cnt[c] > 0;
    float s = 0.f;
    for (int d = tid; d < D; d += blockDim.x) {
        float v = proto[(size_t)c * D + d] + (nonempty ? bias[d] : 0.0f);
        proto[(size_t)c * D + d] = v;
        s = fmaf(v, v, s);
    }
    red[tid] = s;
    __syncthreads();
    for (int o = 64; o > 0; o >>= 1) {
        if (tid < o) red[tid] += red[tid + o];
        __syncthreads();
    }
    if (tid == 0) pnorm[c] = red[0];
}

// ---------------------------------------------------------------------------
// gemm_fused (fp16 + cp.async): chunk cx (128 cols of D), 128-row xq tile.
//   z = xq16 @ w16[:,chunk] + b       (m16n8k16, fp32 accum, 4-slot pipeline)
//   znp[cx*4+wn][row]  = partial ||z||^2 (warp's 32 cols)
//   crossp[cx][row][c] = z_chunk @ proto[:,chunk]^T  (fp16 mma on smem z)
// SMEM layout (bytes):
//   A slots: 4 x 10240 at 0        (128 rows x 40 halfs)
//   B slots: 4 x 8704  at 40960    (32 k x 136 halfs)
//   Zs: [0, 34816)  128x136 half   (epilogue, overlaps A slots)
//   Ps: [75776, 94208) 128x72 half
// ---------------------------------------------------------------------------
#define BK 32
#define AS2 40      // halfs per A row (32 + 8) ; 80 B row = 16B-multiple
#define BS2 136     // halfs per B k-row (128 + 8) ; 272 B row
#define ZS2 136
#define PS2 72
#define A_BYTES (128 * AS2 * 2)     // 10240
#define B_BYTES (BK * BS2 * 2)      // 8704
#define OFF_B   (4 * A_BYTES)       // 40960
#define OFF_PS  75776
#define GEMM_SMEM (OFF_PS + 128 * PS2 * 2)   // 94208

__global__ __launch_bounds__(256, 2) void gemm_fused(
    const __half* __restrict__ A, const __half* __restrict__ Wh,
    const float* __restrict__ bias, const float* __restrict__ proto,
    float* __restrict__ crossp, float* __restrict__ znp,
    int M, int N, int K)
{
    extern __shared__ __align__(16) char smraw[];
    const uint32_t sbase = smem_u32(smraw);

    int tid  = threadIdx.x;
    int warp = tid >> 5, lane = tid & 31;
    int wm = warp & 1;        // 0..1  (64-row half)
    int wn = warp >> 1;       // 0..3  (32-col strip)
    int cx = blockIdx.x;
    int rowBase = blockIdx.y * 128;
    int colBase = cx * 128;

    // per-thread cp.async assignments (2 x 16B for A, 2 x 16B for B)
    int aRow0 = tid >> 1,           aOff0 = (tid & 1) * 16;       // chunk tid*2 base? no:
    // A: 512 chunks of 8 halfs; chunk = tid + j*256 -> row = chunk>>2, off=(chunk&3)*8
    // B: 512 chunks; chunk = tid + j*256 -> row = chunk>>4, off=(chunk&15)*8
    int aR[2], aO[2], bR[2], bO[2];
    #pragma unroll
    for (int j = 0; j < 2; j++) {
        int ch = tid + j * 256;
        aR[j] = ch >> 2;  aO[j] = (ch & 3) * 8;
        bR[j] = ch >> 4;  bO[j] = (ch & 15) * 8;
    }
    const __half* aG = A + (size_t)rowBase * K;
    const __half* bG = Wh + colBase;

    float acc[4][4][4];
    #pragma unroll
    for (int i = 0; i < 4; i++)
        #pragma unroll
        for (int j = 0; j < 4; j++)
            #pragma unroll
            for (int r = 0; r < 4; r++) acc[i][j][r] = 0.0f;

    // ldmatrix per-lane byte offsets
    int r16 = lane & 15, khalf = (lane >> 4) * 8;
    uint32_t aFragOff[4], bFragOff[4];
    #pragma unroll
    for (int mt = 0; mt < 4; mt++)
        aFragOff[mt] = (uint32_t)((wm * 64 + mt * 16 + r16) * AS2 + khalf) * 2;
    #pragma unroll
    for (int nt = 0; nt < 4; nt++)
        bFragOff[nt] = (uint32_t)(r16 * BS2 + wn * 32 + nt * 8) * 2;

    const int nIt = K / BK;   // 64

    // prologue: fill slots 0..2
    #pragma unroll
    for (int s = 0; s < 3; s++) {
        int k0 = s * BK;
        #pragma unroll
        for (int j = 0; j < 2; j++) {
            CP_ASYNC16(sbase + s * A_BYTES + (uint32_t)(aR[j] * AS2 + aO[j]) * 2,
                       aG + (size_t)aR[j] * K + k0 + aO[j]);
            CP_ASYNC16(sbase + OFF_B + s * B_BYTES + (uint32_t)(bR[j] * BS2 + bO[j]) * 2,
                       bG + (size_t)(k0 + bR[j]) * N + bO[j]);
        }
        CP_COMMIT();
    }

    for (int it = 0; it < nIt; ++it) {
        __syncthreads();   // all warps done computing slot (it+3)&3's old data
        if (it + 3 < nIt) {
            int s = (it + 3) & 3;
            int k0 = (it + 3) * BK;
            #pragma unroll
            for (int j = 0; j < 2; j++) {
                CP_ASYNC16(sbase + s * A_BYTES + (uint32_t)(aR[j] * AS2 + aO[j]) * 2,
                           aG + (size_t)aR[j] * K + k0 + aO[j]);
                CP_ASYNC16(sbase + OFF_B + s * B_BYTES + (uint32_t)(bR[j] * BS2 + bO[j]) * 2,
                           bG + (size_t)(k0 + bR[j]) * N + bO[j]);
            }
        }
        CP_COMMIT();
        CP_WAIT3();
        __syncthreads();   // all threads' copies for slot it&3 visible

        uint32_t aB = sbase + (it & 3) * A_BYTES;
        uint32_t bB = sbase + OFF_B + (it & 3) * B_BYTES;
        #pragma unroll
        for (int ks = 0; ks < 2; ks++) {       // two k16 steps in BK=32
            uint32_t af[4][4], bf[4][2];
            #pragma unroll
            for (int mt = 0; mt < 4; mt++)
                LDSM_X4(af[mt], aB + aFragOff[mt] + ks * 32);
            #pragma unroll
            for (int nt = 0; nt < 4; nt++)
                LDSM_X2T(bf[nt], bB + bFragOff[nt] + ks * 16 * BS2 * 2);
            #pragma unroll
            for (int mt = 0; mt < 4; mt++)
                #pragma unroll
                for (int nt = 0; nt < 4; nt++)
                    mma16(acc[mt][nt], af[mt], bf[nt]);
        }
    }
    __syncthreads();   // all mma smem reads done before Zs overwrites

    __half* Zs = (__half*)smraw;
    __half* Ps = (__half*)(smraw + OFF_PS);

    // fill Ps: proto[c][colBase..+128] -> Ps[d][c] fp16 (disjoint region)
    {
        int cc = tid >> 2;
        int dpart = (tid & 3) * 32;
        const float* pr = proto + (size_t)cc * N + colBase + dpart;
        #pragma unroll
        for (int j = 0; j < 8; j++) {
            float4 v = *(const float4*)(pr + j * 4);
            int d = dpart + j * 4;
            Ps[(d + 0) * PS2 + cc] = __float2half_rn(v.x);
            Ps[(d + 1) * PS2 + cc] = __float2half_rn(v.y);
            Ps[(d + 2) * PS2 + cc] = __float2half_rn(v.z);
            Ps[(d + 3) * PS2 + cc] = __float2half_rn(v.w);
        }
    }

    int lg = lane >> 2, lq = lane & 3;

    // epilogue 1: bias add, znorm partials, stage z (fp16) into Zs
    #pragma unroll
    for (int mt = 0; mt < 4; mt++) {
        int rl = wm * 64 + mt * 16 + lg;
        float sum0 = 0.f, sum1 = 0.f;
        #pragma unroll
        for (int nt = 0; nt < 4; nt++) {
            int cl = wn * 32 + nt * 8 + lq * 2;
            float bv0 = bias[colBase + cl], bv1 = bias[colBase + cl + 1];
            float v0 = acc[mt][nt][0] + bv0;
            float v1 = acc[mt][nt][1] + bv1;
            float v2 = acc[mt][nt][2] + bv0;
            float v3 = acc[mt][nt][3] + bv1;
            *(__half2*)&Zs[rl * ZS2 + cl]       = __floats2half2_rn(v0, v1);
            *(__half2*)&Zs[(rl + 8) * ZS2 + cl] = __floats2half2_rn(v2, v3);
            sum0 = fmaf(v0, v0, fmaf(v1, v1, sum0));
            sum1 = fmaf(v2, v2, fmaf(v3, v3, sum1));
        }
        sum0 += __shfl_xor_sync(0xFFFFFFFFu, sum0, 1);
        sum0 += __shfl_xor_sync(0xFFFFFFFFu, sum0, 2);
        sum1 += __shfl_xor_sync(0xFFFFFFFFu, sum1, 1);
        sum1 += __shfl_xor_sync(0xFFFFFFFFu, sum1, 2);
        if (lq == 0) {
            int slab = (cx * 4 + wn) * M;
            znp[slab + rowBase + rl]     = sum0;
            znp[slab + rowBase + rl + 8] = sum1;
        }
    }
    __syncthreads();

    // epilogue 2: cross partial = Zs[128x128] @ Ps^T -> [128 x 64] (fp16 mma)
    {
        float cacc[8][4];
        #pragma unroll
        for (int ct = 0; ct < 8; ct++)
            #pragma unroll
            for (int r = 0; r < 4; r++) cacc[ct][r] = 0.0f;

        uint32_t zlm = sbase + (uint32_t)((warp * 16 + r16) * ZS2 + khalf) * 2;
        uint32_t psBase = sbase + OFF_PS;

        #pragma unroll
        for (int kk = 0; kk < 8; kk++) {
            uint32_t afx[4];
            LDSM_X4(afx, zlm + kk * 32);
            #pragma unroll
            for (int ct = 0; ct < 8; ct++) {
                uint32_t bfx[2];
                LDSM_X2T(bfx, psBase +
                    (uint32_t)((kk * 16 + r16) * PS2 + ct * 8) * 2);
                mma16(cacc[ct], afx, bfx);
            }
        }

        size_t slab = (size_t)cx * M;
        int r0 = rowBase + warp * 16 + lg;
        #pragma unroll
        for (int ct = 0; ct < 8; ct++) {
            int col = ct * 8 + lq * 2;
            *(float2*)&crossp[(slab + r0) * NWAY + col] =
                make_float2(cacc[ct][0], cacc[ct][1]);
            *(float2*)&crossp[(slab + r0 + 8) * NWAY + col] =
                make_float2(cacc[ct][2], cacc[ct][3]);
        }
    }
}

// ---------------------------------------------------------------------------
// k_fin: out[q,c] = 2 * sum_cx crossp[cx][q][c] - sum_j znp[j][q] - pnorm[c]
// ---------------------------------------------------------------------------
__global__ void k_fin(const float* __restrict__ crossp,
                      const float* __restrict__ znp,
                      const float* __restrict__ pnorm,
                      float* __restrict__ out, int Q) {
    int idx = blockIdx.x * blockDim.x + threadIdx.x;
    int q = idx >> 4;
    int c4 = (idx & 15) * 4;
    size_t base = (size_t)q * NWAY + c4;
    size_t slab = (size_t)Q * NWAY;

    float4 s0 = *(const float4*)&crossp[base];
    float4 s1 = *(const float4*)&crossp[base + slab];
    float4 s2 = *(const float4*)&crossp[base + 2 * slab];
    float4 s3 = *(const float4*)&crossp[base + 3 * slab];

    float zn = 0.f;
    #pragma unroll
    for (int j = 0; j < NC * 4; j++) zn += znp[(size_t)j * Q + q];

    float4 pn = *(const float4*)&pnorm[c4];

    float4 o;
    o.x = 2.0f * (s0.x + s1.x + s2.x + s3.x) - zn - pn.x;
    o.y = 2.0f * (s0.y + s1.y + s2.y + s3.y) - zn - pn.y;
    o.z = 2.0f * (s0.z + s1.z + s2.z + s3.z) - zn - pn.z;
    o.w = 2.0f * (s0.w + s1.w + s2.w + s3.w) - zn - pn.w;
    *(float4*)&out[base] = o;
}

// ---------------------------------------------------------------------------
// Host launcher
// ---------------------------------------------------------------------------
extern "C" void kernel_launch(void* const* d_in, const int* in_sizes, int n_in,
                              void* d_out, int out_size) {
    const float* xs = (const float*)d_in[0];
    const void*  ys = d_in[1];
    const float* xq = (const float*)d_in[2];
    const float* W  = (const float*)d_in[3];
    const float* b  = (const float*)d_in[4];

    int S = in_sizes[1];
    int F = in_sizes[0] / S;
    int D = in_sizes[4];
    int Q = in_sizes[2] / F;

    float *p_cls, *p_proto, *p_pnorm, *p_invcnt, *p_crossp, *p_znp;
    __half *p_xq16, *p_w16;
    int *p_ys, *p_cnt;
    cudaGetSymbolAddress((void**)&p_cls, g_cls_sum);
    cudaGetSymbolAddress((void**)&p_proto, g_proto);
    cudaGetSymbolAddress((void**)&p_pnorm, g_pnorm);
    cudaGetSymbolAddress((void**)&p_invcnt, g_invcnt);
    cudaGetSymbolAddress((void**)&p_ys, g_ys);
    cudaGetSymbolAddress((void**)&p_cnt, g_cnt);
    cudaGetSymbolAddress((void**)&p_crossp, g_crossp);
    cudaGetSymbolAddress((void**)&p_znp, g_znp);
    cudaGetSymbolAddress((void**)&p_xq16, g_xq16);
    cudaGetSymbolAddress((void**)&p_w16, g_w16);

    // 0a. fp16 prepass for the big GEMM operands
    {
        int n8 = Q * F / 8;
        k_cvt<<<(n8 + 255) / 256, 256>>>(xq, p_xq16, n8);
        int w8 = F * D / 8;
        k_cvt<<<(w8 + 255) / 256, 256>>>(W, p_w16, w8);
    }

    // 0b. zero atomic accumulators
    {
        int n = NWAY * F + NWAY * D;
        k_zero2<<<(n + 255) / 256, 256>>>(p_cls, NWAY * F, p_proto, NWAY * D);
    }

    // 1. labels + counts
    k_prep<<<1, 256>>>(ys, S, p_ys, p_invcnt, p_cnt);

    // 2. class sums in F-space
    {
        dim3 grid(F / 128, 8);
        k_cls_sum<<<grid, 128>>>(xs, S, F, p_ys, p_cls);
    }

    // 3. prototypes: proto = (invcnt*cls_sum) @ W  (tf32 tensor cores)
    {
        cudaFuncSetAttribute(k_proto_tc,
                             cudaFuncAttributeMaxDynamicSharedMemorySize,
                             PROTO_SMEM_FLOATS * 4);
        dim3 grid(D / 128, F / 128);
        k_proto_tc<<<grid, 256, PROTO_SMEM_FLOATS * 4>>>(
            p_cls, W, p_invcnt, p_proto, F, D);
    }

    // 4. proto finalize
    k_proto_fin<<<NWAY, 128>>>(p_proto, b, p_cnt, p_pnorm, D);

    // 5. fused fp16 GEMM (cp.async pipeline)
    {
        cudaFuncSetAttribute(gemm_fused,
                             cudaFuncAttributeMaxDynamicSharedMemorySize,
                             GEMM_SMEM);
        dim3 grid(NC, Q / 128);
        gemm_fused<<<grid, 256, GEMM_SMEM>>>(
            p_xq16, p_w16, b, p_proto, p_crossp, p_znp, Q, D, F);
    }

    // 6. combine partials -> output
    k_fin<<<Q * 16 / 256, 256>>>(p_crossp, p_znp, p_pnorm, (float*)d_out, Q);
}

// round 12
// speedup vs baseline: 8.2903x; 1.0145x over previous
#include <cuda_runtime.h>
#include <cuda_fp16.h>
#include <cstdint>

// ---------------------------------------------------------------------------
// ProtoNet: out[q,c] = -||z_q - proto_c||^2
//   z_q   = xq @ W + b   (fp16 m16n8k16 mma, fp32 accum, cp.async pipeline,
//                         never materialized to gmem)
//   proto = (classsum(xs)/cnt) @ W + b   (tf32 mma.sync, split-K)
//   out   = 2*z.proto^T - ||z||^2 - ||proto||^2
// Two-stream capture DAG: [cvt xq/W fp16] || [labels->cls_sum->proto->pnorm]
// Shapes: S=1024, Q=16384, F=2048, D=512, NWAY=64
// ---------------------------------------------------------------------------

#define NWAY 64
#define Q_MAX 16384
#define F_MAX 2048
#define NC 4              // D / 128 column chunks

__device__ __half g_xq16[(size_t)Q_MAX * F_MAX];          // 64 MB
__device__ __half g_w16[F_MAX * 512];                     // 2 MB
__device__ float g_cls_sum[NWAY * F_MAX];                 // 512 KB
__device__ float g_proto[NWAY * 512];                     // 128 KB
__device__ float g_pnorm[NWAY];
__device__ int   g_ys[4096];
__device__ float g_invcnt[NWAY];
__device__ int   g_cnt[NWAY];
__device__ float g_crossp[(size_t)NC * Q_MAX * NWAY];     // 16 MB partial cross
__device__ float g_znp[NC * 4 * Q_MAX];                   // 1 MB partial norms

// ---------------------------------------------------------------------------
// helpers
// ---------------------------------------------------------------------------
__device__ __forceinline__ float f2tf32(float x) {
    unsigned u;
    asm("cvt.rna.tf32.f32 %0, %1;" : "=r"(u) : "f"(x));
    return __uint_as_float(u);
}

__device__ __forceinline__ void mma8(float* d, const float* a, const float* b) {
    const unsigned* A = reinterpret_cast<const unsigned*>(a);
    const unsigned* B = reinterpret_cast<const unsigned*>(b);
    asm volatile(
        "mma.sync.aligned.m16n8k8.row.col.f32.tf32.tf32.f32 "
        "{%0,%1,%2,%3}, {%4,%5,%6,%7}, {%8,%9}, {%0,%1,%2,%3};\n"
        : "+f"(d[0]), "+f"(d[1]), "+f"(d[2]), "+f"(d[3])
        : "r"(A[0]), "r"(A[1]), "r"(A[2]), "r"(A[3]), "r"(B[0]), "r"(B[1]));
}

__device__ __forceinline__ void mma16(float* d, const uint32_t* a,
                                      const uint32_t* b) {
    asm volatile(
        "mma.sync.aligned.m16n8k16.row.col.f32.f16.f16.f32 "
        "{%0,%1,%2,%3}, {%4,%5,%6,%7}, {%8,%9}, {%0,%1,%2,%3};\n"
        : "+f"(d[0]), "+f"(d[1]), "+f"(d[2]), "+f"(d[3])
        : "r"(a[0]), "r"(a[1]), "r"(a[2]), "r"(a[3]), "r"(b[0]), "r"(b[1]));
}

#define LDSM_X4(r, addr)                                                      \
    asm volatile("ldmatrix.sync.aligned.m8n8.x4.shared.b16 {%0,%1,%2,%3}, [%4];" \
                 : "=r"((r)[0]), "=r"((r)[1]), "=r"((r)[2]), "=r"((r)[3])     \
                 : "r"(addr))

#define LDSM_X2T(r, addr)                                                     \
    asm volatile("ldmatrix.sync.aligned.m8n8.x2.trans.shared.b16 {%0,%1}, [%2];" \
                 : "=r"((r)[0]), "=r"((r)[1]) : "r"(addr))

#define CP_ASYNC16(dst, src)                                                  \
    asm volatile("cp.async.cg.shared.global [%0], [%1], 16;"                  \
                 :: "r"(dst), "l"(src) : "memory")
#define CP_COMMIT() asm volatile("cp.async.commit_group;" ::: "memory")
#define CP_WAIT2()  asm volatile("cp.async.wait_group 2;" ::: "memory")

__device__ __forceinline__ uint32_t smem_u32(const void* p) {
    uint32_t a;
    asm("{ .reg .u64 t; cvta.to.shared.u64 t, %1; cvt.u32.u64 %0, t; }"
        : "=r"(a) : "l"(p));
    return a;
}

// ---------------------------------------------------------------------------
__global__ void k_zero2(float* a, int na, float* b, int nb) {
    int i = blockIdx.x * blockDim.x + threadIdx.x;
    if (i < na) a[i] = 0.0f;
    else { int j = i - na; if (j < nb) b[j] = 0.0f; }
}

// k_cvt2: fp32 -> fp16 for two arrays in one launch, 8 elems/thread
__global__ void k_cvt2(const float* __restrict__ x0, __half* __restrict__ y0,
                       int n8_0,
                       const float* __restrict__ x1, __half* __restrict__ y1,
                       int n8_1) {
    int i = blockIdx.x * blockDim.x + threadIdx.x;
    const float* x; __half* y; size_t idx;
    if (i < n8_0) { x = x0; y = y0; idx = (size_t)i; }
    else {
        int j = i - n8_0;
        if (j >= n8_1) return;
        x = x1; y = y1; idx = (size_t)j;
    }
    const float4* p = (const float4*)x + idx * 2;
    float4 a = p[0], b = p[1];
    __half2 h[4];
    h[0] = __floats2half2_rn(a.x, a.y);
    h[1] = __floats2half2_rn(a.z, a.w);
    h[2] = __floats2half2_rn(b.x, b.y);
    h[3] = __floats2half2_rn(b.z, b.w);
    *(uint4*)(y + idx * 8) = *(uint4*)h;
}

// ---------------------------------------------------------------------------
// k_prep: detect int64-vs-int32 label layout, normalize labels, class counts.
// ---------------------------------------------------------------------------
__global__ void k_prep(const void* ys_raw, int S, int* ys_out, float* invcnt,
                       int* cnt_out) {
    __shared__ int s_is32;
    __shared__ int s_cnt[NWAY];
    int tid = threadIdx.x;
    if (tid == 0) s_is32 = 0;
    if (tid < NWAY) s_cnt[tid] = 0;
    __syncthreads();

    const int* w32 = (const int*)ys_raw;
    for (int j = 1 + 2 * tid; j < S; j += 2 * blockDim.x) {
        if (w32[j] != 0) s_is32 = 1;   // benign race
    }
    __syncthreads();
    int is64 = !s_is32;

    const long long* w64 = (const long long*)ys_raw;
    for (int i = tid; i < S; i += blockDim.x) {
        int c = is64 ? (int)w64[i] : w32[i];
        ys_out[i] = c;
        atomicAdd(&s_cnt[c], 1);
    }
    __syncthreads();
    if (tid < NWAY) {
        int c = s_cnt[tid];
        cnt_out[tid] = c;
        invcnt[tid] = 1.0f / (float)(c > 0 ? c : 1);
    }
}

// ---------------------------------------------------------------------------
// k_cls_sum: per-class SUM of xs in F-space, S split 8 ways, atomic combine.
// ---------------------------------------------------------------------------
__global__ void k_cls_sum(const float* __restrict__ xs, int S, int F,
                          const int* __restrict__ ys,
                          float* __restrict__ cls_sum) {
    __shared__ float acc[NWAY][128];
    __shared__ int s_ys[256];
    int tid = threadIdx.x;
    int f = blockIdx.x * 128 + tid;
    int chunk = S / gridDim.y;
    int s0 = blockIdx.y * chunk;

    #pragma unroll
    for (int c = 0; c < NWAY; c++) acc[c][tid] = 0.0f;
    for (int i = tid; i < chunk; i += blockDim.x) s_ys[i] = ys[s0 + i];
    __syncthreads();

    #pragma unroll 4
    for (int i = 0; i < chunk; i++) {
        acc[s_ys[i]][tid] += xs[(size_t)(s0 + i) * F + f];
    }
    __syncthreads();

    #pragma unroll
    for (int c = 0; c < NWAY; c++) {
        atomicAdd(&cls_sum[(size_t)c * F + f], acc[c][tid]);
    }
}

// ---------------------------------------------------------------------------
// k_proto_tc: proto += ((invcnt*cls_sum) @ W) tile, tf32 mma.sync, split-K.
// ---------------------------------------------------------------------------
#define PAS 132
#define PWS 136
#define PROTO_SMEM_FLOATS (64 * PAS + 128 * PWS)

__global__ __launch_bounds__(256) void k_proto_tc(
    const float* __restrict__ cls_sum, const float* __restrict__ W,
    const float* __restrict__ invcnt, float* __restrict__ proto,
    int F, int D)
{
    extern __shared__ float sm[];
    float* As = sm;
    float* Ws = sm + 64 * PAS;

    int tid  = threadIdx.x;
    int warp = tid >> 5, lane = tid & 31;
    int wm = warp & 1;
    int wn = warp >> 1;
    int colBase = blockIdx.x * 128;
    int k0 = blockIdx.y * 128;

    {
        int row = tid >> 2;
        int kp  = (tid & 3) * 32;
        float ic = invcnt[row];
        const float* ap = cls_sum + (size_t)row * F + k0 + kp;
        #pragma unroll
        for (int j = 0; j < 8; j++) {
            float4 v = *(const float4*)(ap + j * 4);
            float4 t;
            t.x = f2tf32(v.x * ic); t.y = f2tf32(v.y * ic);
            t.z = f2tf32(v.z * ic); t.w = f2tf32(v.w * ic);
            *(float4*)&As[row * PAS + kp + j * 4] = t;
        }
    }
    {
        int kr = tid >> 1;
        int cp = (tid & 1) * 64;
        const float* wp = W + (size_t)(k0 + kr) * D + colBase + cp;
        #pragma unroll
        for (int j = 0; j < 16; j++) {
            float4 v = *(const float4*)(wp + j * 4);
            float4 t;
            t.x = f2tf32(v.x); t.y = f2tf32(v.y);
            t.z = f2tf32(v.z); t.w = f2tf32(v.w);
            *(float4*)&Ws[kr * PWS + cp + j * 4] = t;
        }
    }
    __syncthreads();

    int lg = lane >> 2;
    int lq = lane & 3;

    float acc[2][4][4];
    #pragma unroll
    for (int i = 0; i < 2; i++)
        #pragma unroll
        for (int j = 0; j < 4; j++)
            #pragma unroll
            for (int r = 0; r < 4; r++) acc[i][j][r] = 0.0f;

    int aoff[2], boff[4];
    #pragma unroll
    for (int mt = 0; mt < 2; mt++)
        aoff[mt] = (wm * 32 + mt * 16 + lg) * PAS + lq;
    #pragma unroll
    for (int nt = 0; nt < 4; nt++)
        boff[nt] = lq * PWS + wn * 32 + nt * 8 + lg;

    #pragma unroll 4
    for (int kk = 0; kk < 128; kk += 8) {
        float af[2][4], bf[4][2];
        #pragma unroll
        for (int mt = 0; mt < 2; mt++) {
            const float* base = &As[aoff[mt] + kk];
            af[mt][0] = base[0];
            af[mt][1] = base[8 * PAS];
            af[mt][2] = base[4];
            af[mt][3] = base[8 * PAS + 4];
        }
        #pragma unroll
        for (int nt = 0; nt < 4; nt++) {
            const float* base = &Ws[boff[nt] + kk * PWS];
            bf[nt][0] = base[0];
            bf[nt][1] = base[4 * PWS];
        }
        #pragma unroll
        for (int mt = 0; mt < 2; mt++)
            #pragma unroll
            for (int nt = 0; nt < 4; nt++)
                mma8(acc[mt][nt], af[mt], bf[nt]);
    }

    #pragma unroll
    for (int mt = 0; mt < 2; mt++) {
        int r = wm * 32 + mt * 16 + lg;
        #pragma unroll
        for (int nt = 0; nt < 4; nt++) {
            int d = colBase + wn * 32 + nt * 8 + lq * 2;
            atomicAdd(&proto[(size_t)r * D + d],       acc[mt][nt][0]);
            atomicAdd(&proto[(size_t)r * D + d + 1],   acc[mt][nt][1]);
            atomicAdd(&proto[(size_t)(r + 8) * D + d],     acc[mt][nt][2]);
            atomicAdd(&proto[(size_t)(r + 8) * D + d + 1], acc[mt][nt][3]);
        }
    }
}

// ---------------------------------------------------------------------------
// k_proto_fin: proto[c][d] += b[d] (non-empty classes only), pnorm[c]
// ---------------------------------------------------------------------------
__global__ void k_proto_fin(float* __restrict__ proto,
                            const float* __restrict__ bias,
                            const int* __restrict__ cnt,
                            float* __restrict__ pnorm, int D) {
    __shared__ float red[128];
    int c = blockIdx.x;
    int tid = threadIdx.x;
    bool nonempty = cnt[c] > 0;
    float s = 0.f;
    for (int d = tid; d < D; d += blockDim.x) {
        float v = proto[(size_t)c * D + d] + (nonempty ? bias[d] : 0.0f);
        proto[(size_t)c * D + d] = v;
        s = fmaf(v, v, s);
    }
    red[tid] = s;
    __syncthreads();
    for (int o = 64; o > 0; o >>= 1) {
        if (tid < o) red[tid] += red[tid + o];
        __syncthreads();
    }
    if (tid == 0) pnorm[c] = red[0];
}

// ---------------------------------------------------------------------------
// gemm_fused (fp16 + cp.async, single-barrier pipeline):
//   z = xq16 @ w16[:,chunk] + b       (m16n8k16, fp32 accum, 4-slot pipeline)
//   znp[cx*4+wn][row]  = partial ||z||^2 (warp's 32 cols)
//   crossp[cx][row][c] = z_chunk @ proto[:,chunk]^T  (fp16 mma on smem z)
// ---------------------------------------------------------------------------
#define BK 32
#define AS2 40      // halfs per A row (32 + 8) ; 80 B row = 16B-multiple
#define BS2 136     // halfs per B k-row (128 + 8) ; 272 B row
#define ZS2 136
#define PS2 72
#define A_BYTES (128 * AS2 * 2)     // 10240
#define B_BYTES (BK * BS2 * 2)      // 8704
#define OFF_B   (4 * A_BYTES)       // 40960
#define OFF_PS  75776
#define GEMM_SMEM (OFF_PS + 128 * PS2 * 2)   // 94208

__global__ __launch_bounds__(256, 2) void gemm_fused(
    const __half* __restrict__ A, const __half* __restrict__ Wh,
    const float* __restrict__ bias, const float* __restrict__ proto,
    float* __restrict__ crossp, float* __restrict__ znp,
    int M, int N, int K)
{
    extern __shared__ __align__(16) char smraw[];
    const uint32_t sbase = smem_u32(smraw);

    int tid  = threadIdx.x;
    int warp = tid >> 5, lane = tid & 31;
    int wm = warp & 1;        // 0..1  (64-row half)
    int wn = warp >> 1;       // 0..3  (32-col strip)
    int cx = blockIdx.x;
    int rowBase = blockIdx.y * 128;
    int colBase = cx * 128;

    int aR[2], aO[2], bR[2], bO[2];
    #pragma unroll
    for (int j = 0; j < 2; j++) {
        int ch = tid + j * 256;
        aR[j] = ch >> 2;  aO[j] = (ch & 3) * 8;
        bR[j] = ch >> 4;  bO[j] = (ch & 15) * 8;
    }
    const __half* aG = A + (size_t)rowBase * K;
    const __half* bG = Wh + colBase;

    float acc[4][4][4];
    #pragma unroll
    for (int i = 0; i < 4; i++)
        #pragma unroll
        for (int j = 0; j < 4; j++)
            #pragma unroll
            for (int r = 0; r < 4; r++) acc[i][j][r] = 0.0f;

    int r16 = lane & 15, khalf = (lane >> 4) * 8;
    uint32_t aFragOff[4], bFragOff[4];
    #pragma unroll
    for (int mt = 0; mt < 4; mt++)
        aFragOff[mt] = (uint32_t)((wm * 64 + mt * 16 + r16) * AS2 + khalf) * 2;
    #pragma unroll
    for (int nt = 0; nt < 4; nt++)
        bFragOff[nt] = (uint32_t)(r16 * BS2 + wn * 32 + nt * 8) * 2;

    const int nIt = K / BK;   // 64

    // prologue: fill slots 0..2
    #pragma unroll
    for (int s = 0; s < 3; s++) {
        int k0 = s * BK;
        #pragma unroll
        for (int j = 0; j < 2; j++) {
            CP_ASYNC16(sbase + s * A_BYTES + (uint32_t)(aR[j] * AS2 + aO[j]) * 2,
                       aG + (size_t)aR[j] * K + k0 + aO[j]);
            CP_ASYNC16(sbase + OFF_B + s * B_BYTES + (uint32_t)(bR[j] * BS2 + bO[j]) * 2,
                       bG + (size_t)(k0 + bR[j]) * N + bO[j]);
        }
        CP_COMMIT();
    }

    // single-barrier mainloop: wait own copies -> barrier publishes all ->
    // issue next slot (hazard-free: slot (it+3)&3 == (it-1)&3, whose compute
    // finished before this barrier) -> compute current slot.
    for (int it = 0; it < nIt; ++it) {
        CP_WAIT2();
        __syncthreads();

        if (it + 3 < nIt) {
            int s = (it + 3) & 3;
            int k0 = (it + 3) * BK;
            #pragma unroll
            for (int j = 0; j < 2; j++) {
                CP_ASYNC16(sbase + s * A_BYTES + (uint32_t)(aR[j] * AS2 + aO[j]) * 2,
                           aG + (size_t)aR[j] * K + k0 + aO[j]);
                CP_ASYNC16(sbase + OFF_B + s * B_BYTES + (uint32_t)(bR[j] * BS2 + bO[j]) * 2,
                           bG + (size_t)(k0 + bR[j]) * N + bO[j]);
            }
        }
        CP_COMMIT();

        uint32_t aB = sbase + (it & 3) * A_BYTES;
        uint32_t bB = sbase + OFF_B + (it & 3) * B_BYTES;
        #pragma unroll
        for (int ks = 0; ks < 2; ks++) {       // two k16 steps in BK=32
            uint32_t af[4][4], bf[4][2];
            #pragma unroll
            for (int mt = 0; mt < 4; mt++)
                LDSM_X4(af[mt], aB + aFragOff[mt] + ks * 32);
            #pragma unroll
            for (int nt = 0; nt < 4; nt++)
                LDSM_X2T(bf[nt], bB + bFragOff[nt] + ks * 16 * BS2 * 2);
            #pragma unroll
            for (int mt = 0; mt < 4; mt++)
                #pragma unroll
                for (int nt = 0; nt < 4; nt++)
                    mma16(acc[mt][nt], af[mt], bf[nt]);
        }
    }
    __syncthreads();   // all mma smem reads done before Zs overwrites

    __half* Zs = (__half*)smraw;
    __half* Ps = (__half*)(smraw + OFF_PS);

    // fill Ps: proto[c][colBase..+128] -> Ps[d][c] fp16 (disjoint region)
    {
        int cc = tid >> 2;
        int dpart = (tid & 3) * 32;
        const float* pr = proto + (size_t)cc * N + colBase + dpart;
        #pragma unroll
        for (int j = 0; j < 8; j++) {
            float4 v = *(const float4*)(pr + j * 4);
            int d = dpart + j * 4;
            Ps[(d + 0) * PS2 + cc] = __float2half_rn(v.x);
            Ps[(d + 1) * PS2 + cc] = __float2half_rn(v.y);
            Ps[(d + 2) * PS2 + cc] = __float2half_rn(v.z);
            Ps[(d + 3) * PS2 + cc] = __float2half_rn(v.w);
        }
    }

    int lg = lane >> 2, lq = lane & 3;

    // epilogue 1: bias add, znorm partials, stage z (fp16) into Zs
    #pragma unroll
    for (int mt = 0; mt < 4; mt++) {
        int rl = wm * 64 + mt * 16 + lg;
        float sum0 = 0.f, sum1 = 0.f;
        #pragma unroll
        for (int nt = 0; nt < 4; nt++) {
            int cl = wn * 32 + nt * 8 + lq * 2;
            float bv0 = bias[colBase + cl], bv1 = bias[colBase + cl + 1];
            float v0 = acc[mt][nt][0] + bv0;
            float v1 = acc[mt][nt][1] + bv1;
            float v2 = acc[mt][nt][2] + bv0;
            float v3 = acc[mt][nt][3] + bv1;
            *(__half2*)&Zs[rl * ZS2 + cl]       = __floats2half2_rn(v0, v1);
            *(__half2*)&Zs[(rl + 8) * ZS2 + cl] = __floats2half2_rn(v2, v3);
            sum0 = fmaf(v0, v0, fmaf(v1, v1, sum0));
            sum1 = fmaf(v2, v2, fmaf(v3, v3, sum1));
        }
        sum0 += __shfl_xor_sync(0xFFFFFFFFu, sum0, 1);
        sum0 += __shfl_xor_sync(0xFFFFFFFFu, sum0, 2);
        sum1 += __shfl_xor_sync(0xFFFFFFFFu, sum1, 1);
        sum1 += __shfl_xor_sync(0xFFFFFFFFu, sum1, 2);
        if (lq == 0) {
            int slab = (cx * 4 + wn) * M;
            znp[slab + rowBase + rl]     = sum0;
            znp[slab + rowBase + rl + 8] = sum1;
        }
    }
    __syncthreads();

    // epilogue 2: cross partial = Zs[128x128] @ Ps^T -> [128 x 64] (fp16 mma)
    {
        float cacc[8][4];
        #pragma unroll
        for (int ct = 0; ct < 8; ct++)
            #pragma unroll
            for (int r = 0; r < 4; r++) cacc[ct][r] = 0.0f;

        uint32_t zlm = sbase + (uint32_t)((warp * 16 + r16) * ZS2 + khalf) * 2;
        uint32_t psBase = sbase + OFF_PS;

        #pragma unroll
        for (int kk = 0; kk < 8; kk++) {
            uint32_t afx[4];
            LDSM_X4(afx, zlm + kk * 32);
            #pragma unroll
            for (int ct = 0; ct < 8; ct++) {
                uint32_t bfx[2];
                LDSM_X2T(bfx, psBase +
                    (uint32_t)((kk * 16 + r16) * PS2 + ct * 8) * 2);
                mma16(cacc[ct], afx, bfx);
            }
        }

        size_t slab = (size_t)cx * M;
        int r0 = rowBase + warp * 16 + lg;
        #pragma unroll
        for (int ct = 0; ct < 8; ct++) {
            int col = ct * 8 + lq * 2;
            *(float2*)&crossp[(slab + r0) * NWAY + col] =
                make_float2(cacc[ct][0], cacc[ct][1]);
            *(float2*)&crossp[(slab + r0 + 8) * NWAY + col] =
                make_float2(cacc[ct][2], cacc[ct][3]);
        }
    }
}

// ---------------------------------------------------------------------------
// k_fin: out[q,c] = 2 * sum_cx crossp[cx][q][c] - sum_j znp[j][q] - pnorm[c]
// ---------------------------------------------------------------------------
__global__ void k_fin(const float* __restrict__ crossp,
                      const float* __restrict__ znp,
                      const float* __restrict__ pnorm,
                      float* __restrict__ out, int Q) {
    int idx = blockIdx.x * blockDim.x + threadIdx.x;
    int q = idx >> 4;
    int c4 = (idx & 15) * 4;
    size_t base = (size_t)q * NWAY + c4;
    size_t slab = (size_t)Q * NWAY;

    float4 s0 = *(const float4*)&crossp[base];
    float4 s1 = *(const float4*)&crossp[base + slab];
    float4 s2 = *(const float4*)&crossp[base + 2 * slab];
    float4 s3 = *(const float4*)&crossp[base + 3 * slab];

    float zn = 0.f;
    #pragma unroll
    for (int j = 0; j < NC * 4; j++) zn += znp[(size_t)j * Q + q];

    float4 pn = *(const float4*)&pnorm[c4];

    float4 o;
    o.x = 2.0f * (s0.x + s1.x + s2.x + s3.x) - zn - pn.x;
    o.y = 2.0f * (s0.y + s1.y + s2.y + s3.y) - zn - pn.y;
    o.z = 2.0f * (s0.z + s1.z + s2.z + s3.z) - zn - pn.z;
    o.w = 2.0f * (s0.w + s1.w + s2.w + s3.w) - zn - pn.w;
    *(float4*)&out[base] = o;
}

// ---------------------------------------------------------------------------
// Host launcher: fork the proto chain onto a side stream, converge before
// the fused GEMM. Event fork/join is graph-capture legal and builds a DAG.
// ---------------------------------------------------------------------------
extern "C" void kernel_launch(void* const* d_in, const int* in_sizes, int n_in,
                              void* d_out, int out_size) {
    const float* xs = (const float*)d_in[0];
    const void*  ys = d_in[1];
    const float* xq = (const float*)d_in[2];
    const float* W  = (const float*)d_in[3];
    const float* b  = (const float*)d_in[4];

    int S = in_sizes[1];
    int F = in_sizes[0] / S;
    int D = in_sizes[4];
    int Q = in_sizes[2] / F;

    float *p_cls, *p_proto, *p_pnorm, *p_invcnt, *p_crossp, *p_znp;
    __half *p_xq16, *p_w16;
    int *p_ys, *p_cnt;
    cudaGetSymbolAddress((void**)&p_cls, g_cls_sum);
    cudaGetSymbolAddress((void**)&p_proto, g_proto);
    cudaGetSymbolAddress((void**)&p_pnorm, g_pnorm);
    cudaGetSymbolAddress((void**)&p_invcnt, g_invcnt);
    cudaGetSymbolAddress((void**)&p_ys, g_ys);
    cudaGetSymbolAddress((void**)&p_cnt, g_cnt);
    cudaGetSymbolAddress((void**)&p_crossp, g_crossp);
    cudaGetSymbolAddress((void**)&p_znp, g_znp);
    cudaGetSymbolAddress((void**)&p_xq16, g_xq16);
    cudaGetSymbolAddress((void**)&p_w16, g_w16);

    cudaFuncSetAttribute(k_proto_tc,
                         cudaFuncAttributeMaxDynamicSharedMemorySize,
                         PROTO_SMEM_FLOATS * 4);
    cudaFuncSetAttribute(gemm_fused,
                         cudaFuncAttributeMaxDynamicSharedMemorySize,
                         GEMM_SMEM);

    // lazy-init side stream + events (created on the uncaptured warmup call;
    // handles are reused identically every call -> deterministic work)
    static cudaStream_t s_side = nullptr;
    static cudaEvent_t  s_fork = nullptr, s_join = nullptr;
    static bool s_tried = false;
    if (!s_tried) {
        s_tried = true;
        if (cudaStreamCreateWithFlags(&s_side, cudaStreamNonBlocking)
                != cudaSuccess) s_side = nullptr;
        if (cudaEventCreateWithFlags(&s_fork, cudaEventDisableTiming)
                != cudaSuccess) s_fork = nullptr;
        if (cudaEventCreateWithFlags(&s_join, cudaEventDisableTiming)
                != cudaSuccess) s_join = nullptr;
    }
    const bool par = (s_side && s_fork && s_join);
    cudaStream_t side = par ? s_side : (cudaStream_t)0;

    if (par) {
        cudaEventRecord(s_fork, 0);
        cudaStreamWaitEvent(s_side, s_fork, 0);
    }

    // ---- side chain: prototypes (independent of the fp16 conversion) ----
    {
        int n = NWAY * F + NWAY * D;
        k_zero2<<<(n + 255) / 256, 256, 0, side>>>(p_cls, NWAY * F,
                                                   p_proto, NWAY * D);
    }
    k_prep<<<1, 256, 0, side>>>(ys, S, p_ys, p_invcnt, p_cnt);
    {
        dim3 grid(F / 128, 8);
        k_cls_sum<<<grid, 128, 0, side>>>(xs, S, F, p_ys, p_cls);
    }
    {
        dim3 grid(D / 128, F / 128);
        k_proto_tc<<<grid, 256, PROTO_SMEM_FLOATS * 4, side>>>(
            p_cls, W, p_invcnt, p_proto, F, D);
    }
    k_proto_fin<<<NWAY, 128, 0, side>>>(p_proto, b, p_cnt, p_pnorm, D);
    if (par) cudaEventRecord(s_join, s_side);

    // ---- main chain: fp16 conversion of xq and W ----
    {
        int n8q = Q * F / 8;
        int n8w = F * D / 8;
        k_cvt2<<<(n8q + n8w + 255) / 256, 256>>>(xq, p_xq16, n8q,
                                                 W, p_w16, n8w);
    }

    if (par) cudaStreamWaitEvent((cudaStream_t)0, s_join, 0);

    // ---- fused fp16 GEMM (needs xq16, w16, proto) ----
    {
        dim3 grid(NC, Q / 128);
        gemm_fused<<<grid, 256, GEMM_SMEM>>>(
            p_xq16, p_w16, b, p_proto, p_crossp, p_znp, Q, D, F);
    }

    // ---- combine partials -> output ----
    k_fin<<<Q * 16 / 256, 256>>>(p_crossp, p_znp, p_pnorm, (float*)d_out, Q);
}